// round 9
// baseline (speedup 1.0000x reference)
#include <cuda_runtime.h>
#include <cuda_bf16.h>
#include <math.h>
#include <stdint.h>

#define Bb 4
#define LQ 8400
#define Ee 256
#define HEADS 8
#define LEVELS 4
#define POINTS 4
#define HEAD_DIM 32
#define LVTOT 8500
#define KDIM 256

#define MQ (Bb * LQ)     // 33600
#define MV (Bb * LVTOT)  // 34000

// ---------------- scratch (device globals; no allocation allowed) ----------
__device__ float g_v[MV * Ee];            // value @ Wv + bv (f32, sampler input)
__device__ float g_offaw[MQ * 384];       // [off(256) | aw(128)] fused GEMM output
__device__ float g_tmp[MQ * Ee];          // sampler output (f32)
__device__ float g_bias_comb[384];

// transposed weights [N][K] bf16 hi/lo
#define WT_WV    0
#define WT_COMB  65536
#define WT_WO    163840
#define WT_TOTAL 229376
__device__ __nv_bfloat16 g_wt_hi[WT_TOTAL];
__device__ __nv_bfloat16 g_wt_lo[WT_TOTAL];

// ---------------- helpers ----------------------------------------------
#define SMEM_SWIZZLE_128B(byte_offset) \
    ((byte_offset) ^ (((byte_offset) >> 3) & 0x70))

__device__ __forceinline__ uint32_t smem_u32(const void* p) {
    uint32_t a;
    asm("{ .reg .u64 t; cvta.to.shared.u64 t, %1; cvt.u32.u64 %0, t; }"
        : "=r"(a) : "l"(p));
    return a;
}

__device__ __forceinline__ void cp16(uint32_t dst, const void* src) {
    asm volatile("cp.async.cg.shared.global [%0], [%1], 16;"
                 :: "r"(dst), "l"(src));
}

__device__ __forceinline__ void cp_commit() {
    asm volatile("cp.async.commit_group;" ::: "memory");
}
__device__ __forceinline__ void cp_wait0() {
    asm volatile("cp.async.wait_group 0;" ::: "memory");
}

__device__ __forceinline__ void ldm_x4(uint32_t* r, uint32_t addr) {
    asm volatile("ldmatrix.sync.aligned.m8n8.x4.shared.b16 {%0,%1,%2,%3}, [%4];"
                 : "=r"(r[0]), "=r"(r[1]), "=r"(r[2]), "=r"(r[3]) : "r"(addr));
}

__device__ __forceinline__ void mma16816(float* c, const uint32_t* a, const uint32_t* b) {
    asm volatile("mma.sync.aligned.m16n8k16.row.col.f32.bf16.bf16.f32 "
                 "{%0,%1,%2,%3}, {%4,%5,%6,%7}, {%8,%9}, {%0,%1,%2,%3};"
                 : "+f"(c[0]), "+f"(c[1]), "+f"(c[2]), "+f"(c[3])
                 : "r"(a[0]), "r"(a[1]), "r"(a[2]), "r"(a[3]),
                   "r"(b[0]), "r"(b[1]));
}

__device__ __forceinline__ void split4(float4 v, uint2& ho, uint2& lo) {
    __nv_bfloat16 h0 = __float2bfloat16_rn(v.x);
    __nv_bfloat16 h1 = __float2bfloat16_rn(v.y);
    __nv_bfloat16 h2 = __float2bfloat16_rn(v.z);
    __nv_bfloat16 h3 = __float2bfloat16_rn(v.w);
    __nv_bfloat16 l0 = __float2bfloat16_rn(v.x - __bfloat162float(h0));
    __nv_bfloat16 l1 = __float2bfloat16_rn(v.y - __bfloat162float(h1));
    __nv_bfloat16 l2 = __float2bfloat16_rn(v.z - __bfloat162float(h2));
    __nv_bfloat16 l3 = __float2bfloat16_rn(v.w - __bfloat162float(h3));
    __nv_bfloat162 hp0; hp0.x = h0; hp0.y = h1;
    __nv_bfloat162 hp1; hp1.x = h2; hp1.y = h3;
    __nv_bfloat162 lp0; lp0.x = l0; lp0.y = l1;
    __nv_bfloat162 lp1; lp1.x = l2; lp1.y = l3;
    ho.x = *(uint32_t*)&hp0; ho.y = *(uint32_t*)&hp1;
    lo.x = *(uint32_t*)&lp0; lo.y = *(uint32_t*)&lp1;
}

// ---------------------------------------------------------------------------
// ONE prep kernel: all 4 weight transposes+splits + bias concat.
// ---------------------------------------------------------------------------
__global__ void prep_weights_kernel(const float* __restrict__ Wv,
                                    const float* __restrict__ Woff,
                                    const float* __restrict__ Wattn,
                                    const float* __restrict__ Wo,
                                    const float* __restrict__ boff,
                                    const float* __restrict__ battn)
{
    int idx = blockIdx.x * blockDim.x + threadIdx.x;
    if (idx < 384)
        g_bias_comb[idx] = (idx < 256) ? boff[idx] : battn[idx - 256];
    if (idx >= WT_TOTAL) return;

    const float* W;
    int Nd, out, t = idx;
    if (t < 65536)        { W = Wv;    Nd = 256; out = WT_WV; }
    else if (t < 131072)  { W = Woff;  Nd = 256; out = WT_COMB;          t -= 65536; }
    else if (t < 163840)  { W = Wattn; Nd = 128; out = WT_COMB + 65536;  t -= 131072; }
    else                  { W = Wo;    Nd = 256; out = WT_WO;            t -= 163840; }

    int k = t / Nd, n = t % Nd;
    float v = W[k * Nd + n];
    __nv_bfloat16 h = __float2bfloat16_rn(v);
    g_wt_hi[out + n * 256 + k] = h;
    g_wt_lo[out + n * 256 + k] = __float2bfloat16_rn(v - __bfloat162float(h));
}

// ---------------------------------------------------------------------------
// mma.sync bf16x3 GEMM. CTA tile 64x128, 256 threads (8 warps, warp 32x32).
// Single-stage smem 48KB, 4 CTAs/SM (regs capped to 64); inter-CTA overlap.
// Dual-problem dispatch: blocks [0, nblk1) -> problem 1, rest -> problem 2.
// ---------------------------------------------------------------------------
__global__ __launch_bounds__(256, 4)
void gemm_dual_bf16x3(const float* __restrict__ A1,
                      const __nv_bfloat16* __restrict__ Bhi1,
                      const __nv_bfloat16* __restrict__ Blo1,
                      const float* __restrict__ bias1,
                      float* __restrict__ C1, int M1, int N1, int nc1, int nblk1,
                      const float* __restrict__ A2,
                      const __nv_bfloat16* __restrict__ Bhi2,
                      const __nv_bfloat16* __restrict__ Blo2,
                      const float* __restrict__ bias2,
                      float* __restrict__ C2, int M2, int N2, int nc2)
{
    extern __shared__ char smem[];
    // layout: A_hi 0..8K | A_lo 8K..16K | B_hi 16K..32K | B_lo 32K..48K
    const uint32_t sa_hi = smem_u32(smem);
    const uint32_t sa_lo = sa_hi + 8192u;
    const uint32_t sb_hi = sa_hi + 16384u;
    const uint32_t sb_lo = sa_hi + 32768u;

    const float* A; const __nv_bfloat16* Bhi; const __nv_bfloat16* Blo;
    const float* bias; float* C;
    int M, N, brow, bcol;
    {
        int bid = blockIdx.x;
        if (bid < nblk1) {
            A = A1; Bhi = Bhi1; Blo = Blo1; bias = bias1; C = C1; M = M1; N = N1;
            brow = (bid / nc1) * 64; bcol = (bid % nc1) * 128;
        } else {
            bid -= nblk1;
            A = A2; Bhi = Bhi2; Blo = Blo2; bias = bias2; C = C2; M = M2; N = N2;
            brow = (bid / nc2) * 64; bcol = (bid % nc2) * 128;
        }
    }

    const int tid = threadIdx.x, lane = tid & 31, wid = tid >> 5;
    const int wr = (wid >> 2) * 32;   // 0 or 32
    const int wc = (wid & 3) * 32;    // 0,32,64,96

    float acc[2][4][4];
#pragma unroll
    for (int i = 0; i < 2; i++)
#pragma unroll
        for (int j = 0; j < 4; j++)
#pragma unroll
            for (int k = 0; k < 4; k++) acc[i][j][k] = 0.f;

    const int a_r  = wr + (lane & 15);
    const int a_kx = (lane >> 4) << 4;
    const int b_r0 = wc + (lane & 7) + ((lane >> 4) << 3);
    const int b_kx = ((lane >> 3) & 1) << 4;

    const int nk = KDIM / 64;   // 4
    for (int kc = 0; kc < nk; kc++) {
        if (kc) __syncthreads();   // previous compute must finish before overwrite

        // ---- B chunk via cp.async (128 rows x 128B, hi+lo) ----
#pragma unroll
        for (int i = 0; i < 4; i++) {
            int t = i * 256 + tid;
            int r = t >> 3, j = t & 7;
            uint32_t d = SMEM_SWIZZLE_128B((uint32_t)(r * 128 + j * 16));
            size_t src = (size_t)(bcol + r) * KDIM + kc * 64 + j * 8;
            cp16(sb_hi + d, Bhi + src);
            cp16(sb_lo + d, Blo + src);
        }
        cp_commit();

        // ---- A chunk via LDG -> split -> STS (64 rows x 64 f32) ----
        float4 a4[4];
#pragma unroll
        for (int i = 0; i < 4; i++) {
            int t = i * 256 + tid;
            int r = t >> 4, jc = t & 15;
            a4[i] = (brow + r < M)
                ? __ldg((const float4*)(A + (size_t)(brow + r) * KDIM + kc * 64 + jc * 4))
                : make_float4(0.f, 0.f, 0.f, 0.f);
        }
#pragma unroll
        for (int i = 0; i < 4; i++) {
            int t = i * 256 + tid;
            int r = t >> 4, jc = t & 15;
            uint32_t d = SMEM_SWIZZLE_128B((uint32_t)(r * 128 + (jc >> 1) * 16)) + (jc & 1) * 8;
            uint2 ho, lo;
            split4(a4[i], ho, lo);
            *(uint2*)(smem + d) = ho;
            *(uint2*)(smem + 8192u + d) = lo;
        }
        cp_wait0();
        __syncthreads();

        // ---- compute ----
#pragma unroll
        for (int kk = 0; kk < 4; kk++) {
            const uint32_t kbA = (uint32_t)(kk * 32 + a_kx);
            const uint32_t kbB = (uint32_t)(kk * 32 + b_kx);

            uint32_t ahi[2][4], bhi[4][2];
#pragma unroll
            for (int mi = 0; mi < 2; mi++)
                ldm_x4(ahi[mi], sa_hi + SMEM_SWIZZLE_128B((uint32_t)((a_r + mi * 16) * 128) + kbA));
#pragma unroll
            for (int nj = 0; nj < 2; nj++) {
                uint32_t rr[4];
                ldm_x4(rr, sb_hi + SMEM_SWIZZLE_128B((uint32_t)((b_r0 + nj * 16) * 128) + kbB));
                bhi[nj * 2][0] = rr[0]; bhi[nj * 2][1] = rr[1];
                bhi[nj * 2 + 1][0] = rr[2]; bhi[nj * 2 + 1][1] = rr[3];
            }
#pragma unroll
            for (int mi = 0; mi < 2; mi++)
#pragma unroll
                for (int ni = 0; ni < 4; ni++)
                    mma16816(acc[mi][ni], ahi[mi], bhi[ni]);

            uint32_t blo[4][2];
#pragma unroll
            for (int nj = 0; nj < 2; nj++) {
                uint32_t rr[4];
                ldm_x4(rr, sb_lo + SMEM_SWIZZLE_128B((uint32_t)((b_r0 + nj * 16) * 128) + kbB));
                blo[nj * 2][0] = rr[0]; blo[nj * 2][1] = rr[1];
                blo[nj * 2 + 1][0] = rr[2]; blo[nj * 2 + 1][1] = rr[3];
            }
#pragma unroll
            for (int mi = 0; mi < 2; mi++)
#pragma unroll
                for (int ni = 0; ni < 4; ni++)
                    mma16816(acc[mi][ni], ahi[mi], blo[ni]);

            uint32_t alo[2][4];
#pragma unroll
            for (int mi = 0; mi < 2; mi++)
                ldm_x4(alo[mi], sa_lo + SMEM_SWIZZLE_128B((uint32_t)((a_r + mi * 16) * 128) + kbA));
#pragma unroll
            for (int mi = 0; mi < 2; mi++)
#pragma unroll
                for (int ni = 0; ni < 4; ni++)
                    mma16816(acc[mi][ni], alo[mi], bhi[ni]);
        }
    }

    // ---- epilogue: bias + float2 stores ----
    const int row0 = brow + wr + (lane >> 2);
#pragma unroll
    for (int ni = 0; ni < 4; ni++) {
        int col = bcol + wc + ni * 8 + (lane & 3) * 2;
        float2 bb = *(const float2*)&bias[col];
#pragma unroll
        for (int mi = 0; mi < 2; mi++) {
            int r0 = row0 + mi * 16;
            if (r0 < M) {
                float2 o;
                o.x = acc[mi][ni][0] + bb.x;
                o.y = acc[mi][ni][1] + bb.y;
                *(float2*)(C + (size_t)r0 * N + col) = o;
            }
            int r1 = r0 + 8;
            if (r1 < M) {
                float2 o;
                o.x = acc[mi][ni][2] + bb.x;
                o.y = acc[mi][ni][3] + bb.y;
                *(float2*)(C + (size_t)r1 * N + col) = o;
            }
        }
    }
}

// ---------------------------------------------------------------------------
// Fused softmax + bilinear sampling (owner-lane precompute).
// launch_bounds(256, 6): cap regs at 42 -> higher occupancy to hide L2 gathers.
// ---------------------------------------------------------------------------
__global__ __launch_bounds__(256, 6)
void msda_sample_kernel(const float* __restrict__ ref)
{
    int warp_global = blockIdx.x * (blockDim.x >> 5) + (threadIdx.x >> 5);
    if (warp_global >= Bb * LQ * 2) return;
    int lane = threadIdx.x & 31;
    int g = lane >> 3;
    int r = lane & 7;

    int hpair = warp_global & 1;
    int bq    = warp_global >> 1;
    int b     = bq / LQ;
    int hh    = hpair * 4 + g;

    const float2* awp = (const float2*)(g_offaw + (size_t)bq * 384 + 256 + hh * 16);
    float2 lg = awp[r];
    float m = fmaxf(lg.x, lg.y);
#pragma unroll
    for (int o = 4; o > 0; o >>= 1) m = fmaxf(m, __shfl_xor_sync(0xffffffffu, m, o));
    float e0 = __expf(lg.x - m);
    float e1 = __expf(lg.y - m);
    float s = e0 + e1;
#pragma unroll
    for (int o = 4; o > 0; o >>= 1) s += __shfl_xor_sync(0xffffffffu, s, o);
    float inv = 1.f / s;
    float w0 = e0 * inv;
    float w1 = e1 * inv;

    const float4* offp = (const float4*)(g_offaw + (size_t)bq * 384 + hh * 32);
    float4 off4 = offp[r];

    int l  = r >> 1;
    int HW = 80 >> l;
    int start = (l > 0 ? 6400 : 0) + (l > 1 ? 1600 : 0) + (l > 2 ? 400 : 0);
    float fHW = (float)HW;
    float2 rxy = __ldg((const float2*)ref + (size_t)bq * 4 + l);

    float cA[4], cB[4];
    uint32_t pkA0, pkA1, pkB0, pkB1;
#pragma unroll
    for (int pt = 0; pt < 2; pt++) {
        float ox = pt ? off4.z : off4.x;
        float oy = pt ? off4.w : off4.y;
        float aw = pt ? w1 : w0;

        float x = fmaf(rxy.x, fHW, ox - 0.5f);
        float y = fmaf(rxy.y, fHW, oy - 0.5f);
        float x0f = floorf(x), y0f = floorf(y);
        float wx = x - x0f, wy = y - y0f;
        int x0 = (int)x0f, y0 = (int)y0f;
        int x1 = x0 + 1,   y1 = y0 + 1;

        float vx0 = (x0 >= 0 && x0 < HW) ? 1.f : 0.f;
        float vx1 = (x1 >= 0 && x1 < HW) ? 1.f : 0.f;
        float vy0 = (y0 >= 0 && y0 < HW) ? 1.f : 0.f;
        float vy1 = (y1 >= 0 && y1 < HW) ? 1.f : 0.f;

        int cx0 = min(max(x0, 0), HW - 1);
        int cx1 = min(max(x1, 0), HW - 1);
        int cy0 = min(max(y0, 0), HW - 1);
        int cy1 = min(max(y1, 0), HW - 1);

        uint32_t p00 = (uint32_t)(start + cy0 * HW + cx0);
        uint32_t p01 = (uint32_t)(start + cy0 * HW + cx1);
        uint32_t p10 = (uint32_t)(start + cy1 * HW + cx0);
        uint32_t p11 = (uint32_t)(start + cy1 * HW + cx1);

        float wx1 = 1.f - wx, wy1 = 1.f - wy;
        float c0 = aw * wx1 * wy1 * vx0 * vy0;
        float c1 = aw * wx  * wy1 * vx1 * vy0;
        float c2 = aw * wx1 * wy  * vx0 * vy1;
        float c3 = aw * wx  * wy  * vx1 * vy1;

        if (pt == 0) {
            cA[0] = c0; cA[1] = c1; cA[2] = c2; cA[3] = c3;
            pkA0 = p00 | (p01 << 16); pkA1 = p10 | (p11 << 16);
        } else {
            cB[0] = c0; cB[1] = c1; cB[2] = c2; cB[3] = c3;
            pkB0 = p00 | (p01 << 16); pkB1 = p10 | (p11 << 16);
        }
    }

    const float* pbase = g_v + (size_t)b * LVTOT * Ee + hh * HEAD_DIM + r * 4;
    float4 acc = make_float4(0.f, 0.f, 0.f, 0.f);

#pragma unroll
    for (int j = 0; j < 8; j++) {
        int src = (g << 3) + j;
#pragma unroll
        for (int pt = 0; pt < 2; pt++) {
            float c0 = __shfl_sync(0xffffffffu, pt ? cB[0] : cA[0], src);
            float c1 = __shfl_sync(0xffffffffu, pt ? cB[1] : cA[1], src);
            float c2 = __shfl_sync(0xffffffffu, pt ? cB[2] : cA[2], src);
            float c3 = __shfl_sync(0xffffffffu, pt ? cB[3] : cA[3], src);
            uint32_t q0 = __shfl_sync(0xffffffffu, pt ? pkB0 : pkA0, src);
            uint32_t q1 = __shfl_sync(0xffffffffu, pt ? pkB1 : pkA1, src);

            uint32_t i00 = q0 & 0xffffu, i01 = q0 >> 16;
            uint32_t i10 = q1 & 0xffffu, i11 = q1 >> 16;

            float4 v00 = __ldg((const float4*)(pbase + (size_t)i00 * Ee));
            float4 v01 = __ldg((const float4*)(pbase + (size_t)i01 * Ee));
            float4 v10 = __ldg((const float4*)(pbase + (size_t)i10 * Ee));
            float4 v11 = __ldg((const float4*)(pbase + (size_t)i11 * Ee));

            acc.x = fmaf(c0, v00.x, fmaf(c1, v01.x, fmaf(c2, v10.x, fmaf(c3, v11.x, acc.x))));
            acc.y = fmaf(c0, v00.y, fmaf(c1, v01.y, fmaf(c2, v10.y, fmaf(c3, v11.y, acc.y))));
            acc.z = fmaf(c0, v00.z, fmaf(c1, v01.z, fmaf(c2, v10.z, fmaf(c3, v11.z, acc.z))));
            acc.w = fmaf(c0, v00.w, fmaf(c1, v01.w, fmaf(c2, v10.w, fmaf(c3, v11.w, acc.w))));
        }
    }

    *(float4*)(g_tmp + (size_t)bq * Ee + hh * HEAD_DIM + r * 4) = acc;
}

// ---------------------------------------------------------------------------
extern "C" void kernel_launch(void* const* d_in, const int* in_sizes, int n_in,
                              void* d_out, int out_size)
{
    const float* query = (const float*)d_in[0];
    const float* ref   = (const float*)d_in[1];
    const float* value = (const float*)d_in[2];
    const float* Wv    = (const float*)d_in[4];
    const float* bv    = (const float*)d_in[5];
    const float* Woff  = (const float*)d_in[6];
    const float* boff  = (const float*)d_in[7];
    const float* Wattn = (const float*)d_in[8];
    const float* battn = (const float*)d_in[9];
    const float* Wo    = (const float*)d_in[10];
    const float* bo    = (const float*)d_in[11];
    float* out = (float*)d_out;

    float *pv, *poffaw, *ptmp, *pbc;
    __nv_bfloat16 *pwhi, *pwlo;
    cudaGetSymbolAddress((void**)&pv,     g_v);
    cudaGetSymbolAddress((void**)&poffaw, g_offaw);
    cudaGetSymbolAddress((void**)&ptmp,   g_tmp);
    cudaGetSymbolAddress((void**)&pbc,    g_bias_comb);
    cudaGetSymbolAddress((void**)&pwhi,   g_wt_hi);
    cudaGetSymbolAddress((void**)&pwlo,   g_wt_lo);

    cudaFuncSetAttribute(gemm_dual_bf16x3,
                         cudaFuncAttributeMaxDynamicSharedMemorySize, 49152);

    // ---- prep (single launch) ----
    prep_weights_kernel<<<(WT_TOTAL + 255) / 256, 256>>>(Wv, Woff, Wattn, Wo, boff, battn);

    // ---- GEMM 1+2 merged: g_v = value@Wv+bv  AND  g_offaw = query@[Woff|Wattn]+bias ----
    {
        const int rows1 = (MV + 63) / 64;          // 532
        const int nblk1 = rows1 * 2;               // 1064  (N=256 -> nc1=2)
        const int rows2 = (MQ + 63) / 64;          // 525
        const int nblk2 = rows2 * 3;               // 1575  (N=384 -> nc2=3)
        gemm_dual_bf16x3<<<nblk1 + nblk2, 256, 49152>>>(
            value, pwhi + WT_WV,   pwlo + WT_WV,   bv,  pv,     MV, 256, 2, nblk1,
            query, pwhi + WT_COMB, pwlo + WT_COMB, pbc, poffaw, MQ, 384, 3);
    }
    // ---- sampler ----
    {
        int total_warps = Bb * LQ * 2;
        int blocks = (total_warps + 7) / 8;
        msda_sample_kernel<<<blocks, 256>>>(ref);
    }
    // ---- GEMM 3: out = g_tmp @ Wo + bo ----
    {
        const int rows3 = (MQ + 63) / 64;          // 525
        const int nblk3 = rows3 * 2;               // 1050
        gemm_dual_bf16x3<<<nblk3, 256, 49152>>>(
            ptmp, pwhi + WT_WO, pwlo + WT_WO, bo, out, MQ, 256, 2, nblk3,
            ptmp, pwhi + WT_WO, pwlo + WT_WO, bo, out, MQ, 256, 2);
    }
}

// round 10
// speedup vs baseline: 1.0009x; 1.0009x over previous
#include <cuda_runtime.h>
#include <cuda_bf16.h>
#include <math.h>
#include <stdint.h>

#define Bb 4
#define LQ 8400
#define Ee 256
#define HEADS 8
#define LEVELS 4
#define POINTS 4
#define HEAD_DIM 32
#define LVTOT 8500
#define KDIM 256

#define MQ (Bb * LQ)     // 33600
#define MV (Bb * LVTOT)  // 34000

// ---------------- scratch (device globals; no allocation allowed) ----------
__device__ float g_v[MV * Ee];            // value @ Wv + bv (f32, sampler input)
__device__ float g_offaw[MQ * 384];       // [off(256) | aw(128)] fused GEMM output
__device__ float g_tmp[MQ * Ee];          // sampler output (f32)
__device__ float g_bias_comb[384];

// transposed weights [N][K] bf16 hi/lo
#define WT_WV    0
#define WT_COMB  65536
#define WT_WO    163840
#define WT_TOTAL 229376
__device__ __nv_bfloat16 g_wt_hi[WT_TOTAL];
__device__ __nv_bfloat16 g_wt_lo[WT_TOTAL];

// ---------------- helpers ----------------------------------------------
#define SMEM_SWIZZLE_128B(byte_offset) \
    ((byte_offset) ^ (((byte_offset) >> 3) & 0x70))

__device__ __forceinline__ uint32_t smem_u32(const void* p) {
    uint32_t a;
    asm("{ .reg .u64 t; cvta.to.shared.u64 t, %1; cvt.u32.u64 %0, t; }"
        : "=r"(a) : "l"(p));
    return a;
}

__device__ __forceinline__ void cp16(uint32_t dst, const void* src) {
    asm volatile("cp.async.cg.shared.global [%0], [%1], 16;"
                 :: "r"(dst), "l"(src));
}

__device__ __forceinline__ void cp_commit() {
    asm volatile("cp.async.commit_group;" ::: "memory");
}
__device__ __forceinline__ void cp_wait0() {
    asm volatile("cp.async.wait_group 0;" ::: "memory");
}

__device__ __forceinline__ void ldm_x4(uint32_t* r, uint32_t addr) {
    asm volatile("ldmatrix.sync.aligned.m8n8.x4.shared.b16 {%0,%1,%2,%3}, [%4];"
                 : "=r"(r[0]), "=r"(r[1]), "=r"(r[2]), "=r"(r[3]) : "r"(addr));
}

__device__ __forceinline__ void mma16816(float* c, const uint32_t* a, const uint32_t* b) {
    asm volatile("mma.sync.aligned.m16n8k16.row.col.f32.bf16.bf16.f32 "
                 "{%0,%1,%2,%3}, {%4,%5,%6,%7}, {%8,%9}, {%0,%1,%2,%3};"
                 : "+f"(c[0]), "+f"(c[1]), "+f"(c[2]), "+f"(c[3])
                 : "r"(a[0]), "r"(a[1]), "r"(a[2]), "r"(a[3]),
                   "r"(b[0]), "r"(b[1]));
}

__device__ __forceinline__ void split4(float4 v, uint2& ho, uint2& lo) {
    __nv_bfloat16 h0 = __float2bfloat16_rn(v.x);
    __nv_bfloat16 h1 = __float2bfloat16_rn(v.y);
    __nv_bfloat16 h2 = __float2bfloat16_rn(v.z);
    __nv_bfloat16 h3 = __float2bfloat16_rn(v.w);
    __nv_bfloat16 l0 = __float2bfloat16_rn(v.x - __bfloat162float(h0));
    __nv_bfloat16 l1 = __float2bfloat16_rn(v.y - __bfloat162float(h1));
    __nv_bfloat16 l2 = __float2bfloat16_rn(v.z - __bfloat162float(h2));
    __nv_bfloat16 l3 = __float2bfloat16_rn(v.w - __bfloat162float(h3));
    __nv_bfloat162 hp0; hp0.x = h0; hp0.y = h1;
    __nv_bfloat162 hp1; hp1.x = h2; hp1.y = h3;
    __nv_bfloat162 lp0; lp0.x = l0; lp0.y = l1;
    __nv_bfloat162 lp1; lp1.x = l2; lp1.y = l3;
    ho.x = *(uint32_t*)&hp0; ho.y = *(uint32_t*)&hp1;
    lo.x = *(uint32_t*)&lp0; lo.y = *(uint32_t*)&lp1;
}

// ---------------------------------------------------------------------------
// ONE prep kernel: all 4 weight transposes+splits + bias concat.
// ---------------------------------------------------------------------------
__global__ void prep_weights_kernel(const float* __restrict__ Wv,
                                    const float* __restrict__ Woff,
                                    const float* __restrict__ Wattn,
                                    const float* __restrict__ Wo,
                                    const float* __restrict__ boff,
                                    const float* __restrict__ battn)
{
    int idx = blockIdx.x * blockDim.x + threadIdx.x;
    if (idx < 384)
        g_bias_comb[idx] = (idx < 256) ? boff[idx] : battn[idx - 256];
    if (idx >= WT_TOTAL) return;

    const float* W;
    int Nd, out, t = idx;
    if (t < 65536)        { W = Wv;    Nd = 256; out = WT_WV; }
    else if (t < 131072)  { W = Woff;  Nd = 256; out = WT_COMB;          t -= 65536; }
    else if (t < 163840)  { W = Wattn; Nd = 128; out = WT_COMB + 65536;  t -= 131072; }
    else                  { W = Wo;    Nd = 256; out = WT_WO;            t -= 163840; }

    int k = t / Nd, n = t % Nd;
    float v = W[k * Nd + n];
    __nv_bfloat16 h = __float2bfloat16_rn(v);
    g_wt_hi[out + n * 256 + k] = h;
    g_wt_lo[out + n * 256 + k] = __float2bfloat16_rn(v - __bfloat162float(h));
}

// ---------------------------------------------------------------------------
// mma.sync bf16x3 GEMM. CTA tile 64x128, 128 threads (4 warps, warp 64x32).
// 64x32 warp tile: 48 MMAs per 12 ldmatrix.x4 per kk -> 25% less smem
// crossbar traffic per FLOP than 32x32. Single-stage 48KB smem, 4 CTAs/SM.
// Dual-problem dispatch: blocks [0, nblk1) -> problem 1, rest -> problem 2.
// ---------------------------------------------------------------------------
__global__ __launch_bounds__(128, 4)
void gemm_dual_bf16x3(const float* __restrict__ A1,
                      const __nv_bfloat16* __restrict__ Bhi1,
                      const __nv_bfloat16* __restrict__ Blo1,
                      const float* __restrict__ bias1,
                      float* __restrict__ C1, int M1, int N1, int nc1, int nblk1,
                      const float* __restrict__ A2,
                      const __nv_bfloat16* __restrict__ Bhi2,
                      const __nv_bfloat16* __restrict__ Blo2,
                      const float* __restrict__ bias2,
                      float* __restrict__ C2, int M2, int N2, int nc2)
{
    extern __shared__ char smem[];
    // layout: A_hi 0..8K | A_lo 8K..16K | B_hi 16K..32K | B_lo 32K..48K
    const uint32_t sa_hi = smem_u32(smem);
    const uint32_t sa_lo = sa_hi + 8192u;
    const uint32_t sb_hi = sa_hi + 16384u;
    const uint32_t sb_lo = sa_hi + 32768u;

    const float* A; const __nv_bfloat16* Bhi; const __nv_bfloat16* Blo;
    const float* bias; float* C;
    int M, N, brow, bcol;
    {
        int bid = blockIdx.x;
        if (bid < nblk1) {
            A = A1; Bhi = Bhi1; Blo = Blo1; bias = bias1; C = C1; M = M1; N = N1;
            brow = (bid / nc1) * 64; bcol = (bid % nc1) * 128;
        } else {
            bid -= nblk1;
            A = A2; Bhi = Bhi2; Blo = Blo2; bias = bias2; C = C2; M = M2; N = N2;
            brow = (bid / nc2) * 64; bcol = (bid % nc2) * 128;
        }
    }

    const int tid = threadIdx.x, lane = tid & 31, wid = tid >> 5;
    const int wc = wid * 32;        // warp col base (0,32,64,96); all warps span 64 rows

    float acc[4][4][4];
#pragma unroll
    for (int i = 0; i < 4; i++)
#pragma unroll
        for (int j = 0; j < 4; j++)
#pragma unroll
            for (int k = 0; k < 4; k++) acc[i][j][k] = 0.f;

    const int a_r  = (lane & 15);
    const int a_kx = (lane >> 4) << 4;
    const int b_r0 = wc + (lane & 7) + ((lane >> 4) << 3);
    const int b_kx = ((lane >> 3) & 1) << 4;

    const int nk = KDIM / 64;   // 4
    for (int kc = 0; kc < nk; kc++) {
        if (kc) __syncthreads();   // previous compute must finish before overwrite

        // ---- B chunk via cp.async (128 rows x 128B, hi+lo) ----
#pragma unroll
        for (int i = 0; i < 8; i++) {
            int t = i * 128 + tid;
            int r = t >> 3, j = t & 7;
            uint32_t d = SMEM_SWIZZLE_128B((uint32_t)(r * 128 + j * 16));
            size_t src = (size_t)(bcol + r) * KDIM + kc * 64 + j * 8;
            cp16(sb_hi + d, Bhi + src);
            cp16(sb_lo + d, Blo + src);
        }
        cp_commit();

        // ---- A chunk via LDG -> split -> STS (64 rows x 64 f32), 2 batches ----
#pragma unroll
        for (int bb = 0; bb < 2; bb++) {
            float4 a4[4];
#pragma unroll
            for (int i = 0; i < 4; i++) {
                int t = (bb * 4 + i) * 128 + tid;
                int r = t >> 4, jc = t & 15;
                a4[i] = (brow + r < M)
                    ? __ldg((const float4*)(A + (size_t)(brow + r) * KDIM + kc * 64 + jc * 4))
                    : make_float4(0.f, 0.f, 0.f, 0.f);
            }
#pragma unroll
            for (int i = 0; i < 4; i++) {
                int t = (bb * 4 + i) * 128 + tid;
                int r = t >> 4, jc = t & 15;
                uint32_t d = SMEM_SWIZZLE_128B((uint32_t)(r * 128 + (jc >> 1) * 16)) + (jc & 1) * 8;
                uint2 ho, lo;
                split4(a4[i], ho, lo);
                *(uint2*)(smem + d) = ho;
                *(uint2*)(smem + 8192u + d) = lo;
            }
        }
        cp_wait0();
        __syncthreads();

        // ---- compute: per kk, 12 ldmatrix.x4 feed 48 MMAs ----
#pragma unroll
        for (int kk = 0; kk < 4; kk++) {
            const uint32_t kbA = (uint32_t)(kk * 32 + a_kx);
            const uint32_t kbB = (uint32_t)(kk * 32 + b_kx);

            uint32_t ahi[4][4], bhi[4][2];
#pragma unroll
            for (int mi = 0; mi < 4; mi++)
                ldm_x4(ahi[mi], sa_hi + SMEM_SWIZZLE_128B((uint32_t)((a_r + mi * 16) * 128) + kbA));
#pragma unroll
            for (int nj = 0; nj < 2; nj++) {
                uint32_t rr[4];
                ldm_x4(rr, sb_hi + SMEM_SWIZZLE_128B((uint32_t)((b_r0 + nj * 16) * 128) + kbB));
                bhi[nj * 2][0] = rr[0]; bhi[nj * 2][1] = rr[1];
                bhi[nj * 2 + 1][0] = rr[2]; bhi[nj * 2 + 1][1] = rr[3];
            }
            // pass 0: hi * hi
#pragma unroll
            for (int mi = 0; mi < 4; mi++)
#pragma unroll
                for (int ni = 0; ni < 4; ni++)
                    mma16816(acc[mi][ni], ahi[mi], bhi[ni]);

            {
                uint32_t blo[4][2];
#pragma unroll
                for (int nj = 0; nj < 2; nj++) {
                    uint32_t rr[4];
                    ldm_x4(rr, sb_lo + SMEM_SWIZZLE_128B((uint32_t)((b_r0 + nj * 16) * 128) + kbB));
                    blo[nj * 2][0] = rr[0]; blo[nj * 2][1] = rr[1];
                    blo[nj * 2 + 1][0] = rr[2]; blo[nj * 2 + 1][1] = rr[3];
                }
                // pass 1: hi * lo
#pragma unroll
                for (int mi = 0; mi < 4; mi++)
#pragma unroll
                    for (int ni = 0; ni < 4; ni++)
                        mma16816(acc[mi][ni], ahi[mi], blo[ni]);
            }

            {
                uint32_t alo[4][4];
#pragma unroll
                for (int mi = 0; mi < 4; mi++)
                    ldm_x4(alo[mi], sa_lo + SMEM_SWIZZLE_128B((uint32_t)((a_r + mi * 16) * 128) + kbA));
                // pass 2: lo * hi
#pragma unroll
                for (int mi = 0; mi < 4; mi++)
#pragma unroll
                    for (int ni = 0; ni < 4; ni++)
                        mma16816(acc[mi][ni], alo[mi], bhi[ni]);
            }
        }
    }

    // ---- epilogue: bias + float2 stores ----
    const int row0 = brow + (lane >> 2);
#pragma unroll
    for (int ni = 0; ni < 4; ni++) {
        int col = bcol + wc + ni * 8 + (lane & 3) * 2;
        float2 bb = *(const float2*)&bias[col];
#pragma unroll
        for (int mi = 0; mi < 4; mi++) {
            int r0 = row0 + mi * 16;
            if (r0 < M) {
                float2 o;
                o.x = acc[mi][ni][0] + bb.x;
                o.y = acc[mi][ni][1] + bb.y;
                *(float2*)(C + (size_t)r0 * N + col) = o;
            }
            int r1 = r0 + 8;
            if (r1 < M) {
                float2 o;
                o.x = acc[mi][ni][2] + bb.x;
                o.y = acc[mi][ni][3] + bb.y;
                *(float2*)(C + (size_t)r1 * N + col) = o;
            }
        }
    }
}

// ---------------------------------------------------------------------------
// Fused softmax + bilinear sampling (owner-lane precompute; R8 config).
// ---------------------------------------------------------------------------
__global__ __launch_bounds__(256)
void msda_sample_kernel(const float* __restrict__ ref)
{
    int warp_global = blockIdx.x * (blockDim.x >> 5) + (threadIdx.x >> 5);
    if (warp_global >= Bb * LQ * 2) return;
    int lane = threadIdx.x & 31;
    int g = lane >> 3;
    int r = lane & 7;

    int hpair = warp_global & 1;
    int bq    = warp_global >> 1;
    int b     = bq / LQ;
    int hh    = hpair * 4 + g;

    const float2* awp = (const float2*)(g_offaw + (size_t)bq * 384 + 256 + hh * 16);
    float2 lg = awp[r];
    float m = fmaxf(lg.x, lg.y);
#pragma unroll
    for (int o = 4; o > 0; o >>= 1) m = fmaxf(m, __shfl_xor_sync(0xffffffffu, m, o));
    float e0 = __expf(lg.x - m);
    float e1 = __expf(lg.y - m);
    float s = e0 + e1;
#pragma unroll
    for (int o = 4; o > 0; o >>= 1) s += __shfl_xor_sync(0xffffffffu, s, o);
    float inv = 1.f / s;
    float w0 = e0 * inv;
    float w1 = e1 * inv;

    const float4* offp = (const float4*)(g_offaw + (size_t)bq * 384 + hh * 32);
    float4 off4 = offp[r];

    int l  = r >> 1;
    int HW = 80 >> l;
    int start = (l > 0 ? 6400 : 0) + (l > 1 ? 1600 : 0) + (l > 2 ? 400 : 0);
    float fHW = (float)HW;
    float2 rxy = __ldg((const float2*)ref + (size_t)bq * 4 + l);

    float cA[4], cB[4];
    uint32_t pkA0, pkA1, pkB0, pkB1;
#pragma unroll
    for (int pt = 0; pt < 2; pt++) {
        float ox = pt ? off4.z : off4.x;
        float oy = pt ? off4.w : off4.y;
        float aw = pt ? w1 : w0;

        float x = fmaf(rxy.x, fHW, ox - 0.5f);
        float y = fmaf(rxy.y, fHW, oy - 0.5f);
        float x0f = floorf(x), y0f = floorf(y);
        float wx = x - x0f, wy = y - y0f;
        int x0 = (int)x0f, y0 = (int)y0f;
        int x1 = x0 + 1,   y1 = y0 + 1;

        float vx0 = (x0 >= 0 && x0 < HW) ? 1.f : 0.f;
        float vx1 = (x1 >= 0 && x1 < HW) ? 1.f : 0.f;
        float vy0 = (y0 >= 0 && y0 < HW) ? 1.f : 0.f;
        float vy1 = (y1 >= 0 && y1 < HW) ? 1.f : 0.f;

        int cx0 = min(max(x0, 0), HW - 1);
        int cx1 = min(max(x1, 0), HW - 1);
        int cy0 = min(max(y0, 0), HW - 1);
        int cy1 = min(max(y1, 0), HW - 1);

        uint32_t p00 = (uint32_t)(start + cy0 * HW + cx0);
        uint32_t p01 = (uint32_t)(start + cy0 * HW + cx1);
        uint32_t p10 = (uint32_t)(start + cy1 * HW + cx0);
        uint32_t p11 = (uint32_t)(start + cy1 * HW + cx1);

        float wx1 = 1.f - wx, wy1 = 1.f - wy;
        float c0 = aw * wx1 * wy1 * vx0 * vy0;
        float c1 = aw * wx  * wy1 * vx1 * vy0;
        float c2 = aw * wx1 * wy  * vx0 * vy1;
        float c3 = aw * wx  * wy  * vx1 * vy1;

        if (pt == 0) {
            cA[0] = c0; cA[1] = c1; cA[2] = c2; cA[3] = c3;
            pkA0 = p00 | (p01 << 16); pkA1 = p10 | (p11 << 16);
        } else {
            cB[0] = c0; cB[1] = c1; cB[2] = c2; cB[3] = c3;
            pkB0 = p00 | (p01 << 16); pkB1 = p10 | (p11 << 16);
        }
    }

    const float* pbase = g_v + (size_t)b * LVTOT * Ee + hh * HEAD_DIM + r * 4;
    float4 acc = make_float4(0.f, 0.f, 0.f, 0.f);

#pragma unroll
    for (int j = 0; j < 8; j++) {
        int src = (g << 3) + j;
#pragma unroll
        for (int pt = 0; pt < 2; pt++) {
            float c0 = __shfl_sync(0xffffffffu, pt ? cB[0] : cA[0], src);
            float c1 = __shfl_sync(0xffffffffu, pt ? cB[1] : cA[1], src);
            float c2 = __shfl_sync(0xffffffffu, pt ? cB[2] : cA[2], src);
            float c3 = __shfl_sync(0xffffffffu, pt ? cB[3] : cA[3], src);
            uint32_t q0 = __shfl_sync(0xffffffffu, pt ? pkB0 : pkA0, src);
            uint32_t q1 = __shfl_sync(0xffffffffu, pt ? pkB1 : pkA1, src);

            uint32_t i00 = q0 & 0xffffu, i01 = q0 >> 16;
            uint32_t i10 = q1 & 0xffffu, i11 = q1 >> 16;

            float4 v00 = __ldg((const float4*)(pbase + (size_t)i00 * Ee));
            float4 v01 = __ldg((const float4*)(pbase + (size_t)i01 * Ee));
            float4 v10 = __ldg((const float4*)(pbase + (size_t)i10 * Ee));
            float4 v11 = __ldg((const float4*)(pbase + (size_t)i11 * Ee));

            acc.x = fmaf(c0, v00.x, fmaf(c1, v01.x, fmaf(c2, v10.x, fmaf(c3, v11.x, acc.x))));
            acc.y = fmaf(c0, v00.y, fmaf(c1, v01.y, fmaf(c2, v10.y, fmaf(c3, v11.y, acc.y))));
            acc.z = fmaf(c0, v00.z, fmaf(c1, v01.z, fmaf(c2, v10.z, fmaf(c3, v11.z, acc.z))));
            acc.w = fmaf(c0, v00.w, fmaf(c1, v01.w, fmaf(c2, v10.w, fmaf(c3, v11.w, acc.w))));
        }
    }

    *(float4*)(g_tmp + (size_t)bq * Ee + hh * HEAD_DIM + r * 4) = acc;
}

// ---------------------------------------------------------------------------
extern "C" void kernel_launch(void* const* d_in, const int* in_sizes, int n_in,
                              void* d_out, int out_size)
{
    const float* query = (const float*)d_in[0];
    const float* ref   = (const float*)d_in[1];
    const float* value = (const float*)d_in[2];
    const float* Wv    = (const float*)d_in[4];
    const float* bv    = (const float*)d_in[5];
    const float* Woff  = (const float*)d_in[6];
    const float* boff  = (const float*)d_in[7];
    const float* Wattn = (const float*)d_in[8];
    const float* battn = (const float*)d_in[9];
    const float* Wo    = (const float*)d_in[10];
    const float* bo    = (const float*)d_in[11];
    float* out = (float*)d_out;

    float *pv, *poffaw, *ptmp, *pbc;
    __nv_bfloat16 *pwhi, *pwlo;
    cudaGetSymbolAddress((void**)&pv,     g_v);
    cudaGetSymbolAddress((void**)&poffaw, g_offaw);
    cudaGetSymbolAddress((void**)&ptmp,   g_tmp);
    cudaGetSymbolAddress((void**)&pbc,    g_bias_comb);
    cudaGetSymbolAddress((void**)&pwhi,   g_wt_hi);
    cudaGetSymbolAddress((void**)&pwlo,   g_wt_lo);

    cudaFuncSetAttribute(gemm_dual_bf16x3,
                         cudaFuncAttributeMaxDynamicSharedMemorySize, 49152);

    // ---- prep (single launch) ----
    prep_weights_kernel<<<(WT_TOTAL + 255) / 256, 256>>>(Wv, Woff, Wattn, Wo, boff, battn);

    // ---- GEMM 1+2 merged: g_v = value@Wv+bv  AND  g_offaw = query@[Woff|Wattn]+bias ----
    {
        const int rows1 = (MV + 63) / 64;          // 532
        const int nblk1 = rows1 * 2;               // 1064  (N=256 -> nc1=2)
        const int rows2 = (MQ + 63) / 64;          // 525
        const int nblk2 = rows2 * 3;               // 1575  (N=384 -> nc2=3)
        gemm_dual_bf16x3<<<nblk1 + nblk2, 128, 49152>>>(
            value, pwhi + WT_WV,   pwlo + WT_WV,   bv,  pv,     MV, 256, 2, nblk1,
            query, pwhi + WT_COMB, pwlo + WT_COMB, pbc, poffaw, MQ, 384, 3);
    }
    // ---- sampler ----
    {
        int total_warps = Bb * LQ * 2;
        int blocks = (total_warps + 7) / 8;
        msda_sample_kernel<<<blocks, 256>>>(ref);
    }
    // ---- GEMM 3: out = g_tmp @ Wo + bo ----
    {
        const int rows3 = (MQ + 63) / 64;          // 525
        const int nblk3 = rows3 * 2;               // 1050
        gemm_dual_bf16x3<<<nblk3, 128, 49152>>>(
            ptmp, pwhi + WT_WO, pwlo + WT_WO, bo, out, MQ, 256, 2, nblk3,
            ptmp, pwhi + WT_WO, pwlo + WT_WO, bo, out, MQ, 256, 2);
    }
}

// round 11
// speedup vs baseline: 1.0894x; 1.0884x over previous
#include <cuda_runtime.h>
#include <cuda_fp16.h>
#include <math.h>
#include <stdint.h>

#define Bb 4
#define LQ 8400
#define Ee 256
#define HEADS 8
#define LEVELS 4
#define POINTS 4
#define HEAD_DIM 32
#define LVTOT 8500
#define KDIM 256

#define MQ (Bb * LQ)     // 33600
#define MV (Bb * LVTOT)  // 34000

// ---------------- scratch (device globals; no allocation allowed) ----------
__device__ float g_v[MV * Ee];            // value @ Wv + bv (f32, sampler input)
__device__ float g_offaw[MQ * 384];       // [off(256) | aw(128)] fused GEMM output
__device__ float g_tmp[MQ * Ee];          // sampler output (f32)
__device__ float g_bias_comb[384];

// transposed weights [N][K] fp16 (single precision level — B rounding ~2^-12)
#define WT_WV    0
#define WT_COMB  65536
#define WT_WO    163840
#define WT_TOTAL 229376
__device__ __half g_wt[WT_TOTAL];

// ---------------- helpers ----------------------------------------------
#define SMEM_SWIZZLE_128B(byte_offset) \
    ((byte_offset) ^ (((byte_offset) >> 3) & 0x70))

__device__ __forceinline__ uint32_t smem_u32(const void* p) {
    uint32_t a;
    asm("{ .reg .u64 t; cvta.to.shared.u64 t, %1; cvt.u32.u64 %0, t; }"
        : "=r"(a) : "l"(p));
    return a;
}

__device__ __forceinline__ void cp16(uint32_t dst, const void* src) {
    asm volatile("cp.async.cg.shared.global [%0], [%1], 16;"
                 :: "r"(dst), "l"(src));
}

__device__ __forceinline__ void cp_commit() {
    asm volatile("cp.async.commit_group;" ::: "memory");
}
__device__ __forceinline__ void cp_wait0() {
    asm volatile("cp.async.wait_group 0;" ::: "memory");
}

__device__ __forceinline__ void ldm_x4(uint32_t* r, uint32_t addr) {
    asm volatile("ldmatrix.sync.aligned.m8n8.x4.shared.b16 {%0,%1,%2,%3}, [%4];"
                 : "=r"(r[0]), "=r"(r[1]), "=r"(r[2]), "=r"(r[3]) : "r"(addr));
}

__device__ __forceinline__ void mma16816h(float* c, const uint32_t* a, const uint32_t* b) {
    asm volatile("mma.sync.aligned.m16n8k16.row.col.f32.f16.f16.f32 "
                 "{%0,%1,%2,%3}, {%4,%5,%6,%7}, {%8,%9}, {%0,%1,%2,%3};"
                 : "+f"(c[0]), "+f"(c[1]), "+f"(c[2]), "+f"(c[3])
                 : "r"(a[0]), "r"(a[1]), "r"(a[2]), "r"(a[3]),
                   "r"(b[0]), "r"(b[1]));
}

// float4 -> fp16 hi (uint2 = 4 halves) and fp16 lo residual (uint2)
__device__ __forceinline__ void split4h(float4 v, uint2& ho, uint2& lo) {
    __half h0 = __float2half_rn(v.x);
    __half h1 = __float2half_rn(v.y);
    __half h2 = __float2half_rn(v.z);
    __half h3 = __float2half_rn(v.w);
    __half l0 = __float2half_rn(v.x - __half2float(h0));
    __half l1 = __float2half_rn(v.y - __half2float(h1));
    __half l2 = __float2half_rn(v.z - __half2float(h2));
    __half l3 = __float2half_rn(v.w - __half2float(h3));
    __half2 hp0 = __halves2half2(h0, h1);
    __half2 hp1 = __halves2half2(h2, h3);
    __half2 lp0 = __halves2half2(l0, l1);
    __half2 lp1 = __halves2half2(l2, l3);
    ho.x = *(uint32_t*)&hp0; ho.y = *(uint32_t*)&hp1;
    lo.x = *(uint32_t*)&lp0; lo.y = *(uint32_t*)&lp1;
}

// ---------------------------------------------------------------------------
// ONE prep kernel: all 4 weight transposes (fp16) + bias concat.
// ---------------------------------------------------------------------------
__global__ void prep_weights_kernel(const float* __restrict__ Wv,
                                    const float* __restrict__ Woff,
                                    const float* __restrict__ Wattn,
                                    const float* __restrict__ Wo,
                                    const float* __restrict__ boff,
                                    const float* __restrict__ battn)
{
    int idx = blockIdx.x * blockDim.x + threadIdx.x;
    if (idx < 384)
        g_bias_comb[idx] = (idx < 256) ? boff[idx] : battn[idx - 256];
    if (idx >= WT_TOTAL) return;

    const float* W;
    int Nd, out, t = idx;
    if (t < 65536)        { W = Wv;    Nd = 256; out = WT_WV; }
    else if (t < 131072)  { W = Woff;  Nd = 256; out = WT_COMB;          t -= 65536; }
    else if (t < 163840)  { W = Wattn; Nd = 128; out = WT_COMB + 65536;  t -= 131072; }
    else                  { W = Wo;    Nd = 256; out = WT_WO;            t -= 163840; }

    int k = t / Nd, n = t % Nd;
    g_wt[out + n * 256 + k] = __float2half_rn(W[k * Nd + n]);
}

// ---------------------------------------------------------------------------
// mma.sync fp16x2 GEMM. CTA tile 64x128, 256 threads (8 warps, warp 32x32).
// A split fp16 hi/lo in-kernel (2 passes); B fp16 single.
// smem 32KB single stage: A_hi 8K | A_lo 8K | B 16K.
// Dual-problem dispatch: blocks [0, nblk1) -> problem 1, rest -> problem 2.
// ---------------------------------------------------------------------------
__global__ __launch_bounds__(256, 4)
void gemm_dual_fp16x2(const float* __restrict__ A1,
                      const __half* __restrict__ B1,
                      const float* __restrict__ bias1,
                      float* __restrict__ C1, int M1, int N1, int nc1, int nblk1,
                      const float* __restrict__ A2,
                      const __half* __restrict__ B2,
                      const float* __restrict__ bias2,
                      float* __restrict__ C2, int M2, int N2, int nc2)
{
    extern __shared__ char smem[];
    // layout: A_hi 0..8K | A_lo 8K..16K | B 16K..32K
    const uint32_t sa_hi = smem_u32(smem);
    const uint32_t sa_lo = sa_hi + 8192u;
    const uint32_t sb    = sa_hi + 16384u;

    const float* A; const __half* B; const float* bias; float* C;
    int M, N, brow, bcol;
    {
        int bid = blockIdx.x;
        if (bid < nblk1) {
            A = A1; B = B1; bias = bias1; C = C1; M = M1; N = N1;
            brow = (bid / nc1) * 64; bcol = (bid % nc1) * 128;
        } else {
            bid -= nblk1;
            A = A2; B = B2; bias = bias2; C = C2; M = M2; N = N2;
            brow = (bid / nc2) * 64; bcol = (bid % nc2) * 128;
        }
    }

    const int tid = threadIdx.x, lane = tid & 31, wid = tid >> 5;
    const int wr = (wid >> 2) * 32;   // 0 or 32
    const int wc = (wid & 3) * 32;    // 0,32,64,96

    float acc[2][4][4];
#pragma unroll
    for (int i = 0; i < 2; i++)
#pragma unroll
        for (int j = 0; j < 4; j++)
#pragma unroll
            for (int k = 0; k < 4; k++) acc[i][j][k] = 0.f;

    const int a_r  = wr + (lane & 15);
    const int a_kx = (lane >> 4) << 4;
    const int b_r0 = wc + (lane & 7) + ((lane >> 4) << 3);
    const int b_kx = ((lane >> 3) & 1) << 4;

    const int nk = KDIM / 64;   // 4
    for (int kc = 0; kc < nk; kc++) {
        if (kc) __syncthreads();   // previous compute must finish before overwrite

        // ---- B chunk via cp.async (128 rows x 64 halfs = 128B/row) ----
#pragma unroll
        for (int i = 0; i < 4; i++) {
            int t = i * 256 + tid;
            int r = t >> 3, j = t & 7;
            uint32_t d = SMEM_SWIZZLE_128B((uint32_t)(r * 128 + j * 16));
            size_t src = (size_t)(bcol + r) * KDIM + kc * 64 + j * 8;
            cp16(sb + d, B + src);
        }
        cp_commit();

        // ---- A chunk via LDG -> fp16 split -> STS (64 rows x 64 f32) ----
        float4 a4[4];
#pragma unroll
        for (int i = 0; i < 4; i++) {
            int t = i * 256 + tid;
            int r = t >> 4, jc = t & 15;
            a4[i] = (brow + r < M)
                ? __ldg((const float4*)(A + (size_t)(brow + r) * KDIM + kc * 64 + jc * 4))
                : make_float4(0.f, 0.f, 0.f, 0.f);
        }
#pragma unroll
        for (int i = 0; i < 4; i++) {
            int t = i * 256 + tid;
            int r = t >> 4, jc = t & 15;
            uint32_t d = SMEM_SWIZZLE_128B((uint32_t)(r * 128 + (jc >> 1) * 16)) + (jc & 1) * 8;
            uint2 ho, lo;
            split4h(a4[i], ho, lo);
            *(uint2*)(smem + d) = ho;
            *(uint2*)(smem + 8192u + d) = lo;
        }
        cp_wait0();
        __syncthreads();

        // ---- compute: per kk, 6 ldmatrix.x4 feed 16 MMAs (2 passes) ----
#pragma unroll
        for (int kk = 0; kk < 4; kk++) {
            const uint32_t kbA = (uint32_t)(kk * 32 + a_kx);
            const uint32_t kbB = (uint32_t)(kk * 32 + b_kx);

            uint32_t ahi[2][4], bf[4][2];
#pragma unroll
            for (int mi = 0; mi < 2; mi++)
                ldm_x4(ahi[mi], sa_hi + SMEM_SWIZZLE_128B((uint32_t)((a_r + mi * 16) * 128) + kbA));
#pragma unroll
            for (int nj = 0; nj < 2; nj++) {
                uint32_t rr[4];
                ldm_x4(rr, sb + SMEM_SWIZZLE_128B((uint32_t)((b_r0 + nj * 16) * 128) + kbB));
                bf[nj * 2][0] = rr[0]; bf[nj * 2][1] = rr[1];
                bf[nj * 2 + 1][0] = rr[2]; bf[nj * 2 + 1][1] = rr[3];
            }
            // pass 0: a_hi * b
#pragma unroll
            for (int mi = 0; mi < 2; mi++)
#pragma unroll
                for (int ni = 0; ni < 4; ni++)
                    mma16816h(acc[mi][ni], ahi[mi], bf[ni]);

            uint32_t alo[2][4];
#pragma unroll
            for (int mi = 0; mi < 2; mi++)
                ldm_x4(alo[mi], sa_lo + SMEM_SWIZZLE_128B((uint32_t)((a_r + mi * 16) * 128) + kbA));
            // pass 1: a_lo * b
#pragma unroll
            for (int mi = 0; mi < 2; mi++)
#pragma unroll
                for (int ni = 0; ni < 4; ni++)
                    mma16816h(acc[mi][ni], alo[mi], bf[ni]);
        }
    }

    // ---- epilogue: bias + float2 stores ----
    const int row0 = brow + wr + (lane >> 2);
#pragma unroll
    for (int ni = 0; ni < 4; ni++) {
        int col = bcol + wc + ni * 8 + (lane & 3) * 2;
        float2 bb = *(const float2*)&bias[col];
#pragma unroll
        for (int mi = 0; mi < 2; mi++) {
            int r0 = row0 + mi * 16;
            if (r0 < M) {
                float2 o;
                o.x = acc[mi][ni][0] + bb.x;
                o.y = acc[mi][ni][1] + bb.y;
                *(float2*)(C + (size_t)r0 * N + col) = o;
            }
            int r1 = r0 + 8;
            if (r1 < M) {
                float2 o;
                o.x = acc[mi][ni][2] + bb.x;
                o.y = acc[mi][ni][3] + bb.y;
                *(float2*)(C + (size_t)r1 * N + col) = o;
            }
        }
    }
}

// ---------------------------------------------------------------------------
// Fused softmax + bilinear sampling (owner-lane precompute; R8 config).
// ---------------------------------------------------------------------------
__global__ __launch_bounds__(256)
void msda_sample_kernel(const float* __restrict__ ref)
{
    int warp_global = blockIdx.x * (blockDim.x >> 5) + (threadIdx.x >> 5);
    if (warp_global >= Bb * LQ * 2) return;
    int lane = threadIdx.x & 31;
    int g = lane >> 3;
    int r = lane & 7;

    int hpair = warp_global & 1;
    int bq    = warp_global >> 1;
    int b     = bq / LQ;
    int hh    = hpair * 4 + g;

    const float2* awp = (const float2*)(g_offaw + (size_t)bq * 384 + 256 + hh * 16);
    float2 lg = awp[r];
    float m = fmaxf(lg.x, lg.y);
#pragma unroll
    for (int o = 4; o > 0; o >>= 1) m = fmaxf(m, __shfl_xor_sync(0xffffffffu, m, o));
    float e0 = __expf(lg.x - m);
    float e1 = __expf(lg.y - m);
    float s = e0 + e1;
#pragma unroll
    for (int o = 4; o > 0; o >>= 1) s += __shfl_xor_sync(0xffffffffu, s, o);
    float inv = 1.f / s;
    float w0 = e0 * inv;
    float w1 = e1 * inv;

    const float4* offp = (const float4*)(g_offaw + (size_t)bq * 384 + hh * 32);
    float4 off4 = offp[r];

    int l  = r >> 1;
    int HW = 80 >> l;
    int start = (l > 0 ? 6400 : 0) + (l > 1 ? 1600 : 0) + (l > 2 ? 400 : 0);
    float fHW = (float)HW;
    float2 rxy = __ldg((const float2*)ref + (size_t)bq * 4 + l);

    float cA[4], cB[4];
    uint32_t pkA0, pkA1, pkB0, pkB1;
#pragma unroll
    for (int pt = 0; pt < 2; pt++) {
        float ox = pt ? off4.z : off4.x;
        float oy = pt ? off4.w : off4.y;
        float aw = pt ? w1 : w0;

        float x = fmaf(rxy.x, fHW, ox - 0.5f);
        float y = fmaf(rxy.y, fHW, oy - 0.5f);
        float x0f = floorf(x), y0f = floorf(y);
        float wx = x - x0f, wy = y - y0f;
        int x0 = (int)x0f, y0 = (int)y0f;
        int x1 = x0 + 1,   y1 = y0 + 1;

        float vx0 = (x0 >= 0 && x0 < HW) ? 1.f : 0.f;
        float vx1 = (x1 >= 0 && x1 < HW) ? 1.f : 0.f;
        float vy0 = (y0 >= 0 && y0 < HW) ? 1.f : 0.f;
        float vy1 = (y1 >= 0 && y1 < HW) ? 1.f : 0.f;

        int cx0 = min(max(x0, 0), HW - 1);
        int cx1 = min(max(x1, 0), HW - 1);
        int cy0 = min(max(y0, 0), HW - 1);
        int cy1 = min(max(y1, 0), HW - 1);

        uint32_t p00 = (uint32_t)(start + cy0 * HW + cx0);
        uint32_t p01 = (uint32_t)(start + cy0 * HW + cx1);
        uint32_t p10 = (uint32_t)(start + cy1 * HW + cx0);
        uint32_t p11 = (uint32_t)(start + cy1 * HW + cx1);

        float wx1 = 1.f - wx, wy1 = 1.f - wy;
        float c0 = aw * wx1 * wy1 * vx0 * vy0;
        float c1 = aw * wx  * wy1 * vx1 * vy0;
        float c2 = aw * wx1 * wy  * vx0 * vy1;
        float c3 = aw * wx  * wy  * vx1 * vy1;

        if (pt == 0) {
            cA[0] = c0; cA[1] = c1; cA[2] = c2; cA[3] = c3;
            pkA0 = p00 | (p01 << 16); pkA1 = p10 | (p11 << 16);
        } else {
            cB[0] = c0; cB[1] = c1; cB[2] = c2; cB[3] = c3;
            pkB0 = p00 | (p01 << 16); pkB1 = p10 | (p11 << 16);
        }
    }

    const float* pbase = g_v + (size_t)b * LVTOT * Ee + hh * HEAD_DIM + r * 4;
    float4 acc = make_float4(0.f, 0.f, 0.f, 0.f);

#pragma unroll
    for (int j = 0; j < 8; j++) {
        int src = (g << 3) + j;
#pragma unroll
        for (int pt = 0; pt < 2; pt++) {
            float c0 = __shfl_sync(0xffffffffu, pt ? cB[0] : cA[0], src);
            float c1 = __shfl_sync(0xffffffffu, pt ? cB[1] : cA[1], src);
            float c2 = __shfl_sync(0xffffffffu, pt ? cB[2] : cA[2], src);
            float c3 = __shfl_sync(0xffffffffu, pt ? cB[3] : cA[3], src);
            uint32_t q0 = __shfl_sync(0xffffffffu, pt ? pkB0 : pkA0, src);
            uint32_t q1 = __shfl_sync(0xffffffffu, pt ? pkB1 : pkA1, src);

            uint32_t i00 = q0 & 0xffffu, i01 = q0 >> 16;
            uint32_t i10 = q1 & 0xffffu, i11 = q1 >> 16;

            float4 v00 = __ldg((const float4*)(pbase + (size_t)i00 * Ee));
            float4 v01 = __ldg((const float4*)(pbase + (size_t)i01 * Ee));
            float4 v10 = __ldg((const float4*)(pbase + (size_t)i10 * Ee));
            float4 v11 = __ldg((const float4*)(pbase + (size_t)i11 * Ee));

            acc.x = fmaf(c0, v00.x, fmaf(c1, v01.x, fmaf(c2, v10.x, fmaf(c3, v11.x, acc.x))));
            acc.y = fmaf(c0, v00.y, fmaf(c1, v01.y, fmaf(c2, v10.y, fmaf(c3, v11.y, acc.y))));
            acc.z = fmaf(c0, v00.z, fmaf(c1, v01.z, fmaf(c2, v10.z, fmaf(c3, v11.z, acc.z))));
            acc.w = fmaf(c0, v00.w, fmaf(c1, v01.w, fmaf(c2, v10.w, fmaf(c3, v11.w, acc.w))));
        }
    }

    *(float4*)(g_tmp + (size_t)bq * Ee + hh * HEAD_DIM + r * 4) = acc;
}

// ---------------------------------------------------------------------------
extern "C" void kernel_launch(void* const* d_in, const int* in_sizes, int n_in,
                              void* d_out, int out_size)
{
    const float* query = (const float*)d_in[0];
    const float* ref   = (const float*)d_in[1];
    const float* value = (const float*)d_in[2];
    const float* Wv    = (const float*)d_in[4];
    const float* bv    = (const float*)d_in[5];
    const float* Woff  = (const float*)d_in[6];
    const float* boff  = (const float*)d_in[7];
    const float* Wattn = (const float*)d_in[8];
    const float* battn = (const float*)d_in[9];
    const float* Wo    = (const float*)d_in[10];
    const float* bo    = (const float*)d_in[11];
    float* out = (float*)d_out;

    float *pv, *poffaw, *ptmp, *pbc;
    __half *pwt;
    cudaGetSymbolAddress((void**)&pv,     g_v);
    cudaGetSymbolAddress((void**)&poffaw, g_offaw);
    cudaGetSymbolAddress((void**)&ptmp,   g_tmp);
    cudaGetSymbolAddress((void**)&pbc,    g_bias_comb);
    cudaGetSymbolAddress((void**)&pwt,    g_wt);

    cudaFuncSetAttribute(gemm_dual_fp16x2,
                         cudaFuncAttributeMaxDynamicSharedMemorySize, 32768);

    // ---- prep (single launch) ----
    prep_weights_kernel<<<(WT_TOTAL + 255) / 256, 256>>>(Wv, Woff, Wattn, Wo, boff, battn);

    // ---- GEMM 1+2 merged: g_v = value@Wv+bv  AND  g_offaw = query@[Woff|Wattn]+bias ----
    {
        const int rows1 = (MV + 63) / 64;          // 532
        const int nblk1 = rows1 * 2;               // 1064  (N=256 -> nc1=2)
        const int rows2 = (MQ + 63) / 64;          // 525
        const int nblk2 = rows2 * 3;               // 1575  (N=384 -> nc2=3)
        gemm_dual_fp16x2<<<nblk1 + nblk2, 256, 32768>>>(
            value, pwt + WT_WV,   bv,  pv,     MV, 256, 2, nblk1,
            query, pwt + WT_COMB, pbc, poffaw, MQ, 384, 3);
    }
    // ---- sampler ----
    {
        int total_warps = Bb * LQ * 2;
        int blocks = (total_warps + 7) / 8;
        msda_sample_kernel<<<blocks, 256>>>(ref);
    }
    // ---- GEMM 3: out = g_tmp @ Wo + bo ----
    {
        const int rows3 = (MQ + 63) / 64;          // 525
        const int nblk3 = rows3 * 2;               // 1050
        gemm_dual_fp16x2<<<nblk3, 256, 32768>>>(
            ptmp, pwt + WT_WO, bo, out, MQ, 256, 2, nblk3,
            ptmp, pwt + WT_WO, bo, out, MQ, 256, 2);
    }
}

// round 12
// speedup vs baseline: 1.1605x; 1.0653x over previous
#include <cuda_runtime.h>
#include <cuda_fp16.h>
#include <math.h>
#include <stdint.h>

#define Bb 4
#define LQ 8400
#define Ee 256
#define HEADS 8
#define LEVELS 4
#define POINTS 4
#define HEAD_DIM 32
#define LVTOT 8500
#define KDIM 256

#define MQ (Bb * LQ)     // 33600
#define MV (Bb * LVTOT)  // 34000

// ---------------- scratch (device globals; no allocation allowed) ----------
__device__ float g_v[MV * Ee];            // value @ Wv + bv (f32, sampler input)
__device__ float g_offaw[MQ * 384];       // [off(256) | aw(128)] fused GEMM output
__device__ float g_tmp[MQ * Ee];          // sampler output (f32)
__device__ float g_bias_comb[384];

// transposed weights [N][K] fp16
#define WT_WV    0
#define WT_COMB  65536
#define WT_WO    163840
#define WT_TOTAL 229376
__device__ __half g_wt[WT_TOTAL];

// ---------------- helpers ----------------------------------------------
#define SMEM_SWIZZLE_128B(byte_offset) \
    ((byte_offset) ^ (((byte_offset) >> 3) & 0x70))

__device__ __forceinline__ uint32_t smem_u32(const void* p) {
    uint32_t a;
    asm("{ .reg .u64 t; cvta.to.shared.u64 t, %1; cvt.u32.u64 %0, t; }"
        : "=r"(a) : "l"(p));
    return a;
}

__device__ __forceinline__ void cp16(uint32_t dst, const void* src) {
    asm volatile("cp.async.cg.shared.global [%0], [%1], 16;"
                 :: "r"(dst), "l"(src));
}

__device__ __forceinline__ void cp_commit() {
    asm volatile("cp.async.commit_group;" ::: "memory");
}
__device__ __forceinline__ void cp_wait0() {
    asm volatile("cp.async.wait_group 0;" ::: "memory");
}

__device__ __forceinline__ void ldm_x4(uint32_t* r, uint32_t addr) {
    asm volatile("ldmatrix.sync.aligned.m8n8.x4.shared.b16 {%0,%1,%2,%3}, [%4];"
                 : "=r"(r[0]), "=r"(r[1]), "=r"(r[2]), "=r"(r[3]) : "r"(addr));
}

__device__ __forceinline__ void mma16816h(float* c, const uint32_t* a, const uint32_t* b) {
    asm volatile("mma.sync.aligned.m16n8k16.row.col.f32.f16.f16.f32 "
                 "{%0,%1,%2,%3}, {%4,%5,%6,%7}, {%8,%9}, {%0,%1,%2,%3};"
                 : "+f"(c[0]), "+f"(c[1]), "+f"(c[2]), "+f"(c[3])
                 : "r"(a[0]), "r"(a[1]), "r"(a[2]), "r"(a[3]),
                   "r"(b[0]), "r"(b[1]));
}

// float4 -> fp16 hi (uint2 = 4 halves) and fp16 lo residual (uint2)
__device__ __forceinline__ void split4h(float4 v, uint2& ho, uint2& lo) {
    __half h0 = __float2half_rn(v.x);
    __half h1 = __float2half_rn(v.y);
    __half h2 = __float2half_rn(v.z);
    __half h3 = __float2half_rn(v.w);
    __half l0 = __float2half_rn(v.x - __half2float(h0));
    __half l1 = __float2half_rn(v.y - __half2float(h1));
    __half l2 = __float2half_rn(v.z - __half2float(h2));
    __half l3 = __float2half_rn(v.w - __half2float(h3));
    __half2 hp0 = __halves2half2(h0, h1);
    __half2 hp1 = __halves2half2(h2, h3);
    __half2 lp0 = __halves2half2(l0, l1);
    __half2 lp1 = __halves2half2(l2, l3);
    ho.x = *(uint32_t*)&hp0; ho.y = *(uint32_t*)&hp1;
    lo.x = *(uint32_t*)&lp0; lo.y = *(uint32_t*)&lp1;
}

// ---------------------------------------------------------------------------
// ONE prep kernel: all 4 weight transposes (fp16) + bias concat.
// ---------------------------------------------------------------------------
__global__ void prep_weights_kernel(const float* __restrict__ Wv,
                                    const float* __restrict__ Woff,
                                    const float* __restrict__ Wattn,
                                    const float* __restrict__ Wo,
                                    const float* __restrict__ boff,
                                    const float* __restrict__ battn)
{
    int idx = blockIdx.x * blockDim.x + threadIdx.x;
    if (idx < 384)
        g_bias_comb[idx] = (idx < 256) ? boff[idx] : battn[idx - 256];
    if (idx >= WT_TOTAL) return;

    const float* W;
    int Nd, out, t = idx;
    if (t < 65536)        { W = Wv;    Nd = 256; out = WT_WV; }
    else if (t < 131072)  { W = Woff;  Nd = 256; out = WT_COMB;          t -= 65536; }
    else if (t < 163840)  { W = Wattn; Nd = 128; out = WT_COMB + 65536;  t -= 131072; }
    else                  { W = Wo;    Nd = 256; out = WT_WO;            t -= 163840; }

    int k = t / Nd, n = t % Nd;
    g_wt[out + n * 256 + k] = __float2half_rn(W[k * Nd + n]);
}

// ---------------------------------------------------------------------------
// mma.sync fp16x2 GEMM. CTA tile 64x128, 256 threads (8 warps, warp 32x32).
// A split fp16 hi/lo in-kernel; B fp16. TWO-STAGE pipeline:
// smem = 2 x 32KB (A_hi 8K | A_lo 8K | B 16K per stage) = 64KB -> 3 CTAs/SM.
// Dual-problem dispatch: blocks [0, nblk1) -> problem 1, rest -> problem 2.
// ---------------------------------------------------------------------------
__global__ __launch_bounds__(256, 3)
void gemm_dual_fp16x2(const float* __restrict__ A1,
                      const __half* __restrict__ B1,
                      const float* __restrict__ bias1,
                      float* __restrict__ C1, int M1, int N1, int nc1, int nblk1,
                      const float* __restrict__ A2,
                      const __half* __restrict__ B2,
                      const float* __restrict__ bias2,
                      float* __restrict__ C2, int M2, int N2, int nc2)
{
    extern __shared__ char smem[];
    const uint32_t sbase = smem_u32(smem);
    // per-stage layout: A_hi +0 | A_lo +8K | B +16K ; stage stride 32K

    const float* A; const __half* B; const float* bias; float* C;
    int M, N, brow, bcol;
    {
        int bid = blockIdx.x;
        if (bid < nblk1) {
            A = A1; B = B1; bias = bias1; C = C1; M = M1; N = N1;
            brow = (bid / nc1) * 64; bcol = (bid % nc1) * 128;
        } else {
            bid -= nblk1;
            A = A2; B = B2; bias = bias2; C = C2; M = M2; N = N2;
            brow = (bid / nc2) * 64; bcol = (bid % nc2) * 128;
        }
    }

    const int tid = threadIdx.x, lane = tid & 31, wid = tid >> 5;
    const int wr = (wid >> 2) * 32;   // 0 or 32
    const int wc = (wid & 3) * 32;    // 0,32,64,96

    float acc[2][4][4];
#pragma unroll
    for (int i = 0; i < 2; i++)
#pragma unroll
        for (int j = 0; j < 4; j++)
#pragma unroll
            for (int k = 0; k < 4; k++) acc[i][j][k] = 0.f;

    const int a_r  = wr + (lane & 15);
    const int a_kx = (lane >> 4) << 4;
    const int b_r0 = wc + (lane & 7) + ((lane >> 4) << 3);
    const int b_kx = ((lane >> 3) & 1) << 4;

    // A-load row/col for this thread (fixed across chunks)
    const int ldr = tid >> 2;            // used via t pattern below

    // ---- prologue: load chunk 0 into stage 0 ----
    {
#pragma unroll
        for (int i = 0; i < 4; i++) {
            int t = i * 256 + tid;
            int r = t >> 3, j = t & 7;
            uint32_t d = SMEM_SWIZZLE_128B((uint32_t)(r * 128 + j * 16));
            size_t src = (size_t)(bcol + r) * KDIM + j * 8;
            cp16(sbase + 16384u + d, B + src);
        }
        cp_commit();
        float4 a4[4];
#pragma unroll
        for (int i = 0; i < 4; i++) {
            int t = i * 256 + tid;
            int r = t >> 4, jc = t & 15;
            a4[i] = (brow + r < M)
                ? __ldg((const float4*)(A + (size_t)(brow + r) * KDIM + jc * 4))
                : make_float4(0.f, 0.f, 0.f, 0.f);
        }
#pragma unroll
        for (int i = 0; i < 4; i++) {
            int t = i * 256 + tid;
            int r = t >> 4, jc = t & 15;
            uint32_t d = SMEM_SWIZZLE_128B((uint32_t)(r * 128 + (jc >> 1) * 16)) + (jc & 1) * 8;
            uint2 ho, lo;
            split4h(a4[i], ho, lo);
            *(uint2*)(smem + d) = ho;
            *(uint2*)(smem + 8192u + d) = lo;
        }
        cp_wait0();
        __syncthreads();
    }
    (void)ldr;

    const int nk = KDIM / 64;   // 4
    for (int kc = 0; kc < nk; kc++) {
        const uint32_t curoff = (uint32_t)(kc & 1) * 32768u;
        const uint32_t nxtoff = curoff ^ 32768u;
        const bool hn = (kc + 1) < nk;

        float4 aPre[4];
        if (hn) {
            // issue next B cp.async + next A LDGs (overlap with compute below)
#pragma unroll
            for (int i = 0; i < 4; i++) {
                int t = i * 256 + tid;
                int r = t >> 3, j = t & 7;
                uint32_t d = SMEM_SWIZZLE_128B((uint32_t)(r * 128 + j * 16));
                size_t src = (size_t)(bcol + r) * KDIM + (kc + 1) * 64 + j * 8;
                cp16(sbase + nxtoff + 16384u + d, B + src);
            }
            cp_commit();
#pragma unroll
            for (int i = 0; i < 4; i++) {
                int t = i * 256 + tid;
                int r = t >> 4, jc = t & 15;
                aPre[i] = (brow + r < M)
                    ? __ldg((const float4*)(A + (size_t)(brow + r) * KDIM + (kc + 1) * 64 + jc * 4))
                    : make_float4(0.f, 0.f, 0.f, 0.f);
            }
        }

        // ---- compute on stage cur ----
        const uint32_t sa_hi = sbase + curoff;
        const uint32_t sa_lo = sa_hi + 8192u;
        const uint32_t sb    = sa_hi + 16384u;
#pragma unroll
        for (int kk = 0; kk < 4; kk++) {
            const uint32_t kbA = (uint32_t)(kk * 32 + a_kx);
            const uint32_t kbB = (uint32_t)(kk * 32 + b_kx);

            uint32_t ahi[2][4], bf[4][2];
#pragma unroll
            for (int mi = 0; mi < 2; mi++)
                ldm_x4(ahi[mi], sa_hi + SMEM_SWIZZLE_128B((uint32_t)((a_r + mi * 16) * 128) + kbA));
#pragma unroll
            for (int nj = 0; nj < 2; nj++) {
                uint32_t rr[4];
                ldm_x4(rr, sb + SMEM_SWIZZLE_128B((uint32_t)((b_r0 + nj * 16) * 128) + kbB));
                bf[nj * 2][0] = rr[0]; bf[nj * 2][1] = rr[1];
                bf[nj * 2 + 1][0] = rr[2]; bf[nj * 2 + 1][1] = rr[3];
            }
            // pass 0: a_hi * b
#pragma unroll
            for (int mi = 0; mi < 2; mi++)
#pragma unroll
                for (int ni = 0; ni < 4; ni++)
                    mma16816h(acc[mi][ni], ahi[mi], bf[ni]);

            uint32_t alo[2][4];
#pragma unroll
            for (int mi = 0; mi < 2; mi++)
                ldm_x4(alo[mi], sa_lo + SMEM_SWIZZLE_128B((uint32_t)((a_r + mi * 16) * 128) + kbA));
            // pass 1: a_lo * b
#pragma unroll
            for (int mi = 0; mi < 2; mi++)
#pragma unroll
                for (int ni = 0; ni < 4; ni++)
                    mma16816h(acc[mi][ni], alo[mi], bf[ni]);
        }

        if (hn) {
            // store prefetched A into next stage; wait B; one sync
#pragma unroll
            for (int i = 0; i < 4; i++) {
                int t = i * 256 + tid;
                int r = t >> 4, jc = t & 15;
                uint32_t d = SMEM_SWIZZLE_128B((uint32_t)(r * 128 + (jc >> 1) * 16)) + (jc & 1) * 8;
                uint2 ho, lo;
                split4h(aPre[i], ho, lo);
                *(uint2*)(smem + nxtoff + d) = ho;
                *(uint2*)(smem + nxtoff + 8192u + d) = lo;
            }
            cp_wait0();
            __syncthreads();
        }
    }

    // ---- epilogue: bias + float2 stores ----
    const int row0 = brow + wr + (lane >> 2);
#pragma unroll
    for (int ni = 0; ni < 4; ni++) {
        int col = bcol + wc + ni * 8 + (lane & 3) * 2;
        float2 bb = *(const float2*)&bias[col];
#pragma unroll
        for (int mi = 0; mi < 2; mi++) {
            int r0 = row0 + mi * 16;
            if (r0 < M) {
                float2 o;
                o.x = acc[mi][ni][0] + bb.x;
                o.y = acc[mi][ni][1] + bb.y;
                *(float2*)(C + (size_t)r0 * N + col) = o;
            }
            int r1 = r0 + 8;
            if (r1 < M) {
                float2 o;
                o.x = acc[mi][ni][2] + bb.x;
                o.y = acc[mi][ni][3] + bb.y;
                *(float2*)(C + (size_t)r1 * N + col) = o;
            }
        }
    }
}

// ---------------------------------------------------------------------------
// Fused softmax + bilinear sampling (owner-lane precompute; R8 config).
// ---------------------------------------------------------------------------
__global__ __launch_bounds__(256)
void msda_sample_kernel(const float* __restrict__ ref)
{
    int warp_global = blockIdx.x * (blockDim.x >> 5) + (threadIdx.x >> 5);
    if (warp_global >= Bb * LQ * 2) return;
    int lane = threadIdx.x & 31;
    int g = lane >> 3;
    int r = lane & 7;

    int hpair = warp_global & 1;
    int bq    = warp_global >> 1;
    int b     = bq / LQ;
    int hh    = hpair * 4 + g;

    const float2* awp = (const float2*)(g_offaw + (size_t)bq * 384 + 256 + hh * 16);
    float2 lg = awp[r];
    float m = fmaxf(lg.x, lg.y);
#pragma unroll
    for (int o = 4; o > 0; o >>= 1) m = fmaxf(m, __shfl_xor_sync(0xffffffffu, m, o));
    float e0 = __expf(lg.x - m);
    float e1 = __expf(lg.y - m);
    float s = e0 + e1;
#pragma unroll
    for (int o = 4; o > 0; o >>= 1) s += __shfl_xor_sync(0xffffffffu, s, o);
    float inv = 1.f / s;
    float w0 = e0 * inv;
    float w1 = e1 * inv;

    const float4* offp = (const float4*)(g_offaw + (size_t)bq * 384 + hh * 32);
    float4 off4 = offp[r];

    int l  = r >> 1;
    int HW = 80 >> l;
    int start = (l > 0 ? 6400 : 0) + (l > 1 ? 1600 : 0) + (l > 2 ? 400 : 0);
    float fHW = (float)HW;
    float2 rxy = __ldg((const float2*)ref + (size_t)bq * 4 + l);

    float cA[4], cB[4];
    uint32_t pkA0, pkA1, pkB0, pkB1;
#pragma unroll
    for (int pt = 0; pt < 2; pt++) {
        float ox = pt ? off4.z : off4.x;
        float oy = pt ? off4.w : off4.y;
        float aw = pt ? w1 : w0;

        float x = fmaf(rxy.x, fHW, ox - 0.5f);
        float y = fmaf(rxy.y, fHW, oy - 0.5f);
        float x0f = floorf(x), y0f = floorf(y);
        float wx = x - x0f, wy = y - y0f;
        int x0 = (int)x0f, y0 = (int)y0f;
        int x1 = x0 + 1,   y1 = y0 + 1;

        float vx0 = (x0 >= 0 && x0 < HW) ? 1.f : 0.f;
        float vx1 = (x1 >= 0 && x1 < HW) ? 1.f : 0.f;
        float vy0 = (y0 >= 0 && y0 < HW) ? 1.f : 0.f;
        float vy1 = (y1 >= 0 && y1 < HW) ? 1.f : 0.f;

        int cx0 = min(max(x0, 0), HW - 1);
        int cx1 = min(max(x1, 0), HW - 1);
        int cy0 = min(max(y0, 0), HW - 1);
        int cy1 = min(max(y1, 0), HW - 1);

        uint32_t p00 = (uint32_t)(start + cy0 * HW + cx0);
        uint32_t p01 = (uint32_t)(start + cy0 * HW + cx1);
        uint32_t p10 = (uint32_t)(start + cy1 * HW + cx0);
        uint32_t p11 = (uint32_t)(start + cy1 * HW + cx1);

        float wx1 = 1.f - wx, wy1 = 1.f - wy;
        float c0 = aw * wx1 * wy1 * vx0 * vy0;
        float c1 = aw * wx  * wy1 * vx1 * vy0;
        float c2 = aw * wx1 * wy  * vx0 * vy1;
        float c3 = aw * wx  * wy  * vx1 * vy1;

        if (pt == 0) {
            cA[0] = c0; cA[1] = c1; cA[2] = c2; cA[3] = c3;
            pkA0 = p00 | (p01 << 16); pkA1 = p10 | (p11 << 16);
        } else {
            cB[0] = c0; cB[1] = c1; cB[2] = c2; cB[3] = c3;
            pkB0 = p00 | (p01 << 16); pkB1 = p10 | (p11 << 16);
        }
    }

    const float* pbase = g_v + (size_t)b * LVTOT * Ee + hh * HEAD_DIM + r * 4;
    float4 acc = make_float4(0.f, 0.f, 0.f, 0.f);

#pragma unroll
    for (int j = 0; j < 8; j++) {
        int src = (g << 3) + j;
#pragma unroll
        for (int pt = 0; pt < 2; pt++) {
            float c0 = __shfl_sync(0xffffffffu, pt ? cB[0] : cA[0], src);
            float c1 = __shfl_sync(0xffffffffu, pt ? cB[1] : cA[1], src);
            float c2 = __shfl_sync(0xffffffffu, pt ? cB[2] : cA[2], src);
            float c3 = __shfl_sync(0xffffffffu, pt ? cB[3] : cA[3], src);
            uint32_t q0 = __shfl_sync(0xffffffffu, pt ? pkB0 : pkA0, src);
            uint32_t q1 = __shfl_sync(0xffffffffu, pt ? pkB1 : pkA1, src);

            uint32_t i00 = q0 & 0xffffu, i01 = q0 >> 16;
            uint32_t i10 = q1 & 0xffffu, i11 = q1 >> 16;

            float4 v00 = __ldg((const float4*)(pbase + (size_t)i00 * Ee));
            float4 v01 = __ldg((const float4*)(pbase + (size_t)i01 * Ee));
            float4 v10 = __ldg((const float4*)(pbase + (size_t)i10 * Ee));
            float4 v11 = __ldg((const float4*)(pbase + (size_t)i11 * Ee));

            acc.x = fmaf(c0, v00.x, fmaf(c1, v01.x, fmaf(c2, v10.x, fmaf(c3, v11.x, acc.x))));
            acc.y = fmaf(c0, v00.y, fmaf(c1, v01.y, fmaf(c2, v10.y, fmaf(c3, v11.y, acc.y))));
            acc.z = fmaf(c0, v00.z, fmaf(c1, v01.z, fmaf(c2, v10.z, fmaf(c3, v11.z, acc.z))));
            acc.w = fmaf(c0, v00.w, fmaf(c1, v01.w, fmaf(c2, v10.w, fmaf(c3, v11.w, acc.w))));
        }
    }

    *(float4*)(g_tmp + (size_t)bq * Ee + hh * HEAD_DIM + r * 4) = acc;
}

// ---------------------------------------------------------------------------
extern "C" void kernel_launch(void* const* d_in, const int* in_sizes, int n_in,
                              void* d_out, int out_size)
{
    const float* query = (const float*)d_in[0];
    const float* ref   = (const float*)d_in[1];
    const float* value = (const float*)d_in[2];
    const float* Wv    = (const float*)d_in[4];
    const float* bv    = (const float*)d_in[5];
    const float* Woff  = (const float*)d_in[6];
    const float* boff  = (const float*)d_in[7];
    const float* Wattn = (const float*)d_in[8];
    const float* battn = (const float*)d_in[9];
    const float* Wo    = (const float*)d_in[10];
    const float* bo    = (const float*)d_in[11];
    float* out = (float*)d_out;

    float *pv, *poffaw, *ptmp, *pbc;
    __half *pwt;
    cudaGetSymbolAddress((void**)&pv,     g_v);
    cudaGetSymbolAddress((void**)&poffaw, g_offaw);
    cudaGetSymbolAddress((void**)&ptmp,   g_tmp);
    cudaGetSymbolAddress((void**)&pbc,    g_bias_comb);
    cudaGetSymbolAddress((void**)&pwt,    g_wt);

    cudaFuncSetAttribute(gemm_dual_fp16x2,
                         cudaFuncAttributeMaxDynamicSharedMemorySize, 65536);

    // ---- prep (single launch) ----
    prep_weights_kernel<<<(WT_TOTAL + 255) / 256, 256>>>(Wv, Woff, Wattn, Wo, boff, battn);

    // ---- GEMM 1+2 merged: g_v = value@Wv+bv  AND  g_offaw = query@[Woff|Wattn]+bias ----
    {
        const int rows1 = (MV + 63) / 64;          // 532
        const int nblk1 = rows1 * 2;               // 1064  (N=256 -> nc1=2)
        const int rows2 = (MQ + 63) / 64;          // 525
        const int nblk2 = rows2 * 3;               // 1575  (N=384 -> nc2=3)
        gemm_dual_fp16x2<<<nblk1 + nblk2, 256, 65536>>>(
            value, pwt + WT_WV,   bv,  pv,     MV, 256, 2, nblk1,
            query, pwt + WT_COMB, pbc, poffaw, MQ, 384, 3);
    }
    // ---- sampler ----
    {
        int total_warps = Bb * LQ * 2;
        int blocks = (total_warps + 7) / 8;
        msda_sample_kernel<<<blocks, 256>>>(ref);
    }
    // ---- GEMM 3: out = g_tmp @ Wo + bo ----
    {
        const int rows3 = (MQ + 63) / 64;          // 525
        const int nblk3 = rows3 * 2;               // 1050
        gemm_dual_fp16x2<<<nblk3, 256, 65536>>>(
            ptmp, pwt + WT_WO, bo, out, MQ, 256, 2, nblk3,
            ptmp, pwt + WT_WO, bo, out, MQ, 256, 2);
    }
}

// round 13
// speedup vs baseline: 1.3381x; 1.1530x over previous
#include <cuda_runtime.h>
#include <cuda_fp16.h>
#include <math.h>
#include <stdint.h>

#define Bb 4
#define LQ 8400
#define Ee 256
#define HEADS 8
#define LEVELS 4
#define POINTS 4
#define HEAD_DIM 32
#define LVTOT 8500
#define KDIM 256

#define MQ (Bb * LQ)     // 33600
#define MV (Bb * LVTOT)  // 34000

// ---------------- scratch (device globals; no allocation allowed) ----------
__device__ __half g_vh[MV * Ee];          // value @ Wv + bv (fp16, sampler input)
__device__ float g_offaw[MQ * 384];       // [off(256) | aw(128)] fused GEMM output
__device__ float g_tmp[MQ * Ee];          // sampler output (f32)
__device__ float g_bias_comb[384];

// transposed weights [N][K] fp16
#define WT_WV    0
#define WT_COMB  65536
#define WT_WO    163840
#define WT_TOTAL 229376
__device__ __half g_wt[WT_TOTAL];

// ---------------- helpers ----------------------------------------------
#define SMEM_SWIZZLE_128B(byte_offset) \
    ((byte_offset) ^ (((byte_offset) >> 3) & 0x70))

__device__ __forceinline__ uint32_t smem_u32(const void* p) {
    uint32_t a;
    asm("{ .reg .u64 t; cvta.to.shared.u64 t, %1; cvt.u32.u64 %0, t; }"
        : "=r"(a) : "l"(p));
    return a;
}

__device__ __forceinline__ void cp16(uint32_t dst, const void* src) {
    asm volatile("cp.async.cg.shared.global [%0], [%1], 16;"
                 :: "r"(dst), "l"(src));
}

__device__ __forceinline__ void cp_commit() {
    asm volatile("cp.async.commit_group;" ::: "memory");
}
__device__ __forceinline__ void cp_wait0() {
    asm volatile("cp.async.wait_group 0;" ::: "memory");
}

__device__ __forceinline__ void ldm_x4(uint32_t* r, uint32_t addr) {
    asm volatile("ldmatrix.sync.aligned.m8n8.x4.shared.b16 {%0,%1,%2,%3}, [%4];"
                 : "=r"(r[0]), "=r"(r[1]), "=r"(r[2]), "=r"(r[3]) : "r"(addr));
}

__device__ __forceinline__ void mma16816h(float* c, const uint32_t* a, const uint32_t* b) {
    asm volatile("mma.sync.aligned.m16n8k16.row.col.f32.f16.f16.f32 "
                 "{%0,%1,%2,%3}, {%4,%5,%6,%7}, {%8,%9}, {%0,%1,%2,%3};"
                 : "+f"(c[0]), "+f"(c[1]), "+f"(c[2]), "+f"(c[3])
                 : "r"(a[0]), "r"(a[1]), "r"(a[2]), "r"(a[3]),
                   "r"(b[0]), "r"(b[1]));
}

// float4 -> fp16 hi (uint2 = 4 halves) and fp16 lo residual (uint2)
__device__ __forceinline__ void split4h(float4 v, uint2& ho, uint2& lo) {
    __half h0 = __float2half_rn(v.x);
    __half h1 = __float2half_rn(v.y);
    __half h2 = __float2half_rn(v.z);
    __half h3 = __float2half_rn(v.w);
    __half l0 = __float2half_rn(v.x - __half2float(h0));
    __half l1 = __float2half_rn(v.y - __half2float(h1));
    __half l2 = __float2half_rn(v.z - __half2float(h2));
    __half l3 = __float2half_rn(v.w - __half2float(h3));
    __half2 hp0 = __halves2half2(h0, h1);
    __half2 hp1 = __halves2half2(h2, h3);
    __half2 lp0 = __halves2half2(l0, l1);
    __half2 lp1 = __halves2half2(l2, l3);
    ho.x = *(uint32_t*)&hp0; ho.y = *(uint32_t*)&hp1;
    lo.x = *(uint32_t*)&lp0; lo.y = *(uint32_t*)&lp1;
}

// ---------------------------------------------------------------------------
// ONE prep kernel: all 4 weight transposes (fp16) + bias concat.
// ---------------------------------------------------------------------------
__global__ void prep_weights_kernel(const float* __restrict__ Wv,
                                    const float* __restrict__ Woff,
                                    const float* __restrict__ Wattn,
                                    const float* __restrict__ Wo,
                                    const float* __restrict__ boff,
                                    const float* __restrict__ battn)
{
    int idx = blockIdx.x * blockDim.x + threadIdx.x;
    if (idx < 384)
        g_bias_comb[idx] = (idx < 256) ? boff[idx] : battn[idx - 256];
    if (idx >= WT_TOTAL) return;

    const float* W;
    int Nd, out, t = idx;
    if (t < 65536)        { W = Wv;    Nd = 256; out = WT_WV; }
    else if (t < 131072)  { W = Woff;  Nd = 256; out = WT_COMB;          t -= 65536; }
    else if (t < 163840)  { W = Wattn; Nd = 128; out = WT_COMB + 65536;  t -= 131072; }
    else                  { W = Wo;    Nd = 256; out = WT_WO;            t -= 163840; }

    int k = t / Nd, n = t % Nd;
    g_wt[out + n * 256 + k] = __float2half_rn(W[k * Nd + n]);
}

// ---------------------------------------------------------------------------
// mma.sync fp16x2 GEMM. CTA tile 64x128, 256 threads (8 warps, warp 32x32).
// A split fp16 hi/lo in-kernel; B fp16. Two-stage pipeline, 64KB smem.
// oh flag: output fp16 (half2 stores) instead of f32.
// Dual-problem dispatch: blocks [0, nblk1) -> problem 1, rest -> problem 2.
// ---------------------------------------------------------------------------
__global__ __launch_bounds__(256, 3)
void gemm_dual_fp16x2(const float* __restrict__ A1,
                      const __half* __restrict__ B1,
                      const float* __restrict__ bias1,
                      void* __restrict__ C1, int M1, int N1, int nc1, int oh1, int nblk1,
                      const float* __restrict__ A2,
                      const __half* __restrict__ B2,
                      const float* __restrict__ bias2,
                      void* __restrict__ C2, int M2, int N2, int nc2, int oh2)
{
    extern __shared__ char smem[];
    const uint32_t sbase = smem_u32(smem);
    // per-stage layout: A_hi +0 | A_lo +8K | B +16K ; stage stride 32K

    const float* A; const __half* B; const float* bias; void* C;
    int M, N, brow, bcol, oh;
    {
        int bid = blockIdx.x;
        if (bid < nblk1) {
            A = A1; B = B1; bias = bias1; C = C1; M = M1; N = N1; oh = oh1;
            brow = (bid / nc1) * 64; bcol = (bid % nc1) * 128;
        } else {
            bid -= nblk1;
            A = A2; B = B2; bias = bias2; C = C2; M = M2; N = N2; oh = oh2;
            brow = (bid / nc2) * 64; bcol = (bid % nc2) * 128;
        }
    }

    const int tid = threadIdx.x, lane = tid & 31, wid = tid >> 5;
    const int wr = (wid >> 2) * 32;   // 0 or 32
    const int wc = (wid & 3) * 32;    // 0,32,64,96

    float acc[2][4][4];
#pragma unroll
    for (int i = 0; i < 2; i++)
#pragma unroll
        for (int j = 0; j < 4; j++)
#pragma unroll
            for (int k = 0; k < 4; k++) acc[i][j][k] = 0.f;

    const int a_r  = wr + (lane & 15);
    const int a_kx = (lane >> 4) << 4;
    const int b_r0 = wc + (lane & 7) + ((lane >> 4) << 3);
    const int b_kx = ((lane >> 3) & 1) << 4;

    // ---- prologue: load chunk 0 into stage 0 ----
    {
#pragma unroll
        for (int i = 0; i < 4; i++) {
            int t = i * 256 + tid;
            int r = t >> 3, j = t & 7;
            uint32_t d = SMEM_SWIZZLE_128B((uint32_t)(r * 128 + j * 16));
            size_t src = (size_t)(bcol + r) * KDIM + j * 8;
            cp16(sbase + 16384u + d, B + src);
        }
        cp_commit();
        float4 a4[4];
#pragma unroll
        for (int i = 0; i < 4; i++) {
            int t = i * 256 + tid;
            int r = t >> 4, jc = t & 15;
            a4[i] = (brow + r < M)
                ? __ldg((const float4*)(A + (size_t)(brow + r) * KDIM + jc * 4))
                : make_float4(0.f, 0.f, 0.f, 0.f);
        }
#pragma unroll
        for (int i = 0; i < 4; i++) {
            int t = i * 256 + tid;
            int r = t >> 4, jc = t & 15;
            uint32_t d = SMEM_SWIZZLE_128B((uint32_t)(r * 128 + (jc >> 1) * 16)) + (jc & 1) * 8;
            uint2 ho, lo;
            split4h(a4[i], ho, lo);
            *(uint2*)(smem + d) = ho;
            *(uint2*)(smem + 8192u + d) = lo;
        }
        cp_wait0();
        __syncthreads();
    }

    const int nk = KDIM / 64;   // 4
    for (int kc = 0; kc < nk; kc++) {
        const uint32_t curoff = (uint32_t)(kc & 1) * 32768u;
        const uint32_t nxtoff = curoff ^ 32768u;
        const bool hn = (kc + 1) < nk;

        float4 aPre[4];
        if (hn) {
#pragma unroll
            for (int i = 0; i < 4; i++) {
                int t = i * 256 + tid;
                int r = t >> 3, j = t & 7;
                uint32_t d = SMEM_SWIZZLE_128B((uint32_t)(r * 128 + j * 16));
                size_t src = (size_t)(bcol + r) * KDIM + (kc + 1) * 64 + j * 8;
                cp16(sbase + nxtoff + 16384u + d, B + src);
            }
            cp_commit();
#pragma unroll
            for (int i = 0; i < 4; i++) {
                int t = i * 256 + tid;
                int r = t >> 4, jc = t & 15;
                aPre[i] = (brow + r < M)
                    ? __ldg((const float4*)(A + (size_t)(brow + r) * KDIM + (kc + 1) * 64 + jc * 4))
                    : make_float4(0.f, 0.f, 0.f, 0.f);
            }
        }

        // ---- compute on stage cur ----
        const uint32_t sa_hi = sbase + curoff;
        const uint32_t sa_lo = sa_hi + 8192u;
        const uint32_t sb    = sa_hi + 16384u;
#pragma unroll
        for (int kk = 0; kk < 4; kk++) {
            const uint32_t kbA = (uint32_t)(kk * 32 + a_kx);
            const uint32_t kbB = (uint32_t)(kk * 32 + b_kx);

            uint32_t ahi[2][4], bf[4][2];
#pragma unroll
            for (int mi = 0; mi < 2; mi++)
                ldm_x4(ahi[mi], sa_hi + SMEM_SWIZZLE_128B((uint32_t)((a_r + mi * 16) * 128) + kbA));
#pragma unroll
            for (int nj = 0; nj < 2; nj++) {
                uint32_t rr[4];
                ldm_x4(rr, sb + SMEM_SWIZZLE_128B((uint32_t)((b_r0 + nj * 16) * 128) + kbB));
                bf[nj * 2][0] = rr[0]; bf[nj * 2][1] = rr[1];
                bf[nj * 2 + 1][0] = rr[2]; bf[nj * 2 + 1][1] = rr[3];
            }
#pragma unroll
            for (int mi = 0; mi < 2; mi++)
#pragma unroll
                for (int ni = 0; ni < 4; ni++)
                    mma16816h(acc[mi][ni], ahi[mi], bf[ni]);

            uint32_t alo[2][4];
#pragma unroll
            for (int mi = 0; mi < 2; mi++)
                ldm_x4(alo[mi], sa_lo + SMEM_SWIZZLE_128B((uint32_t)((a_r + mi * 16) * 128) + kbA));
#pragma unroll
            for (int mi = 0; mi < 2; mi++)
#pragma unroll
                for (int ni = 0; ni < 4; ni++)
                    mma16816h(acc[mi][ni], alo[mi], bf[ni]);
        }

        if (hn) {
#pragma unroll
            for (int i = 0; i < 4; i++) {
                int t = i * 256 + tid;
                int r = t >> 4, jc = t & 15;
                uint32_t d = SMEM_SWIZZLE_128B((uint32_t)(r * 128 + (jc >> 1) * 16)) + (jc & 1) * 8;
                uint2 ho, lo;
                split4h(aPre[i], ho, lo);
                *(uint2*)(smem + nxtoff + d) = ho;
                *(uint2*)(smem + nxtoff + 8192u + d) = lo;
            }
            cp_wait0();
            __syncthreads();
        }
    }

    // ---- epilogue: bias + stores (f32 float2 or fp16 half2) ----
    const int row0 = brow + wr + (lane >> 2);
#pragma unroll
    for (int ni = 0; ni < 4; ni++) {
        int col = bcol + wc + ni * 8 + (lane & 3) * 2;
        float2 bb = *(const float2*)&bias[col];
#pragma unroll
        for (int mi = 0; mi < 2; mi++) {
            int r0 = row0 + mi * 16;
            int r1 = r0 + 8;
            float ox0 = acc[mi][ni][0] + bb.x, oy0 = acc[mi][ni][1] + bb.y;
            float ox1 = acc[mi][ni][2] + bb.x, oy1 = acc[mi][ni][3] + bb.y;
            if (oh) {
                if (r0 < M)
                    *(__half2*)((__half*)C + (size_t)r0 * N + col) = __floats2half2_rn(ox0, oy0);
                if (r1 < M)
                    *(__half2*)((__half*)C + (size_t)r1 * N + col) = __floats2half2_rn(ox1, oy1);
            } else {
                if (r0 < M) {
                    float2 o; o.x = ox0; o.y = oy0;
                    *(float2*)((float*)C + (size_t)r0 * N + col) = o;
                }
                if (r1 < M) {
                    float2 o; o.x = ox1; o.y = oy1;
                    *(float2*)((float*)C + (size_t)r1 * N + col) = o;
                }
            }
        }
    }
}

// ---------------------------------------------------------------------------
// Fused softmax + bilinear sampling. Values gathered as fp16 (uint2 = 8B/lane
// = 64B per 8-lane head group -> half the L1 sector traffic of f32).
// ---------------------------------------------------------------------------
__global__ __launch_bounds__(256)
void msda_sample_kernel(const float* __restrict__ ref)
{
    int warp_global = blockIdx.x * (blockDim.x >> 5) + (threadIdx.x >> 5);
    if (warp_global >= Bb * LQ * 2) return;
    int lane = threadIdx.x & 31;
    int g = lane >> 3;
    int r = lane & 7;

    int hpair = warp_global & 1;
    int bq    = warp_global >> 1;
    int b     = bq / LQ;
    int hh    = hpair * 4 + g;

    const float2* awp = (const float2*)(g_offaw + (size_t)bq * 384 + 256 + hh * 16);
    float2 lg = awp[r];
    float m = fmaxf(lg.x, lg.y);
#pragma unroll
    for (int o = 4; o > 0; o >>= 1) m = fmaxf(m, __shfl_xor_sync(0xffffffffu, m, o));
    float e0 = __expf(lg.x - m);
    float e1 = __expf(lg.y - m);
    float s = e0 + e1;
#pragma unroll
    for (int o = 4; o > 0; o >>= 1) s += __shfl_xor_sync(0xffffffffu, s, o);
    float inv = 1.f / s;
    float w0 = e0 * inv;
    float w1 = e1 * inv;

    const float4* offp = (const float4*)(g_offaw + (size_t)bq * 384 + hh * 32);
    float4 off4 = offp[r];

    int l  = r >> 1;
    int HW = 80 >> l;
    int start = (l > 0 ? 6400 : 0) + (l > 1 ? 1600 : 0) + (l > 2 ? 400 : 0);
    float fHW = (float)HW;
    float2 rxy = __ldg((const float2*)ref + (size_t)bq * 4 + l);

    float cA[4], cB[4];
    uint32_t pkA0, pkA1, pkB0, pkB1;
#pragma unroll
    for (int pt = 0; pt < 2; pt++) {
        float ox = pt ? off4.z : off4.x;
        float oy = pt ? off4.w : off4.y;
        float aw = pt ? w1 : w0;

        float x = fmaf(rxy.x, fHW, ox - 0.5f);
        float y = fmaf(rxy.y, fHW, oy - 0.5f);
        float x0f = floorf(x), y0f = floorf(y);
        float wx = x - x0f, wy = y - y0f;
        int x0 = (int)x0f, y0 = (int)y0f;
        int x1 = x0 + 1,   y1 = y0 + 1;

        float vx0 = (x0 >= 0 && x0 < HW) ? 1.f : 0.f;
        float vx1 = (x1 >= 0 && x1 < HW) ? 1.f : 0.f;
        float vy0 = (y0 >= 0 && y0 < HW) ? 1.f : 0.f;
        float vy1 = (y1 >= 0 && y1 < HW) ? 1.f : 0.f;

        int cx0 = min(max(x0, 0), HW - 1);
        int cx1 = min(max(x1, 0), HW - 1);
        int cy0 = min(max(y0, 0), HW - 1);
        int cy1 = min(max(y1, 0), HW - 1);

        uint32_t p00 = (uint32_t)(start + cy0 * HW + cx0);
        uint32_t p01 = (uint32_t)(start + cy0 * HW + cx1);
        uint32_t p10 = (uint32_t)(start + cy1 * HW + cx0);
        uint32_t p11 = (uint32_t)(start + cy1 * HW + cx1);

        float wx1 = 1.f - wx, wy1 = 1.f - wy;
        float c0 = aw * wx1 * wy1 * vx0 * vy0;
        float c1 = aw * wx  * wy1 * vx1 * vy0;
        float c2 = aw * wx1 * wy  * vx0 * vy1;
        float c3 = aw * wx  * wy  * vx1 * vy1;

        if (pt == 0) {
            cA[0] = c0; cA[1] = c1; cA[2] = c2; cA[3] = c3;
            pkA0 = p00 | (p01 << 16); pkA1 = p10 | (p11 << 16);
        } else {
            cB[0] = c0; cB[1] = c1; cB[2] = c2; cB[3] = c3;
            pkB0 = p00 | (p01 << 16); pkB1 = p10 | (p11 << 16);
        }
    }

    const __half* pbase = g_vh + (size_t)b * LVTOT * Ee + hh * HEAD_DIM + r * 4;
    float4 acc = make_float4(0.f, 0.f, 0.f, 0.f);

#pragma unroll
    for (int j = 0; j < 8; j++) {
        int src = (g << 3) + j;
#pragma unroll
        for (int pt = 0; pt < 2; pt++) {
            float c0 = __shfl_sync(0xffffffffu, pt ? cB[0] : cA[0], src);
            float c1 = __shfl_sync(0xffffffffu, pt ? cB[1] : cA[1], src);
            float c2 = __shfl_sync(0xffffffffu, pt ? cB[2] : cA[2], src);
            float c3 = __shfl_sync(0xffffffffu, pt ? cB[3] : cA[3], src);
            uint32_t q0 = __shfl_sync(0xffffffffu, pt ? pkB0 : pkA0, src);
            uint32_t q1 = __shfl_sync(0xffffffffu, pt ? pkB1 : pkA1, src);

            uint32_t i00 = q0 & 0xffffu, i01 = q0 >> 16;
            uint32_t i10 = q1 & 0xffffu, i11 = q1 >> 16;

            uint2 r00 = __ldg((const uint2*)(pbase + (size_t)i00 * Ee));
            uint2 r01 = __ldg((const uint2*)(pbase + (size_t)i01 * Ee));
            uint2 r10 = __ldg((const uint2*)(pbase + (size_t)i10 * Ee));
            uint2 r11 = __ldg((const uint2*)(pbase + (size_t)i11 * Ee));

            float2 a00 = __half22float2(*(__half2*)&r00.x);
            float2 b00 = __half22float2(*(__half2*)&r00.y);
            float2 a01 = __half22float2(*(__half2*)&r01.x);
            float2 b01 = __half22float2(*(__half2*)&r01.y);
            float2 a10 = __half22float2(*(__half2*)&r10.x);
            float2 b10 = __half22float2(*(__half2*)&r10.y);
            float2 a11 = __half22float2(*(__half2*)&r11.x);
            float2 b11 = __half22float2(*(__half2*)&r11.y);

            acc.x = fmaf(c0, a00.x, fmaf(c1, a01.x, fmaf(c2, a10.x, fmaf(c3, a11.x, acc.x))));
            acc.y = fmaf(c0, a00.y, fmaf(c1, a01.y, fmaf(c2, a10.y, fmaf(c3, a11.y, acc.y))));
            acc.z = fmaf(c0, b00.x, fmaf(c1, b01.x, fmaf(c2, b10.x, fmaf(c3, b11.x, acc.z))));
            acc.w = fmaf(c0, b00.y, fmaf(c1, b01.y, fmaf(c2, b10.y, fmaf(c3, b11.y, acc.w))));
        }
    }

    *(float4*)(g_tmp + (size_t)bq * Ee + hh * HEAD_DIM + r * 4) = acc;
}

// ---------------------------------------------------------------------------
extern "C" void kernel_launch(void* const* d_in, const int* in_sizes, int n_in,
                              void* d_out, int out_size)
{
    const float* query = (const float*)d_in[0];
    const float* ref   = (const float*)d_in[1];
    const float* value = (const float*)d_in[2];
    const float* Wv    = (const float*)d_in[4];
    const float* bv    = (const float*)d_in[5];
    const float* Woff  = (const float*)d_in[6];
    const float* boff  = (const float*)d_in[7];
    const float* Wattn = (const float*)d_in[8];
    const float* battn = (const float*)d_in[9];
    const float* Wo    = (const float*)d_in[10];
    const float* bo    = (const float*)d_in[11];
    float* out = (float*)d_out;

    float *poffaw, *ptmp, *pbc;
    __half *pwt, *pvh;
    cudaGetSymbolAddress((void**)&pvh,    g_vh);
    cudaGetSymbolAddress((void**)&poffaw, g_offaw);
    cudaGetSymbolAddress((void**)&ptmp,   g_tmp);
    cudaGetSymbolAddress((void**)&pbc,    g_bias_comb);
    cudaGetSymbolAddress((void**)&pwt,    g_wt);

    cudaFuncSetAttribute(gemm_dual_fp16x2,
                         cudaFuncAttributeMaxDynamicSharedMemorySize, 65536);

    // ---- prep (single launch) ----
    prep_weights_kernel<<<(WT_TOTAL + 255) / 256, 256>>>(Wv, Woff, Wattn, Wo, boff, battn);

    // ---- GEMM 1+2 merged: g_vh(fp16) = value@Wv+bv  AND  g_offaw(f32) = query@[Woff|Wattn]+bias ----
    {
        const int rows1 = (MV + 63) / 64;          // 532
        const int nblk1 = rows1 * 2;               // 1064  (N=256 -> nc1=2)
        const int rows2 = (MQ + 63) / 64;          // 525
        const int nblk2 = rows2 * 3;               // 1575  (N=384 -> nc2=3)
        gemm_dual_fp16x2<<<nblk1 + nblk2, 256, 65536>>>(
            value, pwt + WT_WV,   bv,  pvh,    MV, 256, 2, 1, nblk1,
            query, pwt + WT_COMB, pbc, poffaw, MQ, 384, 3, 0);
    }
    // ---- sampler ----
    {
        int total_warps = Bb * LQ * 2;
        int blocks = (total_warps + 7) / 8;
        msda_sample_kernel<<<blocks, 256>>>(ref);
    }
    // ---- GEMM 3: out = g_tmp @ Wo + bo ----
    {
        const int rows3 = (MQ + 63) / 64;          // 525
        const int nblk3 = rows3 * 2;               // 1050
        gemm_dual_fp16x2<<<nblk3, 256, 65536>>>(
            ptmp, pwt + WT_WO, bo, out, MQ, 256, 2, 0, nblk3,
            ptmp, pwt + WT_WO, bo, out, MQ, 256, 2, 0);
    }
}

// round 14
// speedup vs baseline: 1.4379x; 1.0746x over previous
#include <cuda_runtime.h>
#include <cuda_fp16.h>
#include <math.h>
#include <stdint.h>

#define Bb 4
#define LQ 8400
#define Ee 256
#define HEADS 8
#define LEVELS 4
#define POINTS 4
#define HEAD_DIM 32
#define LVTOT 8500
#define KDIM 256

#define MQ (Bb * LQ)     // 33600
#define MV (Bb * LVTOT)  // 34000

// ---------------- scratch (device globals; no allocation allowed) ----------
__device__ __half g_vh[MV * Ee];          // value @ Wv + bv (fp16, sampler input)
__device__ float g_offaw[MQ * 384];       // [off(256) | aw(128)] fused GEMM output
__device__ __half g_th[MQ * Ee];          // sampler output (fp16, GEMM3 A)
__device__ float g_bias_comb[384];

// transposed weights [N][K] fp16
#define WT_WV    0
#define WT_COMB  65536
#define WT_WO    163840
#define WT_TOTAL 229376
__device__ __half g_wt[WT_TOTAL];

// ---------------- helpers ----------------------------------------------
#define SMEM_SWIZZLE_128B(byte_offset) \
    ((byte_offset) ^ (((byte_offset) >> 3) & 0x70))

__device__ __forceinline__ uint32_t smem_u32(const void* p) {
    uint32_t a;
    asm("{ .reg .u64 t; cvta.to.shared.u64 t, %1; cvt.u32.u64 %0, t; }"
        : "=r"(a) : "l"(p));
    return a;
}

__device__ __forceinline__ void cp16(uint32_t dst, const void* src) {
    asm volatile("cp.async.cg.shared.global [%0], [%1], 16;"
                 :: "r"(dst), "l"(src));
}

__device__ __forceinline__ void cp_commit() {
    asm volatile("cp.async.commit_group;" ::: "memory");
}
__device__ __forceinline__ void cp_wait0() {
    asm volatile("cp.async.wait_group 0;" ::: "memory");
}

__device__ __forceinline__ void ldm_x4(uint32_t* r, uint32_t addr) {
    asm volatile("ldmatrix.sync.aligned.m8n8.x4.shared.b16 {%0,%1,%2,%3}, [%4];"
                 : "=r"(r[0]), "=r"(r[1]), "=r"(r[2]), "=r"(r[3]) : "r"(addr));
}

__device__ __forceinline__ void mma16816h(float* c, const uint32_t* a, const uint32_t* b) {
    asm volatile("mma.sync.aligned.m16n8k16.row.col.f32.f16.f16.f32 "
                 "{%0,%1,%2,%3}, {%4,%5,%6,%7}, {%8,%9}, {%0,%1,%2,%3};"
                 : "+f"(c[0]), "+f"(c[1]), "+f"(c[2]), "+f"(c[3])
                 : "r"(a[0]), "r"(a[1]), "r"(a[2]), "r"(a[3]),
                   "r"(b[0]), "r"(b[1]));
}

// float4 -> fp16 hi (uint2 = 4 halves) and fp16 lo residual (uint2)
__device__ __forceinline__ void split4h(float4 v, uint2& ho, uint2& lo) {
    __half h0 = __float2half_rn(v.x);
    __half h1 = __float2half_rn(v.y);
    __half h2 = __float2half_rn(v.z);
    __half h3 = __float2half_rn(v.w);
    __half l0 = __float2half_rn(v.x - __half2float(h0));
    __half l1 = __float2half_rn(v.y - __half2float(h1));
    __half l2 = __float2half_rn(v.z - __half2float(h2));
    __half l3 = __float2half_rn(v.w - __half2float(h3));
    __half2 hp0 = __halves2half2(h0, h1);
    __half2 hp1 = __halves2half2(h2, h3);
    __half2 lp0 = __halves2half2(l0, l1);
    __half2 lp1 = __halves2half2(l2, l3);
    ho.x = *(uint32_t*)&hp0; ho.y = *(uint32_t*)&hp1;
    lo.x = *(uint32_t*)&lp0; lo.y = *(uint32_t*)&lp1;
}

// ---------------------------------------------------------------------------
// ONE prep kernel: all 4 weight transposes (fp16) + bias concat.
// ---------------------------------------------------------------------------
__global__ void prep_weights_kernel(const float* __restrict__ Wv,
                                    const float* __restrict__ Woff,
                                    const float* __restrict__ Wattn,
                                    const float* __restrict__ Wo,
                                    const float* __restrict__ boff,
                                    const float* __restrict__ battn)
{
    int idx = blockIdx.x * blockDim.x + threadIdx.x;
    if (idx < 384)
        g_bias_comb[idx] = (idx < 256) ? boff[idx] : battn[idx - 256];
    if (idx >= WT_TOTAL) return;

    const float* W;
    int Nd, out, t = idx;
    if (t < 65536)        { W = Wv;    Nd = 256; out = WT_WV; }
    else if (t < 131072)  { W = Woff;  Nd = 256; out = WT_COMB;          t -= 65536; }
    else if (t < 163840)  { W = Wattn; Nd = 128; out = WT_COMB + 65536;  t -= 131072; }
    else                  { W = Wo;    Nd = 256; out = WT_WO;            t -= 163840; }

    int k = t / Nd, n = t % Nd;
    g_wt[out + n * 256 + k] = __float2half_rn(W[k * Nd + n]);
}

// ---------------------------------------------------------------------------
// mma.sync fp16x2 GEMM (f32 A split in-kernel; 2 passes). CTA 64x128, 256 thr.
// Two-stage pipeline, 64KB smem, 3 CTAs/SM. Used for GEMM1+2.
// ---------------------------------------------------------------------------
__global__ __launch_bounds__(256, 3)
void gemm_dual_fp16x2(const float* __restrict__ A1,
                      const __half* __restrict__ B1,
                      const float* __restrict__ bias1,
                      void* __restrict__ C1, int M1, int N1, int nc1, int oh1, int nblk1,
                      const float* __restrict__ A2,
                      const __half* __restrict__ B2,
                      const float* __restrict__ bias2,
                      void* __restrict__ C2, int M2, int N2, int nc2, int oh2)
{
    extern __shared__ char smem[];
    const uint32_t sbase = smem_u32(smem);
    // per-stage layout: A_hi +0 | A_lo +8K | B +16K ; stage stride 32K

    const float* A; const __half* B; const float* bias; void* C;
    int M, N, brow, bcol, oh;
    {
        int bid = blockIdx.x;
        if (bid < nblk1) {
            A = A1; B = B1; bias = bias1; C = C1; M = M1; N = N1; oh = oh1;
            brow = (bid / nc1) * 64; bcol = (bid % nc1) * 128;
        } else {
            bid -= nblk1;
            A = A2; B = B2; bias = bias2; C = C2; M = M2; N = N2; oh = oh2;
            brow = (bid / nc2) * 64; bcol = (bid % nc2) * 128;
        }
    }

    const int tid = threadIdx.x, lane = tid & 31, wid = tid >> 5;
    const int wr = (wid >> 2) * 32;
    const int wc = (wid & 3) * 32;

    float acc[2][4][4];
#pragma unroll
    for (int i = 0; i < 2; i++)
#pragma unroll
        for (int j = 0; j < 4; j++)
#pragma unroll
            for (int k = 0; k < 4; k++) acc[i][j][k] = 0.f;

    const int a_r  = wr + (lane & 15);
    const int a_kx = (lane >> 4) << 4;
    const int b_r0 = wc + (lane & 7) + ((lane >> 4) << 3);
    const int b_kx = ((lane >> 3) & 1) << 4;

    // ---- prologue: load chunk 0 into stage 0 ----
    {
#pragma unroll
        for (int i = 0; i < 4; i++) {
            int t = i * 256 + tid;
            int r = t >> 3, j = t & 7;
            uint32_t d = SMEM_SWIZZLE_128B((uint32_t)(r * 128 + j * 16));
            size_t src = (size_t)(bcol + r) * KDIM + j * 8;
            cp16(sbase + 16384u + d, B + src);
        }
        cp_commit();
        float4 a4[4];
#pragma unroll
        for (int i = 0; i < 4; i++) {
            int t = i * 256 + tid;
            int r = t >> 4, jc = t & 15;
            a4[i] = (brow + r < M)
                ? __ldg((const float4*)(A + (size_t)(brow + r) * KDIM + jc * 4))
                : make_float4(0.f, 0.f, 0.f, 0.f);
        }
#pragma unroll
        for (int i = 0; i < 4; i++) {
            int t = i * 256 + tid;
            int r = t >> 4, jc = t & 15;
            uint32_t d = SMEM_SWIZZLE_128B((uint32_t)(r * 128 + (jc >> 1) * 16)) + (jc & 1) * 8;
            uint2 ho, lo;
            split4h(a4[i], ho, lo);
            *(uint2*)(smem + d) = ho;
            *(uint2*)(smem + 8192u + d) = lo;
        }
        cp_wait0();
        __syncthreads();
    }

    const int nk = KDIM / 64;
    for (int kc = 0; kc < nk; kc++) {
        const uint32_t curoff = (uint32_t)(kc & 1) * 32768u;
        const uint32_t nxtoff = curoff ^ 32768u;
        const bool hn = (kc + 1) < nk;

        float4 aPre[4];
        if (hn) {
#pragma unroll
            for (int i = 0; i < 4; i++) {
                int t = i * 256 + tid;
                int r = t >> 3, j = t & 7;
                uint32_t d = SMEM_SWIZZLE_128B((uint32_t)(r * 128 + j * 16));
                size_t src = (size_t)(bcol + r) * KDIM + (kc + 1) * 64 + j * 8;
                cp16(sbase + nxtoff + 16384u + d, B + src);
            }
            cp_commit();
#pragma unroll
            for (int i = 0; i < 4; i++) {
                int t = i * 256 + tid;
                int r = t >> 4, jc = t & 15;
                aPre[i] = (brow + r < M)
                    ? __ldg((const float4*)(A + (size_t)(brow + r) * KDIM + (kc + 1) * 64 + jc * 4))
                    : make_float4(0.f, 0.f, 0.f, 0.f);
            }
        }

        const uint32_t sa_hi = sbase + curoff;
        const uint32_t sa_lo = sa_hi + 8192u;
        const uint32_t sb    = sa_hi + 16384u;
#pragma unroll
        for (int kk = 0; kk < 4; kk++) {
            const uint32_t kbA = (uint32_t)(kk * 32 + a_kx);
            const uint32_t kbB = (uint32_t)(kk * 32 + b_kx);

            uint32_t ahi[2][4], bf[4][2];
#pragma unroll
            for (int mi = 0; mi < 2; mi++)
                ldm_x4(ahi[mi], sa_hi + SMEM_SWIZZLE_128B((uint32_t)((a_r + mi * 16) * 128) + kbA));
#pragma unroll
            for (int nj = 0; nj < 2; nj++) {
                uint32_t rr[4];
                ldm_x4(rr, sb + SMEM_SWIZZLE_128B((uint32_t)((b_r0 + nj * 16) * 128) + kbB));
                bf[nj * 2][0] = rr[0]; bf[nj * 2][1] = rr[1];
                bf[nj * 2 + 1][0] = rr[2]; bf[nj * 2 + 1][1] = rr[3];
            }
#pragma unroll
            for (int mi = 0; mi < 2; mi++)
#pragma unroll
                for (int ni = 0; ni < 4; ni++)
                    mma16816h(acc[mi][ni], ahi[mi], bf[ni]);

            uint32_t alo[2][4];
#pragma unroll
            for (int mi = 0; mi < 2; mi++)
                ldm_x4(alo[mi], sa_lo + SMEM_SWIZZLE_128B((uint32_t)((a_r + mi * 16) * 128) + kbA));
#pragma unroll
            for (int mi = 0; mi < 2; mi++)
#pragma unroll
                for (int ni = 0; ni < 4; ni++)
                    mma16816h(acc[mi][ni], alo[mi], bf[ni]);
        }

        if (hn) {
#pragma unroll
            for (int i = 0; i < 4; i++) {
                int t = i * 256 + tid;
                int r = t >> 4, jc = t & 15;
                uint32_t d = SMEM_SWIZZLE_128B((uint32_t)(r * 128 + (jc >> 1) * 16)) + (jc & 1) * 8;
                uint2 ho, lo;
                split4h(aPre[i], ho, lo);
                *(uint2*)(smem + nxtoff + d) = ho;
                *(uint2*)(smem + nxtoff + 8192u + d) = lo;
            }
            cp_wait0();
            __syncthreads();
        }
    }

    // ---- epilogue ----
    const int row0 = brow + wr + (lane >> 2);
#pragma unroll
    for (int ni = 0; ni < 4; ni++) {
        int col = bcol + wc + ni * 8 + (lane & 3) * 2;
        float2 bb = *(const float2*)&bias[col];
#pragma unroll
        for (int mi = 0; mi < 2; mi++) {
            int r0 = row0 + mi * 16;
            int r1 = r0 + 8;
            float ox0 = acc[mi][ni][0] + bb.x, oy0 = acc[mi][ni][1] + bb.y;
            float ox1 = acc[mi][ni][2] + bb.x, oy1 = acc[mi][ni][3] + bb.y;
            if (oh) {
                if (r0 < M)
                    *(__half2*)((__half*)C + (size_t)r0 * N + col) = __floats2half2_rn(ox0, oy0);
                if (r1 < M)
                    *(__half2*)((__half*)C + (size_t)r1 * N + col) = __floats2half2_rn(ox1, oy1);
            } else {
                if (r0 < M) {
                    float2 o; o.x = ox0; o.y = oy0;
                    *(float2*)((float*)C + (size_t)r0 * N + col) = o;
                }
                if (r1 < M) {
                    float2 o; o.x = ox1; o.y = oy1;
                    *(float2*)((float*)C + (size_t)r1 * N + col) = o;
                }
            }
        }
    }
}

// ---------------------------------------------------------------------------
// Pure fp16 GEMM (A fp16 exact, single pass). CTA 64x128, 256 thr, 8 warps.
// Stage: A 8K | B 16K = 24K; 2 stages = 48K -> 4 CTAs/SM. Used for GEMM3.
// ---------------------------------------------------------------------------
__global__ __launch_bounds__(256, 4)
void gemm_a16_fp16(const __half* __restrict__ A,   // [M][K] fp16
                   const __half* __restrict__ B,   // [N][K] fp16
                   const float* __restrict__ bias,
                   float* __restrict__ C,
                   int M, int N, int nc)
{
    extern __shared__ char smem[];
    const uint32_t sbase = smem_u32(smem);
    // per-stage: A +0 (8K) | B +8K (16K); stage stride 24K

    const int bid = blockIdx.x;
    const int brow = (bid / nc) * 64, bcol = (bid % nc) * 128;

    const int tid = threadIdx.x, lane = tid & 31, wid = tid >> 5;
    const int wr = (wid >> 2) * 32;
    const int wc = (wid & 3) * 32;

    float acc[2][4][4];
#pragma unroll
    for (int i = 0; i < 2; i++)
#pragma unroll
        for (int j = 0; j < 4; j++)
#pragma unroll
            for (int k = 0; k < 4; k++) acc[i][j][k] = 0.f;

    const int a_r  = wr + (lane & 15);
    const int a_kx = (lane >> 4) << 4;
    const int b_r0 = wc + (lane & 7) + ((lane >> 4) << 3);
    const int b_kx = ((lane >> 3) & 1) << 4;

    // ---- prologue: chunk 0 -> stage 0 (all cp.async) ----
    {
#pragma unroll
        for (int i = 0; i < 2; i++) {           // A: 64 rows x 8 x 16B = 512 cp
            int t = i * 256 + tid;
            int r = t >> 3, j = t & 7;
            uint32_t d = SMEM_SWIZZLE_128B((uint32_t)(r * 128 + j * 16));
            cp16(sbase + d, A + (size_t)(brow + r) * KDIM + j * 8);
        }
#pragma unroll
        for (int i = 0; i < 4; i++) {           // B: 128 rows x 8 x 16B
            int t = i * 256 + tid;
            int r = t >> 3, j = t & 7;
            uint32_t d = SMEM_SWIZZLE_128B((uint32_t)(r * 128 + j * 16));
            cp16(sbase + 8192u + d, B + (size_t)(bcol + r) * KDIM + j * 8);
        }
        cp_commit();
        cp_wait0();
        __syncthreads();
    }

    const int nk = KDIM / 64;
    for (int kc = 0; kc < nk; kc++) {
        const uint32_t curoff = (uint32_t)(kc & 1) * 24576u;
        const uint32_t nxtoff = curoff ^ 24576u;
        const bool hn = (kc + 1) < nk;

        if (hn) {
#pragma unroll
            for (int i = 0; i < 2; i++) {
                int t = i * 256 + tid;
                int r = t >> 3, j = t & 7;
                uint32_t d = SMEM_SWIZZLE_128B((uint32_t)(r * 128 + j * 16));
                cp16(sbase + nxtoff + d, A + (size_t)(brow + r) * KDIM + (kc + 1) * 64 + j * 8);
            }
#pragma unroll
            for (int i = 0; i < 4; i++) {
                int t = i * 256 + tid;
                int r = t >> 3, j = t & 7;
                uint32_t d = SMEM_SWIZZLE_128B((uint32_t)(r * 128 + j * 16));
                cp16(sbase + nxtoff + 8192u + d, B + (size_t)(bcol + r) * KDIM + (kc + 1) * 64 + j * 8);
            }
            cp_commit();
        }

        const uint32_t sa = sbase + curoff;
        const uint32_t sb = sa + 8192u;
#pragma unroll
        for (int kk = 0; kk < 4; kk++) {
            const uint32_t kbA = (uint32_t)(kk * 32 + a_kx);
            const uint32_t kbB = (uint32_t)(kk * 32 + b_kx);

            uint32_t af[2][4], bf[4][2];
#pragma unroll
            for (int mi = 0; mi < 2; mi++)
                ldm_x4(af[mi], sa + SMEM_SWIZZLE_128B((uint32_t)((a_r + mi * 16) * 128) + kbA));
#pragma unroll
            for (int nj = 0; nj < 2; nj++) {
                uint32_t rr[4];
                ldm_x4(rr, sb + SMEM_SWIZZLE_128B((uint32_t)((b_r0 + nj * 16) * 128) + kbB));
                bf[nj * 2][0] = rr[0]; bf[nj * 2][1] = rr[1];
                bf[nj * 2 + 1][0] = rr[2]; bf[nj * 2 + 1][1] = rr[3];
            }
#pragma unroll
            for (int mi = 0; mi < 2; mi++)
#pragma unroll
                for (int ni = 0; ni < 4; ni++)
                    mma16816h(acc[mi][ni], af[mi], bf[ni]);
        }

        if (hn) {
            cp_wait0();
            __syncthreads();
        }
    }

    // ---- epilogue: bias + float2 stores ----
    const int row0 = brow + wr + (lane >> 2);
#pragma unroll
    for (int ni = 0; ni < 4; ni++) {
        int col = bcol + wc + ni * 8 + (lane & 3) * 2;
        float2 bb = *(const float2*)&bias[col];
#pragma unroll
        for (int mi = 0; mi < 2; mi++) {
            int r0 = row0 + mi * 16;
            if (r0 < M) {
                float2 o;
                o.x = acc[mi][ni][0] + bb.x;
                o.y = acc[mi][ni][1] + bb.y;
                *(float2*)(C + (size_t)r0 * N + col) = o;
            }
            int r1 = r0 + 8;
            if (r1 < M) {
                float2 o;
                o.x = acc[mi][ni][2] + bb.x;
                o.y = acc[mi][ni][3] + bb.y;
                *(float2*)(C + (size_t)r1 * N + col) = o;
            }
        }
    }
}

// ---------------------------------------------------------------------------
// Fused softmax + bilinear sampling. fp16 gathers; emits fp16 (GEMM3 A).
// ---------------------------------------------------------------------------
__global__ __launch_bounds__(256)
void msda_sample_kernel(const float* __restrict__ ref)
{
    int warp_global = blockIdx.x * (blockDim.x >> 5) + (threadIdx.x >> 5);
    if (warp_global >= Bb * LQ * 2) return;
    int lane = threadIdx.x & 31;
    int g = lane >> 3;
    int r = lane & 7;

    int hpair = warp_global & 1;
    int bq    = warp_global >> 1;
    int b     = bq / LQ;
    int hh    = hpair * 4 + g;

    const float2* awp = (const float2*)(g_offaw + (size_t)bq * 384 + 256 + hh * 16);
    float2 lg = awp[r];
    float m = fmaxf(lg.x, lg.y);
#pragma unroll
    for (int o = 4; o > 0; o >>= 1) m = fmaxf(m, __shfl_xor_sync(0xffffffffu, m, o));
    float e0 = __expf(lg.x - m);
    float e1 = __expf(lg.y - m);
    float s = e0 + e1;
#pragma unroll
    for (int o = 4; o > 0; o >>= 1) s += __shfl_xor_sync(0xffffffffu, s, o);
    float inv = 1.f / s;
    float w0 = e0 * inv;
    float w1 = e1 * inv;

    const float4* offp = (const float4*)(g_offaw + (size_t)bq * 384 + hh * 32);
    float4 off4 = offp[r];

    int l  = r >> 1;
    int HW = 80 >> l;
    int start = (l > 0 ? 6400 : 0) + (l > 1 ? 1600 : 0) + (l > 2 ? 400 : 0);
    float fHW = (float)HW;
    float2 rxy = __ldg((const float2*)ref + (size_t)bq * 4 + l);

    float cA[4], cB[4];
    uint32_t pkA0, pkA1, pkB0, pkB1;
#pragma unroll
    for (int pt = 0; pt < 2; pt++) {
        float ox = pt ? off4.z : off4.x;
        float oy = pt ? off4.w : off4.y;
        float aw = pt ? w1 : w0;

        float x = fmaf(rxy.x, fHW, ox - 0.5f);
        float y = fmaf(rxy.y, fHW, oy - 0.5f);
        float x0f = floorf(x), y0f = floorf(y);
        float wx = x - x0f, wy = y - y0f;
        int x0 = (int)x0f, y0 = (int)y0f;
        int x1 = x0 + 1,   y1 = y0 + 1;

        float vx0 = (x0 >= 0 && x0 < HW) ? 1.f : 0.f;
        float vx1 = (x1 >= 0 && x1 < HW) ? 1.f : 0.f;
        float vy0 = (y0 >= 0 && y0 < HW) ? 1.f : 0.f;
        float vy1 = (y1 >= 0 && y1 < HW) ? 1.f : 0.f;

        int cx0 = min(max(x0, 0), HW - 1);
        int cx1 = min(max(x1, 0), HW - 1);
        int cy0 = min(max(y0, 0), HW - 1);
        int cy1 = min(max(y1, 0), HW - 1);

        uint32_t p00 = (uint32_t)(start + cy0 * HW + cx0);
        uint32_t p01 = (uint32_t)(start + cy0 * HW + cx1);
        uint32_t p10 = (uint32_t)(start + cy1 * HW + cx0);
        uint32_t p11 = (uint32_t)(start + cy1 * HW + cx1);

        float wx1 = 1.f - wx, wy1 = 1.f - wy;
        float c0 = aw * wx1 * wy1 * vx0 * vy0;
        float c1 = aw * wx  * wy1 * vx1 * vy0;
        float c2 = aw * wx1 * wy  * vx0 * vy1;
        float c3 = aw * wx  * wy  * vx1 * vy1;

        if (pt == 0) {
            cA[0] = c0; cA[1] = c1; cA[2] = c2; cA[3] = c3;
            pkA0 = p00 | (p01 << 16); pkA1 = p10 | (p11 << 16);
        } else {
            cB[0] = c0; cB[1] = c1; cB[2] = c2; cB[3] = c3;
            pkB0 = p00 | (p01 << 16); pkB1 = p10 | (p11 << 16);
        }
    }

    const __half* pbase = g_vh + (size_t)b * LVTOT * Ee + hh * HEAD_DIM + r * 4;
    float4 acc = make_float4(0.f, 0.f, 0.f, 0.f);

#pragma unroll
    for (int j = 0; j < 8; j++) {
        int src = (g << 3) + j;
#pragma unroll
        for (int pt = 0; pt < 2; pt++) {
            float c0 = __shfl_sync(0xffffffffu, pt ? cB[0] : cA[0], src);
            float c1 = __shfl_sync(0xffffffffu, pt ? cB[1] : cA[1], src);
            float c2 = __shfl_sync(0xffffffffu, pt ? cB[2] : cA[2], src);
            float c3 = __shfl_sync(0xffffffffu, pt ? cB[3] : cA[3], src);
            uint32_t q0 = __shfl_sync(0xffffffffu, pt ? pkB0 : pkA0, src);
            uint32_t q1 = __shfl_sync(0xffffffffu, pt ? pkB1 : pkA1, src);

            uint32_t i00 = q0 & 0xffffu, i01 = q0 >> 16;
            uint32_t i10 = q1 & 0xffffu, i11 = q1 >> 16;

            uint2 r00 = __ldg((const uint2*)(pbase + (size_t)i00 * Ee));
            uint2 r01 = __ldg((const uint2*)(pbase + (size_t)i01 * Ee));
            uint2 r10 = __ldg((const uint2*)(pbase + (size_t)i10 * Ee));
            uint2 r11 = __ldg((const uint2*)(pbase + (size_t)i11 * Ee));

            float2 a00 = __half22float2(*(__half2*)&r00.x);
            float2 b00 = __half22float2(*(__half2*)&r00.y);
            float2 a01 = __half22float2(*(__half2*)&r01.x);
            float2 b01 = __half22float2(*(__half2*)&r01.y);
            float2 a10 = __half22float2(*(__half2*)&r10.x);
            float2 b10 = __half22float2(*(__half2*)&r10.y);
            float2 a11 = __half22float2(*(__half2*)&r11.x);
            float2 b11 = __half22float2(*(__half2*)&r11.y);

            acc.x = fmaf(c0, a00.x, fmaf(c1, a01.x, fmaf(c2, a10.x, fmaf(c3, a11.x, acc.x))));
            acc.y = fmaf(c0, a00.y, fmaf(c1, a01.y, fmaf(c2, a10.y, fmaf(c3, a11.y, acc.y))));
            acc.z = fmaf(c0, b00.x, fmaf(c1, b01.x, fmaf(c2, b10.x, fmaf(c3, b11.x, acc.z))));
            acc.w = fmaf(c0, b00.y, fmaf(c1, b01.y, fmaf(c2, b10.y, fmaf(c3, b11.y, acc.w))));
        }
    }

    // emit fp16 (4 halves = uint2) -> GEMM3 A
    __half2 o0 = __floats2half2_rn(acc.x, acc.y);
    __half2 o1 = __floats2half2_rn(acc.z, acc.w);
    uint2 ov;
    ov.x = *(uint32_t*)&o0;
    ov.y = *(uint32_t*)&o1;
    *(uint2*)(g_th + (size_t)bq * Ee + hh * HEAD_DIM + r * 4) = ov;
}

// ---------------------------------------------------------------------------
extern "C" void kernel_launch(void* const* d_in, const int* in_sizes, int n_in,
                              void* d_out, int out_size)
{
    const float* query = (const float*)d_in[0];
    const float* ref   = (const float*)d_in[1];
    const float* value = (const float*)d_in[2];
    const float* Wv    = (const float*)d_in[4];
    const float* bv    = (const float*)d_in[5];
    const float* Woff  = (const float*)d_in[6];
    const float* boff  = (const float*)d_in[7];
    const float* Wattn = (const float*)d_in[8];
    const float* battn = (const float*)d_in[9];
    const float* Wo    = (const float*)d_in[10];
    const float* bo    = (const float*)d_in[11];
    float* out = (float*)d_out;

    float *poffaw, *pbc;
    __half *pwt, *pvh, *pth;
    cudaGetSymbolAddress((void**)&pvh,    g_vh);
    cudaGetSymbolAddress((void**)&poffaw, g_offaw);
    cudaGetSymbolAddress((void**)&pth,    g_th);
    cudaGetSymbolAddress((void**)&pbc,    g_bias_comb);
    cudaGetSymbolAddress((void**)&pwt,    g_wt);

    cudaFuncSetAttribute(gemm_dual_fp16x2,
                         cudaFuncAttributeMaxDynamicSharedMemorySize, 65536);
    cudaFuncSetAttribute(gemm_a16_fp16,
                         cudaFuncAttributeMaxDynamicSharedMemorySize, 49152);

    // ---- prep (single launch) ----
    prep_weights_kernel<<<(WT_TOTAL + 255) / 256, 256>>>(Wv, Woff, Wattn, Wo, boff, battn);

    // ---- GEMM 1+2 merged: g_vh(fp16) = value@Wv+bv  AND  g_offaw(f32) = query@[Woff|Wattn]+bias ----
    {
        const int rows1 = (MV + 63) / 64;          // 532
        const int nblk1 = rows1 * 2;               // 1064
        const int rows2 = (MQ + 63) / 64;          // 525
        const int nblk2 = rows2 * 3;               // 1575
        gemm_dual_fp16x2<<<nblk1 + nblk2, 256, 65536>>>(
            value, pwt + WT_WV,   bv,  pvh,    MV, 256, 2, 1, nblk1,
            query, pwt + WT_COMB, pbc, poffaw, MQ, 384, 3, 0);
    }
    // ---- sampler (emits fp16) ----
    {
        int total_warps = Bb * LQ * 2;
        int blocks = (total_warps + 7) / 8;
        msda_sample_kernel<<<blocks, 256>>>(ref);
    }
    // ---- GEMM 3: out = g_th(fp16) @ Wo + bo  (single-pass fp16 GEMM) ----
    {
        const int rows3 = (MQ + 63) / 64;          // 525
        gemm_a16_fp16<<<rows3 * 2, 256, 49152>>>(
            pth, pwt + WT_WO, bo, out, MQ, 256, 2);
    }
}

// round 15
// speedup vs baseline: 1.5215x; 1.0581x over previous
#include <cuda_runtime.h>
#include <cuda_fp16.h>
#include <math.h>
#include <stdint.h>

#define Bb 4
#define LQ 8400
#define Ee 256
#define HEADS 8
#define LEVELS 4
#define POINTS 4
#define HEAD_DIM 32
#define LVTOT 8500
#define KDIM 256

#define MQ (Bb * LQ)     // 33600
#define MV (Bb * LVTOT)  // 34000

// ---------------- scratch (device globals; no allocation allowed) ----------
__device__ __half g_vh[MV * Ee];          // value @ Wv + bv (fp16)
__device__ __half g_offaw[MQ * 384];      // [off(256) | aw(128)] fp16
__device__ __half g_th[MQ * Ee];          // sampler output (fp16, GEMM3 A)
__device__ float g_bias_comb[384];

// transposed weights [N][K] fp16
#define WT_WV    0
#define WT_COMB  65536
#define WT_WO    163840
#define WT_TOTAL 229376
__device__ __half g_wt[WT_TOTAL];

// ---------------- helpers ----------------------------------------------
#define SMEM_SWIZZLE_128B(byte_offset) \
    ((byte_offset) ^ (((byte_offset) >> 3) & 0x70))

__device__ __forceinline__ uint32_t smem_u32(const void* p) {
    uint32_t a;
    asm("{ .reg .u64 t; cvta.to.shared.u64 t, %1; cvt.u32.u64 %0, t; }"
        : "=r"(a) : "l"(p));
    return a;
}

__device__ __forceinline__ void cp16(uint32_t dst, const void* src) {
    asm volatile("cp.async.cg.shared.global [%0], [%1], 16;"
                 :: "r"(dst), "l"(src));
}

__device__ __forceinline__ void cp_commit() {
    asm volatile("cp.async.commit_group;" ::: "memory");
}
__device__ __forceinline__ void cp_wait0() {
    asm volatile("cp.async.wait_group 0;" ::: "memory");
}

__device__ __forceinline__ void ldm_x4(uint32_t* r, uint32_t addr) {
    asm volatile("ldmatrix.sync.aligned.m8n8.x4.shared.b16 {%0,%1,%2,%3}, [%4];"
                 : "=r"(r[0]), "=r"(r[1]), "=r"(r[2]), "=r"(r[3]) : "r"(addr));
}

__device__ __forceinline__ void mma16816h(float* c, const uint32_t* a, const uint32_t* b) {
    asm volatile("mma.sync.aligned.m16n8k16.row.col.f32.f16.f16.f32 "
                 "{%0,%1,%2,%3}, {%4,%5,%6,%7}, {%8,%9}, {%0,%1,%2,%3};"
                 : "+f"(c[0]), "+f"(c[1]), "+f"(c[2]), "+f"(c[3])
                 : "r"(a[0]), "r"(a[1]), "r"(a[2]), "r"(a[3]),
                   "r"(b[0]), "r"(b[1]));
}

__device__ __forceinline__ void split4h(float4 v, uint2& ho, uint2& lo) {
    __half h0 = __float2half_rn(v.x);
    __half h1 = __float2half_rn(v.y);
    __half h2 = __float2half_rn(v.z);
    __half h3 = __float2half_rn(v.w);
    __half l0 = __float2half_rn(v.x - __half2float(h0));
    __half l1 = __float2half_rn(v.y - __half2float(h1));
    __half l2 = __float2half_rn(v.z - __half2float(h2));
    __half l3 = __float2half_rn(v.w - __half2float(h3));
    __half2 hp0 = __halves2half2(h0, h1);
    __half2 hp1 = __halves2half2(h2, h3);
    __half2 lp0 = __halves2half2(l0, l1);
    __half2 lp1 = __halves2half2(l2, l3);
    ho.x = *(uint32_t*)&hp0; ho.y = *(uint32_t*)&hp1;
    lo.x = *(uint32_t*)&lp0; lo.y = *(uint32_t*)&lp1;
}

// ---------------------------------------------------------------------------
// ONE prep kernel: all 4 weight transposes (fp16) + bias concat.
// ---------------------------------------------------------------------------
__global__ void prep_weights_kernel(const float* __restrict__ Wv,
                                    const float* __restrict__ Woff,
                                    const float* __restrict__ Wattn,
                                    const float* __restrict__ Wo,
                                    const float* __restrict__ boff,
                                    const float* __restrict__ battn)
{
    int idx = blockIdx.x * blockDim.x + threadIdx.x;
    if (idx < 384)
        g_bias_comb[idx] = (idx < 256) ? boff[idx] : battn[idx - 256];
    if (idx >= WT_TOTAL) return;

    const float* W;
    int Nd, out, t = idx;
    if (t < 65536)        { W = Wv;    Nd = 256; out = WT_WV; }
    else if (t < 131072)  { W = Woff;  Nd = 256; out = WT_COMB;          t -= 65536; }
    else if (t < 163840)  { W = Wattn; Nd = 128; out = WT_COMB + 65536;  t -= 131072; }
    else                  { W = Wo;    Nd = 256; out = WT_WO;            t -= 163840; }

    int k = t / Nd, n = t % Nd;
    g_wt[out + n * 256 + k] = __float2half_rn(W[k * Nd + n]);
}

// ---------------------------------------------------------------------------
// mma.sync fp16 GEMM, f32 A converted in-kernel. sp flag: 1 = single pass
// (A rounded to fp16), 0 = two passes (hi+lo split). CTA 64x128, 256 thr,
// 2-stage pipeline, 64KB smem, 3 CTAs/SM. oh: fp16 output.
// ---------------------------------------------------------------------------
__global__ __launch_bounds__(256, 3)
void gemm_dual_fp16(const float* __restrict__ A1,
                    const __half* __restrict__ B1,
                    const float* __restrict__ bias1,
                    void* __restrict__ C1, int M1, int N1, int nc1, int oh1, int sp1, int nblk1,
                    const float* __restrict__ A2,
                    const __half* __restrict__ B2,
                    const float* __restrict__ bias2,
                    void* __restrict__ C2, int M2, int N2, int nc2, int oh2, int sp2)
{
    extern __shared__ char smem[];
    const uint32_t sbase = smem_u32(smem);
    // per-stage layout: A_hi +0 | A_lo +8K | B +16K ; stage stride 32K

    const float* A; const __half* B; const float* bias; void* C;
    int M, N, brow, bcol, oh, sp;
    {
        int bid = blockIdx.x;
        if (bid < nblk1) {
            A = A1; B = B1; bias = bias1; C = C1; M = M1; N = N1; oh = oh1; sp = sp1;
            brow = (bid / nc1) * 64; bcol = (bid % nc1) * 128;
        } else {
            bid -= nblk1;
            A = A2; B = B2; bias = bias2; C = C2; M = M2; N = N2; oh = oh2; sp = sp2;
            brow = (bid / nc2) * 64; bcol = (bid % nc2) * 128;
        }
    }

    const int tid = threadIdx.x, lane = tid & 31, wid = tid >> 5;
    const int wr = (wid >> 2) * 32;
    const int wc = (wid & 3) * 32;

    float acc[2][4][4];
#pragma unroll
    for (int i = 0; i < 2; i++)
#pragma unroll
        for (int j = 0; j < 4; j++)
#pragma unroll
            for (int k = 0; k < 4; k++) acc[i][j][k] = 0.f;

    const int a_r  = wr + (lane & 15);
    const int a_kx = (lane >> 4) << 4;
    const int b_r0 = wc + (lane & 7) + ((lane >> 4) << 3);
    const int b_kx = ((lane >> 3) & 1) << 4;

    // ---- prologue: load chunk 0 into stage 0 ----
    {
#pragma unroll
        for (int i = 0; i < 4; i++) {
            int t = i * 256 + tid;
            int r = t >> 3, j = t & 7;
            uint32_t d = SMEM_SWIZZLE_128B((uint32_t)(r * 128 + j * 16));
            size_t src = (size_t)(bcol + r) * KDIM + j * 8;
            cp16(sbase + 16384u + d, B + src);
        }
        cp_commit();
        float4 a4[4];
#pragma unroll
        for (int i = 0; i < 4; i++) {
            int t = i * 256 + tid;
            int r = t >> 4, jc = t & 15;
            a4[i] = (brow + r < M)
                ? __ldg((const float4*)(A + (size_t)(brow + r) * KDIM + jc * 4))
                : make_float4(0.f, 0.f, 0.f, 0.f);
        }
#pragma unroll
        for (int i = 0; i < 4; i++) {
            int t = i * 256 + tid;
            int r = t >> 4, jc = t & 15;
            uint32_t d = SMEM_SWIZZLE_128B((uint32_t)(r * 128 + (jc >> 1) * 16)) + (jc & 1) * 8;
            uint2 ho, lo;
            split4h(a4[i], ho, lo);
            *(uint2*)(smem + d) = ho;
            if (!sp) *(uint2*)(smem + 8192u + d) = lo;
        }
        cp_wait0();
        __syncthreads();
    }

    const int nk = KDIM / 64;
    for (int kc = 0; kc < nk; kc++) {
        const uint32_t curoff = (uint32_t)(kc & 1) * 32768u;
        const uint32_t nxtoff = curoff ^ 32768u;
        const bool hn = (kc + 1) < nk;

        float4 aPre[4];
        if (hn) {
#pragma unroll
            for (int i = 0; i < 4; i++) {
                int t = i * 256 + tid;
                int r = t >> 3, j = t & 7;
                uint32_t d = SMEM_SWIZZLE_128B((uint32_t)(r * 128 + j * 16));
                size_t src = (size_t)(bcol + r) * KDIM + (kc + 1) * 64 + j * 8;
                cp16(sbase + nxtoff + 16384u + d, B + src);
            }
            cp_commit();
#pragma unroll
            for (int i = 0; i < 4; i++) {
                int t = i * 256 + tid;
                int r = t >> 4, jc = t & 15;
                aPre[i] = (brow + r < M)
                    ? __ldg((const float4*)(A + (size_t)(brow + r) * KDIM + (kc + 1) * 64 + jc * 4))
                    : make_float4(0.f, 0.f, 0.f, 0.f);
            }
        }

        const uint32_t sa_hi = sbase + curoff;
        const uint32_t sa_lo = sa_hi + 8192u;
        const uint32_t sb    = sa_hi + 16384u;
#pragma unroll
        for (int kk = 0; kk < 4; kk++) {
            const uint32_t kbA = (uint32_t)(kk * 32 + a_kx);
            const uint32_t kbB = (uint32_t)(kk * 32 + b_kx);

            uint32_t ahi[2][4], bf[4][2];
#pragma unroll
            for (int mi = 0; mi < 2; mi++)
                ldm_x4(ahi[mi], sa_hi + SMEM_SWIZZLE_128B((uint32_t)((a_r + mi * 16) * 128) + kbA));
#pragma unroll
            for (int nj = 0; nj < 2; nj++) {
                uint32_t rr[4];
                ldm_x4(rr, sb + SMEM_SWIZZLE_128B((uint32_t)((b_r0 + nj * 16) * 128) + kbB));
                bf[nj * 2][0] = rr[0]; bf[nj * 2][1] = rr[1];
                bf[nj * 2 + 1][0] = rr[2]; bf[nj * 2 + 1][1] = rr[3];
            }
#pragma unroll
            for (int mi = 0; mi < 2; mi++)
#pragma unroll
                for (int ni = 0; ni < 4; ni++)
                    mma16816h(acc[mi][ni], ahi[mi], bf[ni]);

            if (!sp) {
                uint32_t alo[2][4];
#pragma unroll
                for (int mi = 0; mi < 2; mi++)
                    ldm_x4(alo[mi], sa_lo + SMEM_SWIZZLE_128B((uint32_t)((a_r + mi * 16) * 128) + kbA));
#pragma unroll
                for (int mi = 0; mi < 2; mi++)
#pragma unroll
                    for (int ni = 0; ni < 4; ni++)
                        mma16816h(acc[mi][ni], alo[mi], bf[ni]);
            }
        }

        if (hn) {
#pragma unroll
            for (int i = 0; i < 4; i++) {
                int t = i * 256 + tid;
                int r = t >> 4, jc = t & 15;
                uint32_t d = SMEM_SWIZZLE_128B((uint32_t)(r * 128 + (jc >> 1) * 16)) + (jc & 1) * 8;
                uint2 ho, lo;
                split4h(aPre[i], ho, lo);
                *(uint2*)(smem + nxtoff + d) = ho;
                if (!sp) *(uint2*)(smem + nxtoff + 8192u + d) = lo;
            }
            cp_wait0();
            __syncthreads();
        }
    }

    // ---- epilogue ----
    const int row0 = brow + wr + (lane >> 2);
#pragma unroll
    for (int ni = 0; ni < 4; ni++) {
        int col = bcol + wc + ni * 8 + (lane & 3) * 2;
        float2 bb = *(const float2*)&bias[col];
#pragma unroll
        for (int mi = 0; mi < 2; mi++) {
            int r0 = row0 + mi * 16;
            int r1 = r0 + 8;
            float ox0 = acc[mi][ni][0] + bb.x, oy0 = acc[mi][ni][1] + bb.y;
            float ox1 = acc[mi][ni][2] + bb.x, oy1 = acc[mi][ni][3] + bb.y;
            if (oh) {
                if (r0 < M)
                    *(__half2*)((__half*)C + (size_t)r0 * N + col) = __floats2half2_rn(ox0, oy0);
                if (r1 < M)
                    *(__half2*)((__half*)C + (size_t)r1 * N + col) = __floats2half2_rn(ox1, oy1);
            } else {
                if (r0 < M) {
                    float2 o; o.x = ox0; o.y = oy0;
                    *(float2*)((float*)C + (size_t)r0 * N + col) = o;
                }
                if (r1 < M) {
                    float2 o; o.x = ox1; o.y = oy1;
                    *(float2*)((float*)C + (size_t)r1 * N + col) = o;
                }
            }
        }
    }
}

// ---------------------------------------------------------------------------
// Pure fp16 GEMM (A fp16 exact, single pass). CTA 64x128, 256 thr, 8 warps.
// Stage: A 8K | B 16K = 24K; 2 stages = 48K -> 4 CTAs/SM. Used for GEMM3.
// ---------------------------------------------------------------------------
__global__ __launch_bounds__(256, 4)
void gemm_a16_fp16(const __half* __restrict__ A,
                   const __half* __restrict__ B,
                   const float* __restrict__ bias,
                   float* __restrict__ C,
                   int M, int N, int nc)
{
    extern __shared__ char smem[];
    const uint32_t sbase = smem_u32(smem);

    const int bid = blockIdx.x;
    const int brow = (bid / nc) * 64, bcol = (bid % nc) * 128;

    const int tid = threadIdx.x, lane = tid & 31, wid = tid >> 5;
    const int wr = (wid >> 2) * 32;
    const int wc = (wid & 3) * 32;

    float acc[2][4][4];
#pragma unroll
    for (int i = 0; i < 2; i++)
#pragma unroll
        for (int j = 0; j < 4; j++)
#pragma unroll
            for (int k = 0; k < 4; k++) acc[i][j][k] = 0.f;

    const int a_r  = wr + (lane & 15);
    const int a_kx = (lane >> 4) << 4;
    const int b_r0 = wc + (lane & 7) + ((lane >> 4) << 3);
    const int b_kx = ((lane >> 3) & 1) << 4;

    {
#pragma unroll
        for (int i = 0; i < 2; i++) {
            int t = i * 256 + tid;
            int r = t >> 3, j = t & 7;
            uint32_t d = SMEM_SWIZZLE_128B((uint32_t)(r * 128 + j * 16));
            cp16(sbase + d, A + (size_t)(brow + r) * KDIM + j * 8);
        }
#pragma unroll
        for (int i = 0; i < 4; i++) {
            int t = i * 256 + tid;
            int r = t >> 3, j = t & 7;
            uint32_t d = SMEM_SWIZZLE_128B((uint32_t)(r * 128 + j * 16));
            cp16(sbase + 8192u + d, B + (size_t)(bcol + r) * KDIM + j * 8);
        }
        cp_commit();
        cp_wait0();
        __syncthreads();
    }

    const int nk = KDIM / 64;
    for (int kc = 0; kc < nk; kc++) {
        const uint32_t curoff = (uint32_t)(kc & 1) * 24576u;
        const uint32_t nxtoff = curoff ^ 24576u;
        const bool hn = (kc + 1) < nk;

        if (hn) {
#pragma unroll
            for (int i = 0; i < 2; i++) {
                int t = i * 256 + tid;
                int r = t >> 3, j = t & 7;
                uint32_t d = SMEM_SWIZZLE_128B((uint32_t)(r * 128 + j * 16));
                cp16(sbase + nxtoff + d, A + (size_t)(brow + r) * KDIM + (kc + 1) * 64 + j * 8);
            }
#pragma unroll
            for (int i = 0; i < 4; i++) {
                int t = i * 256 + tid;
                int r = t >> 3, j = t & 7;
                uint32_t d = SMEM_SWIZZLE_128B((uint32_t)(r * 128 + j * 16));
                cp16(sbase + nxtoff + 8192u + d, B + (size_t)(bcol + r) * KDIM + (kc + 1) * 64 + j * 8);
            }
            cp_commit();
        }

        const uint32_t sa = sbase + curoff;
        const uint32_t sb = sa + 8192u;
#pragma unroll
        for (int kk = 0; kk < 4; kk++) {
            const uint32_t kbA = (uint32_t)(kk * 32 + a_kx);
            const uint32_t kbB = (uint32_t)(kk * 32 + b_kx);

            uint32_t af[2][4], bf[4][2];
#pragma unroll
            for (int mi = 0; mi < 2; mi++)
                ldm_x4(af[mi], sa + SMEM_SWIZZLE_128B((uint32_t)((a_r + mi * 16) * 128) + kbA));
#pragma unroll
            for (int nj = 0; nj < 2; nj++) {
                uint32_t rr[4];
                ldm_x4(rr, sb + SMEM_SWIZZLE_128B((uint32_t)((b_r0 + nj * 16) * 128) + kbB));
                bf[nj * 2][0] = rr[0]; bf[nj * 2][1] = rr[1];
                bf[nj * 2 + 1][0] = rr[2]; bf[nj * 2 + 1][1] = rr[3];
            }
#pragma unroll
            for (int mi = 0; mi < 2; mi++)
#pragma unroll
                for (int ni = 0; ni < 4; ni++)
                    mma16816h(acc[mi][ni], af[mi], bf[ni]);
        }

        if (hn) {
            cp_wait0();
            __syncthreads();
        }
    }

    const int row0 = brow + wr + (lane >> 2);
#pragma unroll
    for (int ni = 0; ni < 4; ni++) {
        int col = bcol + wc + ni * 8 + (lane & 3) * 2;
        float2 bb = *(const float2*)&bias[col];
#pragma unroll
        for (int mi = 0; mi < 2; mi++) {
            int r0 = row0 + mi * 16;
            if (r0 < M) {
                float2 o;
                o.x = acc[mi][ni][0] + bb.x;
                o.y = acc[mi][ni][1] + bb.y;
                *(float2*)(C + (size_t)r0 * N + col) = o;
            }
            int r1 = r0 + 8;
            if (r1 < M) {
                float2 o;
                o.x = acc[mi][ni][2] + bb.x;
                o.y = acc[mi][ni][3] + bb.y;
                *(float2*)(C + (size_t)r1 * N + col) = o;
            }
        }
    }
}

// ---------------------------------------------------------------------------
// Fused softmax + bilinear sampling. fp16 offaw + fp16 value gathers;
// emits fp16 (GEMM3 A).
// ---------------------------------------------------------------------------
__global__ __launch_bounds__(256)
void msda_sample_kernel(const float* __restrict__ ref)
{
    int warp_global = blockIdx.x * (blockDim.x >> 5) + (threadIdx.x >> 5);
    if (warp_global >= Bb * LQ * 2) return;
    int lane = threadIdx.x & 31;
    int g = lane >> 3;
    int r = lane & 7;

    int hpair = warp_global & 1;
    int bq    = warp_global >> 1;
    int b     = bq / LQ;
    int hh    = hpair * 4 + g;

    // logits (fp16): lane r holds logits [2r, 2r+1]
    const __half2* awp = (const __half2*)(g_offaw + (size_t)bq * 384 + 256 + hh * 16);
    float2 lg = __half22float2(awp[r]);
    float m = fmaxf(lg.x, lg.y);
#pragma unroll
    for (int o = 4; o > 0; o >>= 1) m = fmaxf(m, __shfl_xor_sync(0xffffffffu, m, o));
    float e0 = __expf(lg.x - m);
    float e1 = __expf(lg.y - m);
    float s = e0 + e1;
#pragma unroll
    for (int o = 4; o > 0; o >>= 1) s += __shfl_xor_sync(0xffffffffu, s, o);
    float inv = 1.f / s;
    float w0 = e0 * inv;
    float w1 = e1 * inv;

    // offsets (fp16): lane r holds 4 halves = (x,y) of points 2r, 2r+1
    uint2 offr = *(const uint2*)(g_offaw + (size_t)bq * 384 + hh * 32 + r * 4);
    float2 oxy0 = __half22float2(*(__half2*)&offr.x);
    float2 oxy1 = __half22float2(*(__half2*)&offr.y);
    float4 off4 = make_float4(oxy0.x, oxy0.y, oxy1.x, oxy1.y);

    int l  = r >> 1;
    int HW = 80 >> l;
    int start = (l > 0 ? 6400 : 0) + (l > 1 ? 1600 : 0) + (l > 2 ? 400 : 0);
    float fHW = (float)HW;
    float2 rxy = __ldg((const float2*)ref + (size_t)bq * 4 + l);

    float cA[4], cB[4];
    uint32_t pkA0, pkA1, pkB0, pkB1;
#pragma unroll
    for (int pt = 0; pt < 2; pt++) {
        float ox = pt ? off4.z : off4.x;
        float oy = pt ? off4.w : off4.y;
        float aw = pt ? w1 : w0;

        float x = fmaf(rxy.x, fHW, ox - 0.5f);
        float y = fmaf(rxy.y, fHW, oy - 0.5f);
        float x0f = floorf(x), y0f = floorf(y);
        float wx = x - x0f, wy = y - y0f;
        int x0 = (int)x0f, y0 = (int)y0f;
        int x1 = x0 + 1,   y1 = y0 + 1;

        float vx0 = (x0 >= 0 && x0 < HW) ? 1.f : 0.f;
        float vx1 = (x1 >= 0 && x1 < HW) ? 1.f : 0.f;
        float vy0 = (y0 >= 0 && y0 < HW) ? 1.f : 0.f;
        float vy1 = (y1 >= 0 && y1 < HW) ? 1.f : 0.f;

        int cx0 = min(max(x0, 0), HW - 1);
        int cx1 = min(max(x1, 0), HW - 1);
        int cy0 = min(max(y0, 0), HW - 1);
        int cy1 = min(max(y1, 0), HW - 1);

        uint32_t p00 = (uint32_t)(start + cy0 * HW + cx0);
        uint32_t p01 = (uint32_t)(start + cy0 * HW + cx1);
        uint32_t p10 = (uint32_t)(start + cy1 * HW + cx0);
        uint32_t p11 = (uint32_t)(start + cy1 * HW + cx1);

        float wx1 = 1.f - wx, wy1 = 1.f - wy;
        float c0 = aw * wx1 * wy1 * vx0 * vy0;
        float c1 = aw * wx  * wy1 * vx1 * vy0;
        float c2 = aw * wx1 * wy  * vx0 * vy1;
        float c3 = aw * wx  * wy  * vx1 * vy1;

        if (pt == 0) {
            cA[0] = c0; cA[1] = c1; cA[2] = c2; cA[3] = c3;
            pkA0 = p00 | (p01 << 16); pkA1 = p10 | (p11 << 16);
        } else {
            cB[0] = c0; cB[1] = c1; cB[2] = c2; cB[3] = c3;
            pkB0 = p00 | (p01 << 16); pkB1 = p10 | (p11 << 16);
        }
    }

    const __half* pbase = g_vh + (size_t)b * LVTOT * Ee + hh * HEAD_DIM + r * 4;
    float4 acc = make_float4(0.f, 0.f, 0.f, 0.f);

#pragma unroll
    for (int j = 0; j < 8; j++) {
        int src = (g << 3) + j;
#pragma unroll
        for (int pt = 0; pt < 2; pt++) {
            float c0 = __shfl_sync(0xffffffffu, pt ? cB[0] : cA[0], src);
            float c1 = __shfl_sync(0xffffffffu, pt ? cB[1] : cA[1], src);
            float c2 = __shfl_sync(0xffffffffu, pt ? cB[2] : cA[2], src);
            float c3 = __shfl_sync(0xffffffffu, pt ? cB[3] : cA[3], src);
            uint32_t q0 = __shfl_sync(0xffffffffu, pt ? pkB0 : pkA0, src);
            uint32_t q1 = __shfl_sync(0xffffffffu, pt ? pkB1 : pkA1, src);

            uint32_t i00 = q0 & 0xffffu, i01 = q0 >> 16;
            uint32_t i10 = q1 & 0xffffu, i11 = q1 >> 16;

            uint2 r00 = __ldg((const uint2*)(pbase + (size_t)i00 * Ee));
            uint2 r01 = __ldg((const uint2*)(pbase + (size_t)i01 * Ee));
            uint2 r10 = __ldg((const uint2*)(pbase + (size_t)i10 * Ee));
            uint2 r11 = __ldg((const uint2*)(pbase + (size_t)i11 * Ee));

            float2 a00 = __half22float2(*(__half2*)&r00.x);
            float2 b00 = __half22float2(*(__half2*)&r00.y);
            float2 a01 = __half22float2(*(__half2*)&r01.x);
            float2 b01 = __half22float2(*(__half2*)&r01.y);
            float2 a10 = __half22float2(*(__half2*)&r10.x);
            float2 b10 = __half22float2(*(__half2*)&r10.y);
            float2 a11 = __half22float2(*(__half2*)&r11.x);
            float2 b11 = __half22float2(*(__half2*)&r11.y);

            acc.x = fmaf(c0, a00.x, fmaf(c1, a01.x, fmaf(c2, a10.x, fmaf(c3, a11.x, acc.x))));
            acc.y = fmaf(c0, a00.y, fmaf(c1, a01.y, fmaf(c2, a10.y, fmaf(c3, a11.y, acc.y))));
            acc.z = fmaf(c0, b00.x, fmaf(c1, b01.x, fmaf(c2, b10.x, fmaf(c3, b11.x, acc.z))));
            acc.w = fmaf(c0, b00.y, fmaf(c1, b01.y, fmaf(c2, b10.y, fmaf(c3, b11.y, acc.w))));
        }
    }

    __half2 o0 = __floats2half2_rn(acc.x, acc.y);
    __half2 o1 = __floats2half2_rn(acc.z, acc.w);
    uint2 ov;
    ov.x = *(uint32_t*)&o0;
    ov.y = *(uint32_t*)&o1;
    *(uint2*)(g_th + (size_t)bq * Ee + hh * HEAD_DIM + r * 4) = ov;
}

// ---------------------------------------------------------------------------
extern "C" void kernel_launch(void* const* d_in, const int* in_sizes, int n_in,
                              void* d_out, int out_size)
{
    const float* query = (const float*)d_in[0];
    const float* ref   = (const float*)d_in[1];
    const float* value = (const float*)d_in[2];
    const float* Wv    = (const float*)d_in[4];
    const float* bv    = (const float*)d_in[5];
    const float* Woff  = (const float*)d_in[6];
    const float* boff  = (const float*)d_in[7];
    const float* Wattn = (const float*)d_in[8];
    const float* battn = (const float*)d_in[9];
    const float* Wo    = (const float*)d_in[10];
    const float* bo    = (const float*)d_in[11];
    float* out = (float*)d_out;

    float *pbc;
    __half *pwt, *pvh, *pth, *poffaw;
    cudaGetSymbolAddress((void**)&pvh,    g_vh);
    cudaGetSymbolAddress((void**)&poffaw, g_offaw);
    cudaGetSymbolAddress((void**)&pth,    g_th);
    cudaGetSymbolAddress((void**)&pbc,    g_bias_comb);
    cudaGetSymbolAddress((void**)&pwt,    g_wt);

    cudaFuncSetAttribute(gemm_dual_fp16,
                         cudaFuncAttributeMaxDynamicSharedMemorySize, 65536);
    cudaFuncSetAttribute(gemm_a16_fp16,
                         cudaFuncAttributeMaxDynamicSharedMemorySize, 49152);

    // ---- prep (single launch) ----
    prep_weights_kernel<<<(WT_TOTAL + 255) / 256, 256>>>(Wv, Woff, Wattn, Wo, boff, battn);

    // ---- GEMM 1+2 merged: g_vh(fp16, 2-pass) AND g_offaw(fp16, 1-pass) ----
    {
        const int rows1 = (MV + 63) / 64;          // 532
        const int nblk1 = rows1 * 2;               // 1064
        const int rows2 = (MQ + 63) / 64;          // 525
        const int nblk2 = rows2 * 3;               // 1575
        gemm_dual_fp16<<<nblk1 + nblk2, 256, 65536>>>(
            value, pwt + WT_WV,   bv,  pvh,    MV, 256, 2, 1, 0, nblk1,
            query, pwt + WT_COMB, pbc, poffaw, MQ, 384, 3, 1, 1);
    }
    // ---- sampler (fp16 in/out) ----
    {
        int total_warps = Bb * LQ * 2;
        int blocks = (total_warps + 7) / 8;
        msda_sample_kernel<<<blocks, 256>>>(ref);
    }
    // ---- GEMM 3: out = g_th(fp16) @ Wo + bo ----
    {
        const int rows3 = (MQ + 63) / 64;          // 525
        gemm_a16_fp16<<<rows3 * 2, 256, 49152>>>(
            pth, pwt + WT_WO, bo, out, MQ, 256, 2);
    }
}

// round 16
// speedup vs baseline: 1.5830x; 1.0405x over previous
#include <cuda_runtime.h>
#include <cuda_fp16.h>
#include <math.h>
#include <stdint.h>

#define Bb 4
#define LQ 8400
#define Ee 256
#define HEADS 8
#define LEVELS 4
#define POINTS 4
#define HEAD_DIM 32
#define LVTOT 8500
#define KDIM 256

#define MQ (Bb * LQ)     // 33600
#define MV (Bb * LVTOT)  // 34000

// ---------------- scratch (device globals; no allocation allowed) ----------
// g_vh: head-major planes [b][h][pos][32 fp16] (+pad for paired-corner reads)
__device__ __half g_vh[MV * Ee + 32];
__device__ __half g_offaw[MQ * 384];      // [off(256) | aw(128)] fp16
__device__ __half g_th[MQ * Ee];          // sampler output (fp16, GEMM3 A)
__device__ float g_bias_comb[384];

// transposed weights [N][K] fp16
#define WT_WV    0
#define WT_COMB  65536
#define WT_WO    163840
#define WT_TOTAL 229376
__device__ __half g_wt[WT_TOTAL];

// ---------------- helpers ----------------------------------------------
#define SMEM_SWIZZLE_128B(byte_offset) \
    ((byte_offset) ^ (((byte_offset) >> 3) & 0x70))

__device__ __forceinline__ uint32_t smem_u32(const void* p) {
    uint32_t a;
    asm("{ .reg .u64 t; cvta.to.shared.u64 t, %1; cvt.u32.u64 %0, t; }"
        : "=r"(a) : "l"(p));
    return a;
}

__device__ __forceinline__ void cp16(uint32_t dst, const void* src) {
    asm volatile("cp.async.cg.shared.global [%0], [%1], 16;"
                 :: "r"(dst), "l"(src));
}

__device__ __forceinline__ void cp_commit() {
    asm volatile("cp.async.commit_group;" ::: "memory");
}
__device__ __forceinline__ void cp_wait0() {
    asm volatile("cp.async.wait_group 0;" ::: "memory");
}

__device__ __forceinline__ void ldm_x4(uint32_t* r, uint32_t addr) {
    asm volatile("ldmatrix.sync.aligned.m8n8.x4.shared.b16 {%0,%1,%2,%3}, [%4];"
                 : "=r"(r[0]), "=r"(r[1]), "=r"(r[2]), "=r"(r[3]) : "r"(addr));
}

__device__ __forceinline__ void mma16816h(float* c, const uint32_t* a, const uint32_t* b) {
    asm volatile("mma.sync.aligned.m16n8k16.row.col.f32.f16.f16.f32 "
                 "{%0,%1,%2,%3}, {%4,%5,%6,%7}, {%8,%9}, {%0,%1,%2,%3};"
                 : "+f"(c[0]), "+f"(c[1]), "+f"(c[2]), "+f"(c[3])
                 : "r"(a[0]), "r"(a[1]), "r"(a[2]), "r"(a[3]),
                   "r"(b[0]), "r"(b[1]));
}

__device__ __forceinline__ void split4h(float4 v, uint2& ho, uint2& lo) {
    __half h0 = __float2half_rn(v.x);
    __half h1 = __float2half_rn(v.y);
    __half h2 = __float2half_rn(v.z);
    __half h3 = __float2half_rn(v.w);
    __half l0 = __float2half_rn(v.x - __half2float(h0));
    __half l1 = __float2half_rn(v.y - __half2float(h1));
    __half l2 = __float2half_rn(v.z - __half2float(h2));
    __half l3 = __float2half_rn(v.w - __half2float(h3));
    __half2 hp0 = __halves2half2(h0, h1);
    __half2 hp1 = __halves2half2(h2, h3);
    __half2 lp0 = __halves2half2(l0, l1);
    __half2 lp1 = __halves2half2(l2, l3);
    ho.x = *(uint32_t*)&hp0; ho.y = *(uint32_t*)&hp1;
    lo.x = *(uint32_t*)&lp0; lo.y = *(uint32_t*)&lp1;
}

// ---------------------------------------------------------------------------
// ONE prep kernel: all 4 weight transposes (fp16) + bias concat.
// ---------------------------------------------------------------------------
__global__ void prep_weights_kernel(const float* __restrict__ Wv,
                                    const float* __restrict__ Woff,
                                    const float* __restrict__ Wattn,
                                    const float* __restrict__ Wo,
                                    const float* __restrict__ boff,
                                    const float* __restrict__ battn)
{
    int idx = blockIdx.x * blockDim.x + threadIdx.x;
    if (idx < 384)
        g_bias_comb[idx] = (idx < 256) ? boff[idx] : battn[idx - 256];
    if (idx >= WT_TOTAL) return;

    const float* W;
    int Nd, out, t = idx;
    if (t < 65536)        { W = Wv;    Nd = 256; out = WT_WV; }
    else if (t < 131072)  { W = Woff;  Nd = 256; out = WT_COMB;          t -= 65536; }
    else if (t < 163840)  { W = Wattn; Nd = 128; out = WT_COMB + 65536;  t -= 131072; }
    else                  { W = Wo;    Nd = 256; out = WT_WO;            t -= 163840; }

    int k = t / Nd, n = t % Nd;
    g_wt[out + n * 256 + k] = __float2half_rn(W[k * Nd + n]);
}

// ---------------------------------------------------------------------------
// mma.sync fp16 GEMM, f32 A converted in-kernel. sp: 1=single pass, 0=hi+lo.
// oh: 0 = f32 out, 1 = fp16 row-major out, 2 = fp16 head-plane out (g_vh).
// CTA 64x128, 256 thr, 2-stage pipeline, 64KB smem, 3 CTAs/SM.
// ---------------------------------------------------------------------------
__global__ __launch_bounds__(256, 3)
void gemm_dual_fp16(const float* __restrict__ A1,
                    const __half* __restrict__ B1,
                    const float* __restrict__ bias1,
                    void* __restrict__ C1, int M1, int N1, int nc1, int oh1, int sp1, int nblk1,
                    const float* __restrict__ A2,
                    const __half* __restrict__ B2,
                    const float* __restrict__ bias2,
                    void* __restrict__ C2, int M2, int N2, int nc2, int oh2, int sp2)
{
    extern __shared__ char smem[];
    const uint32_t sbase = smem_u32(smem);

    const float* A; const __half* B; const float* bias; void* C;
    int M, N, brow, bcol, oh, sp;
    {
        int bid = blockIdx.x;
        if (bid < nblk1) {
            A = A1; B = B1; bias = bias1; C = C1; M = M1; N = N1; oh = oh1; sp = sp1;
            brow = (bid / nc1) * 64; bcol = (bid % nc1) * 128;
        } else {
            bid -= nblk1;
            A = A2; B = B2; bias = bias2; C = C2; M = M2; N = N2; oh = oh2; sp = sp2;
            brow = (bid / nc2) * 64; bcol = (bid % nc2) * 128;
        }
    }

    const int tid = threadIdx.x, lane = tid & 31, wid = tid >> 5;
    const int wr = (wid >> 2) * 32;
    const int wc = (wid & 3) * 32;

    float acc[2][4][4];
#pragma unroll
    for (int i = 0; i < 2; i++)
#pragma unroll
        for (int j = 0; j < 4; j++)
#pragma unroll
            for (int k = 0; k < 4; k++) acc[i][j][k] = 0.f;

    const int a_r  = wr + (lane & 15);
    const int a_kx = (lane >> 4) << 4;
    const int b_r0 = wc + (lane & 7) + ((lane >> 4) << 3);
    const int b_kx = ((lane >> 3) & 1) << 4;

    // ---- prologue ----
    {
#pragma unroll
        for (int i = 0; i < 4; i++) {
            int t = i * 256 + tid;
            int r = t >> 3, j = t & 7;
            uint32_t d = SMEM_SWIZZLE_128B((uint32_t)(r * 128 + j * 16));
            size_t src = (size_t)(bcol + r) * KDIM + j * 8;
            cp16(sbase + 16384u + d, B + src);
        }
        cp_commit();
        float4 a4[4];
#pragma unroll
        for (int i = 0; i < 4; i++) {
            int t = i * 256 + tid;
            int r = t >> 4, jc = t & 15;
            a4[i] = (brow + r < M)
                ? __ldg((const float4*)(A + (size_t)(brow + r) * KDIM + jc * 4))
                : make_float4(0.f, 0.f, 0.f, 0.f);
        }
#pragma unroll
        for (int i = 0; i < 4; i++) {
            int t = i * 256 + tid;
            int r = t >> 4, jc = t & 15;
            uint32_t d = SMEM_SWIZZLE_128B((uint32_t)(r * 128 + (jc >> 1) * 16)) + (jc & 1) * 8;
            uint2 ho, lo;
            split4h(a4[i], ho, lo);
            *(uint2*)(smem + d) = ho;
            if (!sp) *(uint2*)(smem + 8192u + d) = lo;
        }
        cp_wait0();
        __syncthreads();
    }

    const int nk = KDIM / 64;
    for (int kc = 0; kc < nk; kc++) {
        const uint32_t curoff = (uint32_t)(kc & 1) * 32768u;
        const uint32_t nxtoff = curoff ^ 32768u;
        const bool hn = (kc + 1) < nk;

        float4 aPre[4];
        if (hn) {
#pragma unroll
            for (int i = 0; i < 4; i++) {
                int t = i * 256 + tid;
                int r = t >> 3, j = t & 7;
                uint32_t d = SMEM_SWIZZLE_128B((uint32_t)(r * 128 + j * 16));
                size_t src = (size_t)(bcol + r) * KDIM + (kc + 1) * 64 + j * 8;
                cp16(sbase + nxtoff + 16384u + d, B + src);
            }
            cp_commit();
#pragma unroll
            for (int i = 0; i < 4; i++) {
                int t = i * 256 + tid;
                int r = t >> 4, jc = t & 15;
                aPre[i] = (brow + r < M)
                    ? __ldg((const float4*)(A + (size_t)(brow + r) * KDIM + (kc + 1) * 64 + jc * 4))
                    : make_float4(0.f, 0.f, 0.f, 0.f);
            }
        }

        const uint32_t sa_hi = sbase + curoff;
        const uint32_t sa_lo = sa_hi + 8192u;
        const uint32_t sb    = sa_hi + 16384u;
#pragma unroll
        for (int kk = 0; kk < 4; kk++) {
            const uint32_t kbA = (uint32_t)(kk * 32 + a_kx);
            const uint32_t kbB = (uint32_t)(kk * 32 + b_kx);

            uint32_t ahi[2][4], bf[4][2];
#pragma unroll
            for (int mi = 0; mi < 2; mi++)
                ldm_x4(ahi[mi], sa_hi + SMEM_SWIZZLE_128B((uint32_t)((a_r + mi * 16) * 128) + kbA));
#pragma unroll
            for (int nj = 0; nj < 2; nj++) {
                uint32_t rr[4];
                ldm_x4(rr, sb + SMEM_SWIZZLE_128B((uint32_t)((b_r0 + nj * 16) * 128) + kbB));
                bf[nj * 2][0] = rr[0]; bf[nj * 2][1] = rr[1];
                bf[nj * 2 + 1][0] = rr[2]; bf[nj * 2 + 1][1] = rr[3];
            }
#pragma unroll
            for (int mi = 0; mi < 2; mi++)
#pragma unroll
                for (int ni = 0; ni < 4; ni++)
                    mma16816h(acc[mi][ni], ahi[mi], bf[ni]);

            if (!sp) {
                uint32_t alo[2][4];
#pragma unroll
                for (int mi = 0; mi < 2; mi++)
                    ldm_x4(alo[mi], sa_lo + SMEM_SWIZZLE_128B((uint32_t)((a_r + mi * 16) * 128) + kbA));
#pragma unroll
                for (int mi = 0; mi < 2; mi++)
#pragma unroll
                    for (int ni = 0; ni < 4; ni++)
                        mma16816h(acc[mi][ni], alo[mi], bf[ni]);
            }
        }

        if (hn) {
#pragma unroll
            for (int i = 0; i < 4; i++) {
                int t = i * 256 + tid;
                int r = t >> 4, jc = t & 15;
                uint32_t d = SMEM_SWIZZLE_128B((uint32_t)(r * 128 + (jc >> 1) * 16)) + (jc & 1) * 8;
                uint2 ho, lo;
                split4h(aPre[i], ho, lo);
                *(uint2*)(smem + nxtoff + d) = ho;
                if (!sp) *(uint2*)(smem + nxtoff + 8192u + d) = lo;
            }
            cp_wait0();
            __syncthreads();
        }
    }

    // ---- epilogue ----
    const int row0 = brow + wr + (lane >> 2);
    const int hplane = (bcol + wc) >> 5;       // head index (oh==2; warp tile = 1 head)
#pragma unroll
    for (int ni = 0; ni < 4; ni++) {
        int col = bcol + wc + ni * 8 + (lane & 3) * 2;
        float2 bb = *(const float2*)&bias[col];
        int dd = ni * 8 + (lane & 3) * 2;      // dim within head (oh==2)
#pragma unroll
        for (int mi = 0; mi < 2; mi++) {
            int r0 = row0 + mi * 16;
            int r1 = r0 + 8;
            float ox0 = acc[mi][ni][0] + bb.x, oy0 = acc[mi][ni][1] + bb.y;
            float ox1 = acc[mi][ni][2] + bb.x, oy1 = acc[mi][ni][3] + bb.y;
            if (oh == 2) {
                if (r0 < M) {
                    int b_ = r0 / LVTOT, pos = r0 - b_ * LVTOT;
                    __half* dst = (__half*)C + (((size_t)(b_ * HEADS + hplane) * LVTOT + pos) << 5) + dd;
                    *(__half2*)dst = __floats2half2_rn(ox0, oy0);
                }
                if (r1 < M) {
                    int b_ = r1 / LVTOT, pos = r1 - b_ * LVTOT;
                    __half* dst = (__half*)C + (((size_t)(b_ * HEADS + hplane) * LVTOT + pos) << 5) + dd;
                    *(__half2*)dst = __floats2half2_rn(ox1, oy1);
                }
            } else if (oh == 1) {
                if (r0 < M)
                    *(__half2*)((__half*)C + (size_t)r0 * N + col) = __floats2half2_rn(ox0, oy0);
                if (r1 < M)
                    *(__half2*)((__half*)C + (size_t)r1 * N + col) = __floats2half2_rn(ox1, oy1);
            } else {
                if (r0 < M) {
                    float2 o; o.x = ox0; o.y = oy0;
                    *(float2*)((float*)C + (size_t)r0 * N + col) = o;
                }
                if (r1 < M) {
                    float2 o; o.x = ox1; o.y = oy1;
                    *(float2*)((float*)C + (size_t)r1 * N + col) = o;
                }
            }
        }
    }
}

// ---------------------------------------------------------------------------
// Pure fp16 GEMM (single pass). CTA 64x128, 256 thr. 48KB smem, 4 CTAs/SM.
// ---------------------------------------------------------------------------
__global__ __launch_bounds__(256, 4)
void gemm_a16_fp16(const __half* __restrict__ A,
                   const __half* __restrict__ B,
                   const float* __restrict__ bias,
                   float* __restrict__ C,
                   int M, int N, int nc)
{
    extern __shared__ char smem[];
    const uint32_t sbase = smem_u32(smem);

    const int bid = blockIdx.x;
    const int brow = (bid / nc) * 64, bcol = (bid % nc) * 128;

    const int tid = threadIdx.x, lane = tid & 31, wid = tid >> 5;
    const int wr = (wid >> 2) * 32;
    const int wc = (wid & 3) * 32;

    float acc[2][4][4];
#pragma unroll
    for (int i = 0; i < 2; i++)
#pragma unroll
        for (int j = 0; j < 4; j++)
#pragma unroll
            for (int k = 0; k < 4; k++) acc[i][j][k] = 0.f;

    const int a_r  = wr + (lane & 15);
    const int a_kx = (lane >> 4) << 4;
    const int b_r0 = wc + (lane & 7) + ((lane >> 4) << 3);
    const int b_kx = ((lane >> 3) & 1) << 4;

    {
#pragma unroll
        for (int i = 0; i < 2; i++) {
            int t = i * 256 + tid;
            int r = t >> 3, j = t & 7;
            uint32_t d = SMEM_SWIZZLE_128B((uint32_t)(r * 128 + j * 16));
            cp16(sbase + d, A + (size_t)(brow + r) * KDIM + j * 8);
        }
#pragma unroll
        for (int i = 0; i < 4; i++) {
            int t = i * 256 + tid;
            int r = t >> 3, j = t & 7;
            uint32_t d = SMEM_SWIZZLE_128B((uint32_t)(r * 128 + j * 16));
            cp16(sbase + 8192u + d, B + (size_t)(bcol + r) * KDIM + j * 8);
        }
        cp_commit();
        cp_wait0();
        __syncthreads();
    }

    const int nk = KDIM / 64;
    for (int kc = 0; kc < nk; kc++) {
        const uint32_t curoff = (uint32_t)(kc & 1) * 24576u;
        const uint32_t nxtoff = curoff ^ 24576u;
        const bool hn = (kc + 1) < nk;

        if (hn) {
#pragma unroll
            for (int i = 0; i < 2; i++) {
                int t = i * 256 + tid;
                int r = t >> 3, j = t & 7;
                uint32_t d = SMEM_SWIZZLE_128B((uint32_t)(r * 128 + j * 16));
                cp16(sbase + nxtoff + d, A + (size_t)(brow + r) * KDIM + (kc + 1) * 64 + j * 8);
            }
#pragma unroll
            for (int i = 0; i < 4; i++) {
                int t = i * 256 + tid;
                int r = t >> 3, j = t & 7;
                uint32_t d = SMEM_SWIZZLE_128B((uint32_t)(r * 128 + j * 16));
                cp16(sbase + nxtoff + 8192u + d, B + (size_t)(bcol + r) * KDIM + (kc + 1) * 64 + j * 8);
            }
            cp_commit();
        }

        const uint32_t sa = sbase + curoff;
        const uint32_t sb = sa + 8192u;
#pragma unroll
        for (int kk = 0; kk < 4; kk++) {
            const uint32_t kbA = (uint32_t)(kk * 32 + a_kx);
            const uint32_t kbB = (uint32_t)(kk * 32 + b_kx);

            uint32_t af[2][4], bf[4][2];
#pragma unroll
            for (int mi = 0; mi < 2; mi++)
                ldm_x4(af[mi], sa + SMEM_SWIZZLE_128B((uint32_t)((a_r + mi * 16) * 128) + kbA));
#pragma unroll
            for (int nj = 0; nj < 2; nj++) {
                uint32_t rr[4];
                ldm_x4(rr, sb + SMEM_SWIZZLE_128B((uint32_t)((b_r0 + nj * 16) * 128) + kbB));
                bf[nj * 2][0] = rr[0]; bf[nj * 2][1] = rr[1];
                bf[nj * 2 + 1][0] = rr[2]; bf[nj * 2 + 1][1] = rr[3];
            }
#pragma unroll
            for (int mi = 0; mi < 2; mi++)
#pragma unroll
                for (int ni = 0; ni < 4; ni++)
                    mma16816h(acc[mi][ni], af[mi], bf[ni]);
        }

        if (hn) {
            cp_wait0();
            __syncthreads();
        }
    }

    const int row0 = brow + wr + (lane >> 2);
#pragma unroll
    for (int ni = 0; ni < 4; ni++) {
        int col = bcol + wc + ni * 8 + (lane & 3) * 2;
        float2 bb = *(const float2*)&bias[col];
#pragma unroll
        for (int mi = 0; mi < 2; mi++) {
            int r0 = row0 + mi * 16;
            if (r0 < M) {
                float2 o;
                o.x = acc[mi][ni][0] + bb.x;
                o.y = acc[mi][ni][1] + bb.y;
                *(float2*)(C + (size_t)r0 * N + col) = o;
            }
            int r1 = r0 + 8;
            if (r1 < M) {
                float2 o;
                o.x = acc[mi][ni][2] + bb.x;
                o.y = acc[mi][ni][3] + bb.y;
                *(float2*)(C + (size_t)r1 * N + col) = o;
            }
        }
    }
}

// ---------------------------------------------------------------------------
// Fused softmax + bilinear sampling, head-major planes + paired-corner loads.
// Per point: 2 x LDG.128 (one per y-row, covering both x-corners) -> half the
// L1tex wavefronts of the 4 x LDG.64 scheme. Lanes r<4 weight the left corner,
// r>=4 the right; one shfl_xor(4) merges at the end.
// ---------------------------------------------------------------------------
__global__ __launch_bounds__(256)
void msda_sample_kernel(const float* __restrict__ ref)
{
    int warp_global = blockIdx.x * (blockDim.x >> 5) + (threadIdx.x >> 5);
    if (warp_global >= Bb * LQ * 2) return;
    int lane = threadIdx.x & 31;
    int g = lane >> 3;
    int r = lane & 7;

    int hpair = warp_global & 1;
    int bq    = warp_global >> 1;
    int b     = bq / LQ;
    int hh    = hpair * 4 + g;

    // softmax over 16 logits (fp16); lane r holds logits [2r, 2r+1]
    const __half2* awp = (const __half2*)(g_offaw + (size_t)bq * 384 + 256 + hh * 16);
    float2 lg = __half22float2(awp[r]);
    float m = fmaxf(lg.x, lg.y);
#pragma unroll
    for (int o = 4; o > 0; o >>= 1) m = fmaxf(m, __shfl_xor_sync(0xffffffffu, m, o));
    float e0 = __expf(lg.x - m);
    float e1 = __expf(lg.y - m);
    float s = e0 + e1;
#pragma unroll
    for (int o = 4; o > 0; o >>= 1) s += __shfl_xor_sync(0xffffffffu, s, o);
    float inv = 1.f / s;
    float w0 = e0 * inv;
    float w1 = e1 * inv;

    // offsets (fp16): lane r holds (x,y) of points 2r, 2r+1
    uint2 offr = *(const uint2*)(g_offaw + (size_t)bq * 384 + hh * 32 + r * 4);
    float2 oxy0 = __half22float2(*(__half2*)&offr.x);
    float2 oxy1 = __half22float2(*(__half2*)&offr.y);
    float4 off4 = make_float4(oxy0.x, oxy0.y, oxy1.x, oxy1.y);

    int l  = r >> 1;
    int HW = 80 >> l;
    int start = (l > 0 ? 6400 : 0) + (l > 1 ? 1600 : 0) + (l > 2 ? 400 : 0);
    float fHW = (float)HW;
    float2 rxy = __ldg((const float2*)ref + (size_t)bq * 4 + l);

    // owner-lane precompute: row weights (left/right) + packed row positions
    float cA[4], cB[4];
    uint32_t pkA, pkB;
#pragma unroll
    for (int pt = 0; pt < 2; pt++) {
        float ox = pt ? off4.z : off4.x;
        float oy = pt ? off4.w : off4.y;
        float aw = pt ? w1 : w0;

        float x = fmaf(rxy.x, fHW, ox - 0.5f);
        float y = fmaf(rxy.y, fHW, oy - 0.5f);
        float x0f = floorf(x), y0f = floorf(y);
        float wx = x - x0f, wy = y - y0f;
        int x0 = (int)x0f, y0 = (int)y0f;
        int x1 = x0 + 1,   y1 = y0 + 1;

        float vx0 = (x0 >= 0 && x0 < HW) ? 1.f : 0.f;
        float vx1 = (x1 >= 0 && x1 < HW) ? 1.f : 0.f;
        float vy0 = (y0 >= 0 && y0 < HW) ? 1.f : 0.f;
        float vy1 = (y1 >= 0 && y1 < HW) ? 1.f : 0.f;

        int cx0 = min(max(x0, 0), HW - 1);
        int cx1 = min(max(x1, 0), HW - 1);
        int cy0 = min(max(y0, 0), HW - 1);
        int cy1 = min(max(y1, 0), HW - 1);

        float wx1 = 1.f - wx, wy1 = 1.f - wy;
        float c0 = aw * wx1 * wy1 * vx0 * vy0;   // (x0,y0)
        float c1 = aw * wx  * wy1 * vx1 * vy0;   // (x1,y0)
        float c2 = aw * wx1 * wy  * vx0 * vy1;   // (x0,y1)
        float c3 = aw * wx  * wy  * vx1 * vy1;   // (x1,y1)

        // regroup onto (left=cx0, right=cx0+1)
        bool same = (cx1 == cx0);
        float cL0 = c0 + (same ? c1 : 0.f);
        float cR0 = same ? 0.f : c1;
        float cL1 = c2 + (same ? c3 : 0.f);
        float cR1 = same ? 0.f : c3;

        uint32_t py0 = (uint32_t)(start + cy0 * HW + cx0);
        uint32_t py1 = (uint32_t)(start + cy1 * HW + cx0);
        uint32_t pk = py0 | (py1 << 16);

        if (pt == 0) { cA[0] = cL0; cA[1] = cR0; cA[2] = cL1; cA[3] = cR1; pkA = pk; }
        else         { cB[0] = cL0; cB[1] = cR0; cB[2] = cL1; cB[3] = cR1; pkB = pk; }
    }

    // plane base: head-major [b][h][pos][32]; lane covers 16B of the 128B pair
    const __half* plane = g_vh + ((size_t)(b * HEADS + hh) * LVTOT) * 32
                          + (r >> 2) * 32 + (r & 3) * 8;
    const bool left = (r < 4);

    float a[8];
#pragma unroll
    for (int k = 0; k < 8; k++) a[k] = 0.f;

#pragma unroll
    for (int j = 0; j < 8; j++) {
        int src = (g << 3) + j;
#pragma unroll
        for (int pt = 0; pt < 2; pt++) {
            float cl0 = __shfl_sync(0xffffffffu, pt ? cB[0] : cA[0], src);
            float cr0 = __shfl_sync(0xffffffffu, pt ? cB[1] : cA[1], src);
            float cl1 = __shfl_sync(0xffffffffu, pt ? cB[2] : cA[2], src);
            float cr1 = __shfl_sync(0xffffffffu, pt ? cB[3] : cA[3], src);
            uint32_t pk = __shfl_sync(0xffffffffu, pt ? pkB : pkA, src);

            float wy0 = left ? cl0 : cr0;
            float wy1 = left ? cl1 : cr1;
            uint32_t py0 = pk & 0xffffu, py1 = pk >> 16;

            uint4 v0 = __ldg((const uint4*)(plane + (size_t)py0 * 32));
            uint4 v1 = __ldg((const uint4*)(plane + (size_t)py1 * 32));

            float2 f;
            f = __half22float2(*(__half2*)&v0.x); a[0] = fmaf(wy0, f.x, a[0]); a[1] = fmaf(wy0, f.y, a[1]);
            f = __half22float2(*(__half2*)&v0.y); a[2] = fmaf(wy0, f.x, a[2]); a[3] = fmaf(wy0, f.y, a[3]);
            f = __half22float2(*(__half2*)&v0.z); a[4] = fmaf(wy0, f.x, a[4]); a[5] = fmaf(wy0, f.y, a[5]);
            f = __half22float2(*(__half2*)&v0.w); a[6] = fmaf(wy0, f.x, a[6]); a[7] = fmaf(wy0, f.y, a[7]);
            f = __half22float2(*(__half2*)&v1.x); a[0] = fmaf(wy1, f.x, a[0]); a[1] = fmaf(wy1, f.y, a[1]);
            f = __half22float2(*(__half2*)&v1.y); a[2] = fmaf(wy1, f.x, a[2]); a[3] = fmaf(wy1, f.y, a[3]);
            f = __half22float2(*(__half2*)&v1.z); a[4] = fmaf(wy1, f.x, a[4]); a[5] = fmaf(wy1, f.y, a[5]);
            f = __half22float2(*(__half2*)&v1.w); a[6] = fmaf(wy1, f.x, a[6]); a[7] = fmaf(wy1, f.y, a[7]);
        }
    }

    // merge left/right partials: lanes r and r+4 hold same dims
#pragma unroll
    for (int k = 0; k < 8; k++) a[k] += __shfl_xor_sync(0xffffffffu, a[k], 4);

    if (left) {
        __half2 h0 = __floats2half2_rn(a[0], a[1]);
        __half2 h1 = __floats2half2_rn(a[2], a[3]);
        __half2 h2 = __floats2half2_rn(a[4], a[5]);
        __half2 h3 = __floats2half2_rn(a[6], a[7]);
        uint4 ov;
        ov.x = *(uint32_t*)&h0; ov.y = *(uint32_t*)&h1;
        ov.z = *(uint32_t*)&h2; ov.w = *(uint32_t*)&h3;
        *(uint4*)(g_th + (size_t)bq * Ee + hh * HEAD_DIM + (r & 3) * 8) = ov;
    }
}

// ---------------------------------------------------------------------------
extern "C" void kernel_launch(void* const* d_in, const int* in_sizes, int n_in,
                              void* d_out, int out_size)
{
    const float* query = (const float*)d_in[0];
    const float* ref   = (const float*)d_in[1];
    const float* value = (const float*)d_in[2];
    const float* Wv    = (const float*)d_in[4];
    const float* bv    = (const float*)d_in[5];
    const float* Woff  = (const float*)d_in[6];
    const float* boff  = (const float*)d_in[7];
    const float* Wattn = (const float*)d_in[8];
    const float* battn = (const float*)d_in[9];
    const float* Wo    = (const float*)d_in[10];
    const float* bo    = (const float*)d_in[11];
    float* out = (float*)d_out;

    float *pbc;
    __half *pwt, *pvh, *pth, *poffaw;
    cudaGetSymbolAddress((void**)&pvh,    g_vh);
    cudaGetSymbolAddress((void**)&poffaw, g_offaw);
    cudaGetSymbolAddress((void**)&pth,    g_th);
    cudaGetSymbolAddress((void**)&pbc,    g_bias_comb);
    cudaGetSymbolAddress((void**)&pwt,    g_wt);

    cudaFuncSetAttribute(gemm_dual_fp16,
                         cudaFuncAttributeMaxDynamicSharedMemorySize, 65536);
    cudaFuncSetAttribute(gemm_a16_fp16,
                         cudaFuncAttributeMaxDynamicSharedMemorySize, 49152);

    // ---- prep (single launch) ----
    prep_weights_kernel<<<(WT_TOTAL + 255) / 256, 256>>>(Wv, Woff, Wattn, Wo, boff, battn);

    // ---- GEMM 1+2 merged: g_vh(fp16 head-plane, 2-pass) AND g_offaw(fp16, 1-pass) ----
    {
        const int rows1 = (MV + 63) / 64;          // 532
        const int nblk1 = rows1 * 2;               // 1064
        const int rows2 = (MQ + 63) / 64;          // 525
        const int nblk2 = rows2 * 3;               // 1575
        gemm_dual_fp16<<<nblk1 + nblk2, 256, 65536>>>(
            value, pwt + WT_WV,   bv,  pvh,    MV, 256, 2, 2, 0, nblk1,
            query, pwt + WT_COMB, pbc, poffaw, MQ, 384, 3, 1, 1);
    }
    // ---- sampler (paired-corner loads) ----
    {
        int total_warps = Bb * LQ * 2;
        int blocks = (total_warps + 7) / 8;
        msda_sample_kernel<<<blocks, 256>>>(ref);
    }
    // ---- GEMM 3: out = g_th(fp16) @ Wo + bo ----
    {
        const int rows3 = (MQ + 63) / 64;          // 525
        gemm_a16_fp16<<<rows3 * 2, 256, 49152>>>(
            pth, pwt + WT_WO, bo, out, MQ, 256, 2);
    }
}